// round 2
// baseline (speedup 1.0000x reference)
#include <cuda_runtime.h>
#include <math.h>
#include <float.h>

#define Nn 50000
#define Ee 800000
#define Hh 4
#define Dd 128
#define HDim 512
#define NEG_ATTN 0.2f
#define NEG_ACT 0.01f

// ---------------- scratch (static device allocations) ----------------
__device__ float g_feat[Nn * HDim];
__device__ float g_res [Nn * HDim];
__device__ float g_xa  [Nn * Dd];
__device__ float g_xb  [Nn * Dd];
__device__ float g_el  [Nn * Hh];
__device__ float g_er  [Nn * Hh];
__device__ float g_m   [Nn * Hh];
__device__ float g_z   [Nn * Hh];
__device__ float g_ex  [Ee * Hh];
__device__ int   g_deg [Nn];
__device__ int   g_off [Nn + 1];
__device__ int   g_cur [Nn];
__device__ int   g_csr_src[Ee];
__device__ int   g_csr_eid[Ee];

__device__ __forceinline__ void atomicMaxF(float* addr, float v) {
    if (v >= 0.f) atomicMax((int*)addr, __float_as_int(v));
    else          atomicMin((unsigned int*)addr, __float_as_uint(v));
}

// ---------------- CSR build ----------------
__global__ void k_zero_deg() {
    int i = blockIdx.x * blockDim.x + threadIdx.x;
    if (i < Nn) g_deg[i] = 0;
}

__global__ void k_hist(const int* __restrict__ dst) {
    int i = blockIdx.x * blockDim.x + threadIdx.x;
    if (i < Ee) atomicAdd(&g_deg[dst[i]], 1);
}

// single-block exclusive scan over g_deg -> g_off, g_cur
__global__ void k_scan() {
    __shared__ int sbuf[1024];
    __shared__ int carry;
    int t = threadIdx.x;
    if (t == 0) carry = 0;
    __syncthreads();
    for (int base = 0; base < Nn; base += 1024) {
        int i = base + t;
        int v = (i < Nn) ? g_deg[i] : 0;
        sbuf[t] = v;
        __syncthreads();
        for (int off = 1; off < 1024; off <<= 1) {
            int add = (t >= off) ? sbuf[t - off] : 0;
            __syncthreads();
            sbuf[t] += add;
            __syncthreads();
        }
        int incl = sbuf[t];
        int excl = carry + incl - v;
        if (i < Nn) { g_off[i] = excl; g_cur[i] = excl; }
        int total = sbuf[1023];
        __syncthreads();
        if (t == 0) carry += total;
        __syncthreads();
    }
    if (t == 0) g_off[Nn] = carry;
}

__global__ void k_scatter(const int* __restrict__ src, const int* __restrict__ dst) {
    int i = blockIdx.x * blockDim.x + threadIdx.x;
    if (i < Ee) {
        int d = dst[i];
        int p = atomicAdd(&g_cur[d], 1);
        g_csr_src[p] = src[i];
        g_csr_eid[p] = i;
    }
}

// ---------------- GEMM1: feat = x@Wfc, res = x@Wres (fused over 1024 cols) ----------------
// BM=64, BN=64, BK=32, 256 threads, 4x4 micro-tile
__global__ void k_gemm_fc_res(const float* __restrict__ X,
                              const float* __restrict__ Wfc,
                              const float* __restrict__ Wres) {
    __shared__ float As[64][33];
    __shared__ float Bs[32][64];
    int t = threadIdx.x;
    int tx = t & 15, ty = t >> 4;
    int row0 = blockIdx.x * 64;
    int col0 = blockIdx.y * 64;           // 0..1023 logical
    const float* W = (col0 < HDim) ? Wfc : Wres;
    float* C       = (col0 < HDim) ? g_feat : g_res;
    int wc0 = col0 & (HDim - 1);

    float acc[4][4];
#pragma unroll
    for (int i = 0; i < 4; i++)
#pragma unroll
        for (int j = 0; j < 4; j++) acc[i][j] = 0.f;

    for (int k0 = 0; k0 < Dd; k0 += 32) {
        // load A tile 64x32
#pragma unroll
        for (int i = 0; i < 2; i++) {
            int idx4 = t + 256 * i;
            int r = idx4 >> 3, c4 = (idx4 & 7) * 4;
            int gr = row0 + r;
            float4 v = make_float4(0.f, 0.f, 0.f, 0.f);
            if (gr < Nn) v = *reinterpret_cast<const float4*>(X + gr * Dd + k0 + c4);
            As[r][c4 + 0] = v.x; As[r][c4 + 1] = v.y;
            As[r][c4 + 2] = v.z; As[r][c4 + 3] = v.w;
        }
        // load B tile 32x64
#pragma unroll
        for (int i = 0; i < 2; i++) {
            int idx4 = t + 256 * i;
            int r = idx4 >> 4, c4 = (idx4 & 15) * 4;
            *reinterpret_cast<float4*>(&Bs[r][c4]) =
                *reinterpret_cast<const float4*>(W + (k0 + r) * HDim + wc0 + c4);
        }
        __syncthreads();
#pragma unroll
        for (int kk = 0; kk < 32; kk++) {
            float a0 = As[ty * 4 + 0][kk];
            float a1 = As[ty * 4 + 1][kk];
            float a2 = As[ty * 4 + 2][kk];
            float a3 = As[ty * 4 + 3][kk];
            float4 b = *reinterpret_cast<const float4*>(&Bs[kk][tx * 4]);
            acc[0][0] += a0 * b.x; acc[0][1] += a0 * b.y; acc[0][2] += a0 * b.z; acc[0][3] += a0 * b.w;
            acc[1][0] += a1 * b.x; acc[1][1] += a1 * b.y; acc[1][2] += a1 * b.z; acc[1][3] += a1 * b.w;
            acc[2][0] += a2 * b.x; acc[2][1] += a2 * b.y; acc[2][2] += a2 * b.z; acc[2][3] += a2 * b.w;
            acc[3][0] += a3 * b.x; acc[3][1] += a3 * b.y; acc[3][2] += a3 * b.z; acc[3][3] += a3 * b.w;
        }
        __syncthreads();
    }
#pragma unroll
    for (int i = 0; i < 4; i++) {
        int gr = row0 + ty * 4 + i;
        if (gr < Nn) {
            float4 v = make_float4(acc[i][0], acc[i][1], acc[i][2], acc[i][3]);
            *reinterpret_cast<float4*>(C + gr * HDim + wc0 + tx * 4) = v;
        }
    }
}

// ---------------- el/er: per-node dot(feat, attn) ----------------
__global__ void k_elr(const float* __restrict__ al, const float* __restrict__ ar) {
    int gt = blockIdx.x * blockDim.x + threadIdx.x;
    int node = gt >> 5;
    int lane = gt & 31;
    if (node >= Nn) return;
    const float* f = g_feat + node * HDim;
#pragma unroll
    for (int h = 0; h < Hh; h++) {
        float sl = 0.f, sr = 0.f;
#pragma unroll
        for (int i = 0; i < 4; i++) {
            int idx = h * 128 + lane + 32 * i;
            float v = f[idx];
            sl += v * al[idx];
            sr += v * ar[idx];
        }
#pragma unroll
        for (int o = 16; o; o >>= 1) {
            sl += __shfl_xor_sync(0xffffffffu, sl, o);
            sr += __shfl_xor_sync(0xffffffffu, sr, o);
        }
        if (lane == 0) {
            g_el[node * Hh + h] = sl;
            g_er[node * Hh + h] = sr;
        }
    }
}

__global__ void k_init_mz() {
    int i = blockIdx.x * blockDim.x + threadIdx.x;
    if (i < Nn * Hh) { g_m[i] = -FLT_MAX; g_z[i] = 0.f; }
}

// ---------------- edge logits + segment max ----------------
__global__ void k_edge_logit(const int* __restrict__ src, const int* __restrict__ dst) {
    int e = blockIdx.x * blockDim.x + threadIdx.x;
    if (e >= Ee) return;
    int s = src[e], d = dst[e];
    float4 a = *reinterpret_cast<const float4*>(g_el + s * 4);
    float4 b = *reinterpret_cast<const float4*>(g_er + d * 4);
    float4 ev;
    ev.x = a.x + b.x; ev.x = ev.x > 0.f ? ev.x : NEG_ATTN * ev.x;
    ev.y = a.y + b.y; ev.y = ev.y > 0.f ? ev.y : NEG_ATTN * ev.y;
    ev.z = a.z + b.z; ev.z = ev.z > 0.f ? ev.z : NEG_ATTN * ev.z;
    ev.w = a.w + b.w; ev.w = ev.w > 0.f ? ev.w : NEG_ATTN * ev.w;
    *reinterpret_cast<float4*>(g_ex + e * 4) = ev;
    atomicMaxF(&g_m[d * 4 + 0], ev.x);
    atomicMaxF(&g_m[d * 4 + 1], ev.y);
    atomicMaxF(&g_m[d * 4 + 2], ev.z);
    atomicMaxF(&g_m[d * 4 + 3], ev.w);
}

// ---------------- exp + segment sum ----------------
__global__ void k_edge_exp(const int* __restrict__ dst) {
    int e = blockIdx.x * blockDim.x + threadIdx.x;
    if (e >= Ee) return;
    int d = dst[e];
    float4 ev = *reinterpret_cast<const float4*>(g_ex + e * 4);
    float4 mv = *reinterpret_cast<const float4*>(g_m + d * 4);
    ev.x = expf(ev.x - mv.x);
    ev.y = expf(ev.y - mv.y);
    ev.z = expf(ev.z - mv.z);
    ev.w = expf(ev.w - mv.w);
    *reinterpret_cast<float4*>(g_ex + e * 4) = ev;
    atomicAdd(&g_z[d * 4 + 0], ev.x);
    atomicAdd(&g_z[d * 4 + 1], ev.y);
    atomicAdd(&g_z[d * 4 + 2], ev.z);
    atomicAdd(&g_z[d * 4 + 3], ev.w);
}

// ---------------- aggregation: one block (128 thr) per dst node ----------------
// writes h into g_res in place (reads res only at its own output element)
__global__ void k_aggregate(const float* __restrict__ bgat) {
    int dn = blockIdx.x;
    int t = threadIdx.x;   // 0..127, d index; head = j
    int s = g_off[dn], en = g_off[dn + 1];
    float4 zv = *reinterpret_cast<const float4*>(g_z + dn * 4);
    float iz0 = 1.f / fmaxf(zv.x, 1e-20f);
    float iz1 = 1.f / fmaxf(zv.y, 1e-20f);
    float iz2 = 1.f / fmaxf(zv.z, 1e-20f);
    float iz3 = 1.f / fmaxf(zv.w, 1e-20f);
    float acc0 = 0.f, acc1 = 0.f, acc2 = 0.f, acc3 = 0.f;
    for (int p = s; p < en; p++) {
        int sn  = g_csr_src[p];
        int eid = g_csr_eid[p];
        float4 exv = *reinterpret_cast<const float4*>(g_ex + eid * 4);
        const float* fr = g_feat + sn * HDim + t;
        acc0 += (exv.x * iz0) * fr[0];
        acc1 += (exv.y * iz1) * fr[128];
        acc2 += (exv.z * iz2) * fr[256];
        acc3 += (exv.w * iz3) * fr[384];
    }
    int o = dn * HDim + t;
    float r;
    r = acc0 + g_res[o + 0]   + bgat[t + 0];   r = r > 0.f ? r : NEG_ACT * r; g_res[o + 0]   = r;
    r = acc1 + g_res[o + 128] + bgat[t + 128]; r = r > 0.f ? r : NEG_ACT * r; g_res[o + 128] = r;
    r = acc2 + g_res[o + 256] + bgat[t + 256]; r = r > 0.f ? r : NEG_ACT * r; g_res[o + 256] = r;
    r = acc3 + g_res[o + 384] + bgat[t + 384]; r = r > 0.f ? r : NEG_ACT * r; g_res[o + 384] = r;
}

// ---------------- GEMM2 + bias + LayerNorm: out = LN(h @ Wnrm + bn) ----------------
// BM=32, BN=128(full), BK=32, 256 threads; warp ty owns rows 4ty..4ty+3
__global__ void k_gemm_ln(const float* __restrict__ W,
                          const float* __restrict__ bn,
                          const float* __restrict__ gam,
                          const float* __restrict__ bet,
                          float* __restrict__ out) {
    __shared__ float Hs[32][36];
    __shared__ float Ws[32][128];
    int t = threadIdx.x;
    int tx = t & 31, ty = t >> 5;
    int row0 = blockIdx.x * 32;

    float acc[4][4];
#pragma unroll
    for (int i = 0; i < 4; i++)
#pragma unroll
        for (int j = 0; j < 4; j++) acc[i][j] = 0.f;

    for (int k0 = 0; k0 < HDim; k0 += 32) {
        // Hs: 32 rows x 32 k, from g_res
        {
            int r = t >> 3, c4 = (t & 7) * 4;
            int gr = row0 + r;
            float4 v = make_float4(0.f, 0.f, 0.f, 0.f);
            if (gr < Nn) v = *reinterpret_cast<const float4*>(g_res + gr * HDim + k0 + c4);
            Hs[r][c4 + 0] = v.x; Hs[r][c4 + 1] = v.y;
            Hs[r][c4 + 2] = v.z; Hs[r][c4 + 3] = v.w;
        }
        // Ws: 32 k x 128 cols, W row-major [512][128]
#pragma unroll
        for (int i = 0; i < 4; i++) {
            int idx4 = t + 256 * i;
            int r = idx4 >> 5, c4 = (idx4 & 31) * 4;
            *reinterpret_cast<float4*>(&Ws[r][c4]) =
                *reinterpret_cast<const float4*>(W + (k0 + r) * Dd + c4);
        }
        __syncthreads();
#pragma unroll
        for (int kk = 0; kk < 32; kk++) {
            float a0 = Hs[ty * 4 + 0][kk];
            float a1 = Hs[ty * 4 + 1][kk];
            float a2 = Hs[ty * 4 + 2][kk];
            float a3 = Hs[ty * 4 + 3][kk];
            float4 b = *reinterpret_cast<const float4*>(&Ws[kk][tx * 4]);
            acc[0][0] += a0 * b.x; acc[0][1] += a0 * b.y; acc[0][2] += a0 * b.z; acc[0][3] += a0 * b.w;
            acc[1][0] += a1 * b.x; acc[1][1] += a1 * b.y; acc[1][2] += a1 * b.z; acc[1][3] += a1 * b.w;
            acc[2][0] += a2 * b.x; acc[2][1] += a2 * b.y; acc[2][2] += a2 * b.z; acc[2][3] += a2 * b.w;
            acc[3][0] += a3 * b.x; acc[3][1] += a3 * b.y; acc[3][2] += a3 * b.z; acc[3][3] += a3 * b.w;
        }
        __syncthreads();
    }

    float4 bnv = *reinterpret_cast<const float4*>(bn  + tx * 4);
    float4 gv  = *reinterpret_cast<const float4*>(gam + tx * 4);
    float4 bv  = *reinterpret_cast<const float4*>(bet + tx * 4);
#pragma unroll
    for (int i = 0; i < 4; i++) {
        int gr = row0 + ty * 4 + i;
        float y0 = acc[i][0] + bnv.x;
        float y1 = acc[i][1] + bnv.y;
        float y2 = acc[i][2] + bnv.z;
        float y3 = acc[i][3] + bnv.w;
        float s  = y0 + y1 + y2 + y3;
        float sq = y0 * y0 + y1 * y1 + y2 * y2 + y3 * y3;
#pragma unroll
        for (int o = 16; o; o >>= 1) {
            s  += __shfl_xor_sync(0xffffffffu, s,  o);
            sq += __shfl_xor_sync(0xffffffffu, sq, o);
        }
        float mu  = s * (1.f / 128.f);
        float var = sq * (1.f / 128.f) - mu * mu;
        float rstd = rsqrtf(var + 1e-5f);
        if (gr < Nn) {
            float4 ov;
            ov.x = (y0 - mu) * rstd * gv.x + bv.x;
            ov.y = (y1 - mu) * rstd * gv.y + bv.y;
            ov.z = (y2 - mu) * rstd * gv.z + bv.z;
            ov.w = (y3 - mu) * rstd * gv.w + bv.w;
            *reinterpret_cast<float4*>(out + gr * Dd + tx * 4) = ov;
        }
    }
}

// ---------------- launch ----------------
extern "C" void kernel_launch(void* const* d_in, const int* in_sizes, int n_in,
                              void* d_out, int out_size) {
    const float* features = (const float*)d_in[0];
    const int*   src      = (const int*)  d_in[1];
    const int*   dst      = (const int*)  d_in[2];
    const float* W_fc     = (const float*)d_in[3];
    const float* attn_l   = (const float*)d_in[4];
    const float* attn_r   = (const float*)d_in[5];
    const float* W_res    = (const float*)d_in[6];
    const float* b_gat    = (const float*)d_in[7];
    const float* W_nrm    = (const float*)d_in[8];
    const float* b_nrm    = (const float*)d_in[9];
    const float* ln_g     = (const float*)d_in[10];
    const float* ln_b     = (const float*)d_in[11];
    float* out = (float*)d_out;

    float *xa = nullptr, *xb = nullptr;
    cudaGetSymbolAddress((void**)&xa, g_xa);
    cudaGetSymbolAddress((void**)&xb, g_xb);

    // CSR build (edges are layer-invariant)
    k_zero_deg<<<(Nn + 255) / 256, 256>>>();
    k_hist<<<(Ee + 255) / 256, 256>>>(dst);
    k_scan<<<1, 1024>>>();
    k_scatter<<<(Ee + 255) / 256, 256>>>(src, dst);

    const float* x = features;
    for (int l = 0; l < 4; l++) {
        const float* Wfc = W_fc  + (size_t)l * Dd * HDim;
        const float* Wre = W_res + (size_t)l * Dd * HDim;
        const float* al  = attn_l + (size_t)l * Hh * Dd;
        const float* ar  = attn_r + (size_t)l * Hh * Dd;
        const float* bg  = b_gat + (size_t)l * HDim;
        const float* Wn  = W_nrm + (size_t)l * HDim * Dd;
        const float* bnp = b_nrm + (size_t)l * Dd;
        const float* gp  = ln_g  + (size_t)l * Dd;
        const float* bp  = ln_b  + (size_t)l * Dd;

        k_gemm_fc_res<<<dim3((Nn + 63) / 64, 16), 256>>>(x, Wfc, Wre);
        k_elr<<<(Nn * 32 + 255) / 256, 256>>>(al, ar);
        k_init_mz<<<(Nn * Hh + 255) / 256, 256>>>();
        k_edge_logit<<<(Ee + 255) / 256, 256>>>(src, dst);
        k_edge_exp<<<(Ee + 255) / 256, 256>>>(dst);
        k_aggregate<<<Nn, 128>>>(bg);

        float* xo = (l == 3) ? out : ((l & 1) ? xb : xa);
        k_gemm_ln<<<(Nn + 31) / 32, 256>>>(Wn, bnp, gp, bp, xo);
        x = xo;
    }
}

// round 3
// speedup vs baseline: 1.0443x; 1.0443x over previous
#include <cuda_runtime.h>
#include <math.h>
#include <float.h>
#include <stdint.h>

#define Nn 50000
#define Ee 800000
#define Hh 4
#define Dd 128
#define HDim 512
#define NEG_ATTN 0.2f
#define NEG_ACT 0.01f

// ---------------- scratch (static device allocations) ----------------
__device__ float g_feat[Nn * HDim];
__device__ float g_res [Nn * HDim];
__device__ float g_xa  [Nn * Dd];
__device__ float g_xb  [Nn * Dd];
__device__ float g_el  [Nn * Hh];
__device__ float g_er  [Nn * Hh];
__device__ float g_m   [Nn * Hh];
__device__ float g_z   [Nn * Hh];
__device__ float g_ex  [Ee * Hh];
__device__ int   g_deg [Nn];
__device__ int   g_off [Nn + 1];
__device__ int   g_cur [Nn];
__device__ int   g_csr_src[Ee];
__device__ int   g_csr_eid[Ee];

__device__ __forceinline__ void atomicMaxF(float* addr, float v) {
    if (v >= 0.f) atomicMax((int*)addr, __float_as_int(v));
    else          atomicMin((unsigned int*)addr, __float_as_uint(v));
}

__device__ __forceinline__ uint32_t f2tf32(float x) {
    uint32_t r;
    asm("cvt.rna.tf32.f32 %0, %1;" : "=r"(r) : "f"(x));
    return r;
}

__device__ __forceinline__ void mma_tf32(float c[4], const uint32_t a[4], const uint32_t b[2]) {
    asm volatile(
        "mma.sync.aligned.m16n8k8.row.col.f32.tf32.tf32.f32 "
        "{%0,%1,%2,%3}, {%4,%5,%6,%7}, {%8,%9}, {%0,%1,%2,%3};"
        : "+f"(c[0]), "+f"(c[1]), "+f"(c[2]), "+f"(c[3])
        : "r"(a[0]), "r"(a[1]), "r"(a[2]), "r"(a[3]), "r"(b[0]), "r"(b[1]));
}

// ---------------- CSR build ----------------
__global__ void k_zero_deg() {
    int i = blockIdx.x * blockDim.x + threadIdx.x;
    if (i < Nn) g_deg[i] = 0;
}

__global__ void k_hist(const int* __restrict__ dst) {
    int i = blockIdx.x * blockDim.x + threadIdx.x;
    if (i < Ee) atomicAdd(&g_deg[dst[i]], 1);
}

__global__ void k_scan() {
    __shared__ int sbuf[1024];
    __shared__ int carry;
    int t = threadIdx.x;
    if (t == 0) carry = 0;
    __syncthreads();
    for (int base = 0; base < Nn; base += 1024) {
        int i = base + t;
        int v = (i < Nn) ? g_deg[i] : 0;
        sbuf[t] = v;
        __syncthreads();
        for (int off = 1; off < 1024; off <<= 1) {
            int add = (t >= off) ? sbuf[t - off] : 0;
            __syncthreads();
            sbuf[t] += add;
            __syncthreads();
        }
        int incl = sbuf[t];
        int excl = carry + incl - v;
        if (i < Nn) { g_off[i] = excl; g_cur[i] = excl; }
        int total = sbuf[1023];
        __syncthreads();
        if (t == 0) carry += total;
        __syncthreads();
    }
    if (t == 0) g_off[Nn] = carry;
}

__global__ void k_scatter(const int* __restrict__ src, const int* __restrict__ dst) {
    int i = blockIdx.x * blockDim.x + threadIdx.x;
    if (i < Ee) {
        int d = dst[i];
        int p = atomicAdd(&g_cur[d], 1);
        g_csr_src[p] = src[i];
        g_csr_eid[p] = i;
    }
}

// ============ tensor-core split-TF32 GEMM1: feat = x@Wfc, res = x@Wres ============
// BM=128, BN=128, BK=16; 8 warps as 2(M) x 4(N); warp tile 64x32.
__global__ void k_gemm_tc_fc_res(const float* __restrict__ X,
                                 const float* __restrict__ Wfc,
                                 const float* __restrict__ Wres) {
    __shared__ uint32_t Ah[16][136], Al[16][136], Bh[16][136], Bl[16][136];
    int t = threadIdx.x;
    int lane = t & 31, wid = t >> 5;
    int gr = lane >> 2, gc = lane & 3;
    int wm = (wid & 1) * 64;
    int wn = (wid >> 1) * 32;
    int row0 = blockIdx.x * 128;
    int col0 = blockIdx.y * 128;     // 0..1023 logical
    const float* W = (col0 < HDim) ? Wfc : Wres;
    float* C       = (col0 < HDim) ? g_feat : g_res;
    int wc0 = col0 & (HDim - 1);

    float c[4][4][4];
#pragma unroll
    for (int i = 0; i < 4; i++)
#pragma unroll
        for (int j = 0; j < 4; j++)
#pragma unroll
            for (int q = 0; q < 4; q++) c[i][j][q] = 0.f;

    for (int k0 = 0; k0 < Dd; k0 += 16) {
        // A tile: 128 rows x 16 k -> smem [k][m], hi/lo
#pragma unroll
        for (int u = 0; u < 2; u++) {
            int idx = t + 256 * u;           // 0..511
            int r = idx >> 2, kc = (idx & 3) * 4;
            int grow = row0 + r;
            float4 v = make_float4(0.f, 0.f, 0.f, 0.f);
            if (grow < Nn) v = *reinterpret_cast<const float4*>(X + grow * Dd + k0 + kc);
            float xs[4] = {v.x, v.y, v.z, v.w};
#pragma unroll
            for (int j = 0; j < 4; j++) {
                uint32_t hi = f2tf32(xs[j]);
                Ah[kc + j][r] = hi;
                Al[kc + j][r] = f2tf32(xs[j] - __uint_as_float(hi));
            }
        }
        // B tile: 16 k x 128 n -> smem [k][n], hi/lo
#pragma unroll
        for (int u = 0; u < 2; u++) {
            int idx = t + 256 * u;
            int r = idx >> 5, c4 = (idx & 31) * 4;
            float4 v = *reinterpret_cast<const float4*>(W + (k0 + r) * HDim + wc0 + c4);
            float xs[4] = {v.x, v.y, v.z, v.w};
#pragma unroll
            for (int j = 0; j < 4; j++) {
                uint32_t hi = f2tf32(xs[j]);
                Bh[r][c4 + j] = hi;
                Bl[r][c4 + j] = f2tf32(xs[j] - __uint_as_float(hi));
            }
        }
        __syncthreads();
#pragma unroll
        for (int kk = 0; kk < 16; kk += 8) {
            uint32_t ah[4][4], al_[4][4], bh[4][2], bl_[4][2];
#pragma unroll
            for (int i = 0; i < 4; i++) {
                int mb = wm + i * 16;
                ah[i][0]  = Ah[kk + gc][mb + gr];     ah[i][1]  = Ah[kk + gc][mb + gr + 8];
                ah[i][2]  = Ah[kk + gc + 4][mb + gr]; ah[i][3]  = Ah[kk + gc + 4][mb + gr + 8];
                al_[i][0] = Al[kk + gc][mb + gr];     al_[i][1] = Al[kk + gc][mb + gr + 8];
                al_[i][2] = Al[kk + gc + 4][mb + gr]; al_[i][3] = Al[kk + gc + 4][mb + gr + 8];
            }
#pragma unroll
            for (int j = 0; j < 4; j++) {
                int nb = wn + j * 8;
                bh[j][0]  = Bh[kk + gc][nb + gr];     bh[j][1]  = Bh[kk + gc + 4][nb + gr];
                bl_[j][0] = Bl[kk + gc][nb + gr];     bl_[j][1] = Bl[kk + gc + 4][nb + gr];
            }
#pragma unroll
            for (int i = 0; i < 4; i++)
#pragma unroll
                for (int j = 0; j < 4; j++) {
                    mma_tf32(c[i][j], ah[i], bh[j]);
                    mma_tf32(c[i][j], ah[i], bl_[j]);
                    mma_tf32(c[i][j], al_[i], bh[j]);
                }
        }
        __syncthreads();
    }
#pragma unroll
    for (int i = 0; i < 4; i++) {
        int r0 = row0 + wm + i * 16 + gr;
#pragma unroll
        for (int j = 0; j < 4; j++) {
            int col = wc0 + wn + j * 8 + 2 * gc;
            if (r0 < Nn)
                *reinterpret_cast<float2*>(C + (size_t)r0 * HDim + col) = make_float2(c[i][j][0], c[i][j][1]);
            if (r0 + 8 < Nn)
                *reinterpret_cast<float2*>(C + (size_t)(r0 + 8) * HDim + col) = make_float2(c[i][j][2], c[i][j][3]);
        }
    }
}

// ============ tensor-core split-TF32 GEMM2 + bias + LayerNorm ============
// BM=128, BN=128 (full width), BK=16; same warp layout.
__global__ void k_gemm_tc_ln(const float* __restrict__ Wn,
                             const float* __restrict__ bn,
                             const float* __restrict__ gam,
                             const float* __restrict__ bet,
                             float* __restrict__ out) {
    __shared__ uint32_t Ah[16][136], Al[16][136], Bh[16][136], Bl[16][136];
    __shared__ float red_s[4][128], red_q[4][128];
    int t = threadIdx.x;
    int lane = t & 31, wid = t >> 5;
    int gr = lane >> 2, gc = lane & 3;
    int wm = (wid & 1) * 64;
    int wnid = wid >> 1;
    int wn = wnid * 32;
    int row0 = blockIdx.x * 128;

    float c[4][4][4];
#pragma unroll
    for (int i = 0; i < 4; i++)
#pragma unroll
        for (int j = 0; j < 4; j++)
#pragma unroll
            for (int q = 0; q < 4; q++) c[i][j][q] = 0.f;

    for (int k0 = 0; k0 < HDim; k0 += 16) {
        // A tile from g_res: 128 x 16
#pragma unroll
        for (int u = 0; u < 2; u++) {
            int idx = t + 256 * u;
            int r = idx >> 2, kc = (idx & 3) * 4;
            int grow = row0 + r;
            float4 v = make_float4(0.f, 0.f, 0.f, 0.f);
            if (grow < Nn) v = *reinterpret_cast<const float4*>(g_res + (size_t)grow * HDim + k0 + kc);
            float xs[4] = {v.x, v.y, v.z, v.w};
#pragma unroll
            for (int j = 0; j < 4; j++) {
                uint32_t hi = f2tf32(xs[j]);
                Ah[kc + j][r] = hi;
                Al[kc + j][r] = f2tf32(xs[j] - __uint_as_float(hi));
            }
        }
        // B tile from Wn [512][128]: 16 x 128
#pragma unroll
        for (int u = 0; u < 2; u++) {
            int idx = t + 256 * u;
            int r = idx >> 5, c4 = (idx & 31) * 4;
            float4 v = *reinterpret_cast<const float4*>(Wn + (k0 + r) * Dd + c4);
            float xs[4] = {v.x, v.y, v.z, v.w};
#pragma unroll
            for (int j = 0; j < 4; j++) {
                uint32_t hi = f2tf32(xs[j]);
                Bh[r][c4 + j] = hi;
                Bl[r][c4 + j] = f2tf32(xs[j] - __uint_as_float(hi));
            }
        }
        __syncthreads();
#pragma unroll
        for (int kk = 0; kk < 16; kk += 8) {
            uint32_t ah[4][4], al_[4][4], bh[4][2], bl_[4][2];
#pragma unroll
            for (int i = 0; i < 4; i++) {
                int mb = wm + i * 16;
                ah[i][0]  = Ah[kk + gc][mb + gr];     ah[i][1]  = Ah[kk + gc][mb + gr + 8];
                ah[i][2]  = Ah[kk + gc + 4][mb + gr]; ah[i][3]  = Ah[kk + gc + 4][mb + gr + 8];
                al_[i][0] = Al[kk + gc][mb + gr];     al_[i][1] = Al[kk + gc][mb + gr + 8];
                al_[i][2] = Al[kk + gc + 4][mb + gr]; al_[i][3] = Al[kk + gc + 4][mb + gr + 8];
            }
#pragma unroll
            for (int j = 0; j < 4; j++) {
                int nb = wn + j * 8;
                bh[j][0]  = Bh[kk + gc][nb + gr];     bh[j][1]  = Bh[kk + gc + 4][nb + gr];
                bl_[j][0] = Bl[kk + gc][nb + gr];     bl_[j][1] = Bl[kk + gc + 4][nb + gr];
            }
#pragma unroll
            for (int i = 0; i < 4; i++)
#pragma unroll
                for (int j = 0; j < 4; j++) {
                    mma_tf32(c[i][j], ah[i], bh[j]);
                    mma_tf32(c[i][j], ah[i], bl_[j]);
                    mma_tf32(c[i][j], al_[i], bh[j]);
                }
        }
        __syncthreads();
    }

    // ---- fused bias + LayerNorm epilogue ----
    float bnv[4][2], gv[4][2], bv[4][2];
#pragma unroll
    for (int j = 0; j < 4; j++) {
        int col = wn + j * 8 + 2 * gc;
        bnv[j][0] = bn[col];  bnv[j][1] = bn[col + 1];
        gv[j][0]  = gam[col]; gv[j][1]  = gam[col + 1];
        bv[j][0]  = bet[col]; bv[j][1]  = bet[col + 1];
    }

    // partial row sums: rows rb0 = wm+i*16+gr, rb1 = rb0+8
#pragma unroll
    for (int i = 0; i < 4; i++) {
        int rb0 = wm + i * 16 + gr;
        float s0 = 0.f, q0 = 0.f, s1 = 0.f, q1 = 0.f;
#pragma unroll
        for (int j = 0; j < 4; j++) {
            float y00 = c[i][j][0] + bnv[j][0];
            float y01 = c[i][j][1] + bnv[j][1];
            float y10 = c[i][j][2] + bnv[j][0];
            float y11 = c[i][j][3] + bnv[j][1];
            s0 += y00 + y01;  q0 += y00 * y00 + y01 * y01;
            s1 += y10 + y11;  q1 += y10 * y10 + y11 * y11;
        }
#pragma unroll
        for (int o = 1; o < 4; o <<= 1) {
            s0 += __shfl_xor_sync(0xffffffffu, s0, o);
            q0 += __shfl_xor_sync(0xffffffffu, q0, o);
            s1 += __shfl_xor_sync(0xffffffffu, s1, o);
            q1 += __shfl_xor_sync(0xffffffffu, q1, o);
        }
        if (gc == 0) {
            red_s[wnid][rb0]     = s0;  red_q[wnid][rb0]     = q0;
            red_s[wnid][rb0 + 8] = s1;  red_q[wnid][rb0 + 8] = q1;
        }
    }
    __syncthreads();

#pragma unroll
    for (int i = 0; i < 4; i++) {
        int rb0 = wm + i * 16 + gr;
        float s0 = red_s[0][rb0] + red_s[1][rb0] + red_s[2][rb0] + red_s[3][rb0];
        float q0 = red_q[0][rb0] + red_q[1][rb0] + red_q[2][rb0] + red_q[3][rb0];
        float s1 = red_s[0][rb0 + 8] + red_s[1][rb0 + 8] + red_s[2][rb0 + 8] + red_s[3][rb0 + 8];
        float q1 = red_q[0][rb0 + 8] + red_q[1][rb0 + 8] + red_q[2][rb0 + 8] + red_q[3][rb0 + 8];
        float mu0 = s0 * (1.f / 128.f);
        float mu1 = s1 * (1.f / 128.f);
        float rstd0 = rsqrtf(q0 * (1.f / 128.f) - mu0 * mu0 + 1e-5f);
        float rstd1 = rsqrtf(q1 * (1.f / 128.f) - mu1 * mu1 + 1e-5f);
        int r0 = row0 + rb0;
#pragma unroll
        for (int j = 0; j < 4; j++) {
            int col = wn + j * 8 + 2 * gc;
            if (r0 < Nn) {
                float y00 = c[i][j][0] + bnv[j][0];
                float y01 = c[i][j][1] + bnv[j][1];
                float2 ov = make_float2((y00 - mu0) * rstd0 * gv[j][0] + bv[j][0],
                                        (y01 - mu0) * rstd0 * gv[j][1] + bv[j][1]);
                *reinterpret_cast<float2*>(out + (size_t)r0 * Dd + col) = ov;
            }
            if (r0 + 8 < Nn) {
                float y10 = c[i][j][2] + bnv[j][0];
                float y11 = c[i][j][3] + bnv[j][1];
                float2 ov = make_float2((y10 - mu1) * rstd1 * gv[j][0] + bv[j][0],
                                        (y11 - mu1) * rstd1 * gv[j][1] + bv[j][1]);
                *reinterpret_cast<float2*>(out + (size_t)(r0 + 8) * Dd + col) = ov;
            }
        }
    }
}

// ---------------- el/er: per-node dot(feat, attn) ----------------
__global__ void k_elr(const float* __restrict__ al, const float* __restrict__ ar) {
    int gt = blockIdx.x * blockDim.x + threadIdx.x;
    int node = gt >> 5;
    int lane = gt & 31;
    if (node >= Nn) return;
    const float* f = g_feat + (size_t)node * HDim;
#pragma unroll
    for (int h = 0; h < Hh; h++) {
        float sl = 0.f, sr = 0.f;
#pragma unroll
        for (int i = 0; i < 4; i++) {
            int idx = h * 128 + lane + 32 * i;
            float v = f[idx];
            sl += v * al[idx];
            sr += v * ar[idx];
        }
#pragma unroll
        for (int o = 16; o; o >>= 1) {
            sl += __shfl_xor_sync(0xffffffffu, sl, o);
            sr += __shfl_xor_sync(0xffffffffu, sr, o);
        }
        if (lane == 0) {
            g_el[node * Hh + h] = sl;
            g_er[node * Hh + h] = sr;
        }
    }
}

__global__ void k_init_mz() {
    int i = blockIdx.x * blockDim.x + threadIdx.x;
    if (i < Nn * Hh) { g_m[i] = -FLT_MAX; g_z[i] = 0.f; }
}

// ---------------- edge logits + segment max ----------------
__global__ void k_edge_logit(const int* __restrict__ src, const int* __restrict__ dst) {
    int e = blockIdx.x * blockDim.x + threadIdx.x;
    if (e >= Ee) return;
    int s = src[e], d = dst[e];
    float4 a = *reinterpret_cast<const float4*>(g_el + s * 4);
    float4 b = *reinterpret_cast<const float4*>(g_er + d * 4);
    float4 ev;
    ev.x = a.x + b.x; ev.x = ev.x > 0.f ? ev.x : NEG_ATTN * ev.x;
    ev.y = a.y + b.y; ev.y = ev.y > 0.f ? ev.y : NEG_ATTN * ev.y;
    ev.z = a.z + b.z; ev.z = ev.z > 0.f ? ev.z : NEG_ATTN * ev.z;
    ev.w = a.w + b.w; ev.w = ev.w > 0.f ? ev.w : NEG_ATTN * ev.w;
    *reinterpret_cast<float4*>(g_ex + e * 4) = ev;
    atomicMaxF(&g_m[d * 4 + 0], ev.x);
    atomicMaxF(&g_m[d * 4 + 1], ev.y);
    atomicMaxF(&g_m[d * 4 + 2], ev.z);
    atomicMaxF(&g_m[d * 4 + 3], ev.w);
}

// ---------------- exp + segment sum ----------------
__global__ void k_edge_exp(const int* __restrict__ dst) {
    int e = blockIdx.x * blockDim.x + threadIdx.x;
    if (e >= Ee) return;
    int d = dst[e];
    float4 ev = *reinterpret_cast<const float4*>(g_ex + e * 4);
    float4 mv = *reinterpret_cast<const float4*>(g_m + d * 4);
    ev.x = expf(ev.x - mv.x);
    ev.y = expf(ev.y - mv.y);
    ev.z = expf(ev.z - mv.z);
    ev.w = expf(ev.w - mv.w);
    *reinterpret_cast<float4*>(g_ex + e * 4) = ev;
    atomicAdd(&g_z[d * 4 + 0], ev.x);
    atomicAdd(&g_z[d * 4 + 1], ev.y);
    atomicAdd(&g_z[d * 4 + 2], ev.z);
    atomicAdd(&g_z[d * 4 + 3], ev.w);
}

// ---------------- aggregation: one block (128 thr) per dst node ----------------
__global__ void k_aggregate(const float* __restrict__ bgat) {
    int dn = blockIdx.x;
    int t = threadIdx.x;
    int s = g_off[dn], en = g_off[dn + 1];
    float4 zv = *reinterpret_cast<const float4*>(g_z + dn * 4);
    float iz0 = 1.f / fmaxf(zv.x, 1e-20f);
    float iz1 = 1.f / fmaxf(zv.y, 1e-20f);
    float iz2 = 1.f / fmaxf(zv.z, 1e-20f);
    float iz3 = 1.f / fmaxf(zv.w, 1e-20f);
    float acc0 = 0.f, acc1 = 0.f, acc2 = 0.f, acc3 = 0.f;
    for (int p = s; p < en; p++) {
        int sn  = g_csr_src[p];
        int eid = g_csr_eid[p];
        float4 exv = *reinterpret_cast<const float4*>(g_ex + eid * 4);
        const float* fr = g_feat + (size_t)sn * HDim + t;
        acc0 += (exv.x * iz0) * fr[0];
        acc1 += (exv.y * iz1) * fr[128];
        acc2 += (exv.z * iz2) * fr[256];
        acc3 += (exv.w * iz3) * fr[384];
    }
    int o = dn * HDim + t;
    float r;
    r = acc0 + g_res[o + 0]   + bgat[t + 0];   r = r > 0.f ? r : NEG_ACT * r; g_res[o + 0]   = r;
    r = acc1 + g_res[o + 128] + bgat[t + 128]; r = r > 0.f ? r : NEG_ACT * r; g_res[o + 128] = r;
    r = acc2 + g_res[o + 256] + bgat[t + 256]; r = r > 0.f ? r : NEG_ACT * r; g_res[o + 256] = r;
    r = acc3 + g_res[o + 384] + bgat[t + 384]; r = r > 0.f ? r : NEG_ACT * r; g_res[o + 384] = r;
}

// ---------------- launch ----------------
extern "C" void kernel_launch(void* const* d_in, const int* in_sizes, int n_in,
                              void* d_out, int out_size) {
    const float* features = (const float*)d_in[0];
    const int*   src      = (const int*)  d_in[1];
    const int*   dst      = (const int*)  d_in[2];
    const float* W_fc     = (const float*)d_in[3];
    const float* attn_l   = (const float*)d_in[4];
    const float* attn_r   = (const float*)d_in[5];
    const float* W_res    = (const float*)d_in[6];
    const float* b_gat    = (const float*)d_in[7];
    const float* W_nrm    = (const float*)d_in[8];
    const float* b_nrm    = (const float*)d_in[9];
    const float* ln_g     = (const float*)d_in[10];
    const float* ln_b     = (const float*)d_in[11];
    float* out = (float*)d_out;

    float *xa = nullptr, *xb = nullptr;
    cudaGetSymbolAddress((void**)&xa, g_xa);
    cudaGetSymbolAddress((void**)&xb, g_xb);

    // CSR build (edges are layer-invariant)
    k_zero_deg<<<(Nn + 255) / 256, 256>>>();
    k_hist<<<(Ee + 255) / 256, 256>>>(dst);
    k_scan<<<1, 1024>>>();
    k_scatter<<<(Ee + 255) / 256, 256>>>(src, dst);

    const float* x = features;
    for (int l = 0; l < 4; l++) {
        const float* Wfc = W_fc  + (size_t)l * Dd * HDim;
        const float* Wre = W_res + (size_t)l * Dd * HDim;
        const float* al  = attn_l + (size_t)l * Hh * Dd;
        const float* ar  = attn_r + (size_t)l * Hh * Dd;
        const float* bg  = b_gat + (size_t)l * HDim;
        const float* Wn  = W_nrm + (size_t)l * HDim * Dd;
        const float* bnp = b_nrm + (size_t)l * Dd;
        const float* gp  = ln_g  + (size_t)l * Dd;
        const float* bp  = ln_b  + (size_t)l * Dd;

        k_gemm_tc_fc_res<<<dim3((Nn + 127) / 128, 8), 256>>>(x, Wfc, Wre);
        k_elr<<<(Nn * 32 + 255) / 256, 256>>>(al, ar);
        k_init_mz<<<(Nn * Hh + 255) / 256, 256>>>();
        k_edge_logit<<<(Ee + 255) / 256, 256>>>(src, dst);
        k_edge_exp<<<(Ee + 255) / 256, 256>>>(dst);
        k_aggregate<<<Nn, 128>>>(bg);

        float* xo = (l == 3) ? out : ((l & 1) ? xb : xa);
        k_gemm_tc_ln<<<(Nn + 127) / 128, 256>>>(Wn, bnp, gp, bp, xo);
        x = xo;
    }
}

// round 6
// speedup vs baseline: 1.7920x; 1.7159x over previous
#include <cuda_runtime.h>
#include <cuda_bf16.h>
#include <math.h>
#include <float.h>
#include <stdint.h>

#define Nn 50000
#define Ee 800000
#define Hh 4
#define Dd 128
#define HDim 512
#define NEG_ATTN 0.2f
#define NEG_ACT 0.01f

// ---------------- scratch (static device allocations) ----------------
__device__ float g_feat[Nn * HDim];
__device__ float g_res [Nn * HDim];
__device__ float g_xa  [Nn * Dd];
__device__ float g_xb  [Nn * Dd];
__device__ float g_el  [Nn * Hh];
__device__ float g_er  [Nn * Hh];
__device__ float g_ex  [(size_t)Ee * Hh];
__device__ int   g_deg [Nn];
__device__ int   g_off [Nn + 1];
__device__ int   g_cur [Nn];
__device__ int   g_csr_src[Ee];
__device__ int   g_slot[Ee];

// pre-split transposed weights (bf16 hi/lo), [n][k] layout
__device__ __nv_bfloat16 g_w1h[4u * 1024 * 128];
__device__ __nv_bfloat16 g_w1l[4u * 1024 * 128];
__device__ __nv_bfloat16 g_w2h[4u * 128 * 512];
__device__ __nv_bfloat16 g_w2l[4u * 128 * 512];

// smem offsets (bytes): 4 tiles of [128][72] bf16 = 18432 each
#define O_ALOo 18432
#define O_BHIo 36864
#define O_BLOo 55296
#define O_PARo 73728
#define SMEM_G1 73728
#define SMEM_G2 (73728 + 1536)

// ---------------- helpers ----------------
__device__ __forceinline__ uint32_t s2u(const void* p) {
    uint32_t a;
    asm("{ .reg .u64 t; cvta.to.shared.u64 t, %1; cvt.u32.u64 %0, t; }" : "=r"(a) : "l"(p));
    return a;
}

#define LDSM4(R, A) \
    asm volatile("ldmatrix.sync.aligned.m8n8.x4.shared.b16 {%0,%1,%2,%3}, [%4];" \
        : "=r"((R)[0]), "=r"((R)[1]), "=r"((R)[2]), "=r"((R)[3]) : "r"(A))

__device__ __forceinline__ void mma_bf16(float d[4], const uint32_t a[4],
                                         uint32_t b0, uint32_t b1) {
    asm volatile(
        "mma.sync.aligned.m16n8k16.row.col.f32.bf16.bf16.f32 "
        "{%0,%1,%2,%3},{%4,%5,%6,%7},{%8,%9},{%0,%1,%2,%3};"
        : "+f"(d[0]), "+f"(d[1]), "+f"(d[2]), "+f"(d[3])
        : "r"(a[0]), "r"(a[1]), "r"(a[2]), "r"(a[3]), "r"(b0), "r"(b1));
}

__device__ __forceinline__ void split2(float x, float y, __nv_bfloat162& h, __nv_bfloat162& lo) {
    h.x = __float2bfloat16_rn(x); h.y = __float2bfloat16_rn(y);
    lo.x = __float2bfloat16_rn(x - __bfloat162float(h.x));
    lo.y = __float2bfloat16_rn(y - __bfloat162float(h.y));
}

// ---------------- weight prep ----------------
__global__ void k_prep_w1(const float* __restrict__ Wfc, const float* __restrict__ Wres) {
    int id = blockIdx.x * 256 + threadIdx.x;
    if (id >= 4 * 1024 * 128) return;
    int k = id & 127, n = (id >> 7) & 1023, l = id >> 17;
    float v = (n < 512) ? Wfc[((size_t)l * 128 + k) * 512 + n]
                        : Wres[((size_t)l * 128 + k) * 512 + (n - 512)];
    __nv_bfloat16 h = __float2bfloat16_rn(v);
    g_w1h[id] = h;
    g_w1l[id] = __float2bfloat16_rn(v - __bfloat162float(h));
}

__global__ void k_prep_w2(const float* __restrict__ Wn) {
    int id = blockIdx.x * 256 + threadIdx.x;
    if (id >= 4 * 128 * 512) return;
    int k = id & 511, n = (id >> 9) & 127, l = id >> 16;
    float v = Wn[((size_t)l * 512 + k) * 128 + n];
    __nv_bfloat16 h = __float2bfloat16_rn(v);
    g_w2h[id] = h;
    g_w2l[id] = __float2bfloat16_rn(v - __bfloat162float(h));
}

// ---------------- CSR build ----------------
__global__ void k_zero_deg() {
    int i = blockIdx.x * blockDim.x + threadIdx.x;
    if (i < Nn) g_deg[i] = 0;
}
__global__ void k_hist(const int* __restrict__ dst) {
    int i = blockIdx.x * blockDim.x + threadIdx.x;
    if (i < Ee) atomicAdd(&g_deg[dst[i]], 1);
}
__global__ void k_scan() {
    __shared__ int sbuf[1024];
    __shared__ int carry;
    int t = threadIdx.x;
    if (t == 0) carry = 0;
    __syncthreads();
    for (int base = 0; base < Nn; base += 1024) {
        int i = base + t;
        int v = (i < Nn) ? g_deg[i] : 0;
        sbuf[t] = v;
        __syncthreads();
        for (int off = 1; off < 1024; off <<= 1) {
            int add = (t >= off) ? sbuf[t - off] : 0;
            __syncthreads();
            sbuf[t] += add;
            __syncthreads();
        }
        int incl = sbuf[t];
        int excl = carry + incl - v;
        if (i < Nn) { g_off[i] = excl; g_cur[i] = excl; }
        int total = sbuf[1023];
        __syncthreads();
        if (t == 0) carry += total;
        __syncthreads();
    }
    if (t == 0) g_off[Nn] = carry;
}
__global__ void k_scatter(const int* __restrict__ src, const int* __restrict__ dst) {
    int i = blockIdx.x * blockDim.x + threadIdx.x;
    if (i < Ee) {
        int d = dst[i];
        int p = atomicAdd(&g_cur[d], 1);
        g_csr_src[p] = src[i];
        g_slot[i] = p;
    }
}

// ============ GEMM1: [feat|res](128 cols per yb) = x @ W1  (bf16 split, ldmatrix+mma) ============
__global__ void __launch_bounds__(256) k_gemm1(const float* __restrict__ X, int l) {
    extern __shared__ char smem[];
    uint32_t sb = s2u(smem);
    int t = threadIdx.x, lane = t & 31, wid = t >> 5;
    int gr = lane >> 2, gc = lane & 3;
    int wm = (wid & 1) * 64, wn = (wid >> 1) * 32;
    int row0 = blockIdx.x * 128;
    int yb = blockIdx.y;

    const __nv_bfloat16* Wh = g_w1h + ((size_t)l * 1024 + (size_t)yb * 128) * 128;
    const __nv_bfloat16* Wl = g_w1l + ((size_t)l * 1024 + (size_t)yb * 128) * 128;

    float d[4][4][4];
#pragma unroll
    for (int i = 0; i < 4; i++)
#pragma unroll
        for (int j = 0; j < 4; j++)
#pragma unroll
            for (int q = 0; q < 4; q++) d[i][j][q] = 0.f;

    int arow = (lane & 7) + ((lane >> 3) & 1) * 8;
    int akof = (lane >> 4) * 8;
    int bnr  = (lane & 7) + ((lane >> 4) << 3);
    int bkof = ((lane >> 3) & 1) * 8;

#pragma unroll
    for (int kc = 0; kc < 2; kc++) {
        int k0 = kc * 64;
        // A: 128 x 64 fp32 -> bf16 hi/lo
#pragma unroll
        for (int u = 0; u < 8; u++) {
            int id = t + 256 * u;
            int r = id >> 4, c4 = (id & 15) * 4;
            int grow = row0 + r;
            float4 v = make_float4(0.f, 0.f, 0.f, 0.f);
            if (grow < Nn) v = *reinterpret_cast<const float4*>(X + (size_t)grow * Dd + k0 + c4);
            __nv_bfloat162 h0, l0, h1, l1;
            split2(v.x, v.y, h0, l0);
            split2(v.z, v.w, h1, l1);
            char* pa = smem + (size_t)(r * 72 + c4) * 2;
            reinterpret_cast<__nv_bfloat162*>(pa)[0] = h0;
            reinterpret_cast<__nv_bfloat162*>(pa)[1] = h1;
            reinterpret_cast<__nv_bfloat162*>(pa + O_ALOo)[0] = l0;
            reinterpret_cast<__nv_bfloat162*>(pa + O_ALOo)[1] = l1;
        }
        // B: 128 x 64 bf16 copy (hi/lo)
#pragma unroll
        for (int u = 0; u < 4; u++) {
            int id = t + 256 * u;
            int r = id >> 3, c8 = (id & 7) * 8;
            char* pb = smem + O_BHIo + (size_t)(r * 72 + c8) * 2;
            *reinterpret_cast<uint4*>(pb) = *reinterpret_cast<const uint4*>(Wh + (size_t)r * 128 + k0 + c8);
            *reinterpret_cast<uint4*>(pb + (O_BLOo - O_BHIo)) = *reinterpret_cast<const uint4*>(Wl + (size_t)r * 128 + k0 + c8);
        }
        __syncthreads();
#pragma unroll
        for (int kt = 0; kt < 4; kt++) {
            uint32_t ah[4][4], alf[4][4], bhf[2][4], blf[2][4];
#pragma unroll
            for (int mt = 0; mt < 4; mt++) {
                uint32_t ad = sb + 2u * ((wm + 16 * mt + arow) * 72 + 16 * kt + akof);
                LDSM4(ah[mt], ad);
                LDSM4(alf[mt], ad + O_ALOo);
            }
#pragma unroll
            for (int g = 0; g < 2; g++) {
                uint32_t bd = sb + O_BHIo + 2u * ((wn + 16 * g + bnr) * 72 + 16 * kt + bkof);
                LDSM4(bhf[g], bd);
                LDSM4(blf[g], bd + (O_BLOo - O_BHIo));
            }
#pragma unroll
            for (int mt = 0; mt < 4; mt++)
#pragma unroll
                for (int nt = 0; nt < 4; nt++) {
                    uint32_t bh0 = bhf[nt >> 1][(nt & 1) * 2], bh1 = bhf[nt >> 1][(nt & 1) * 2 + 1];
                    uint32_t bl0 = blf[nt >> 1][(nt & 1) * 2], bl1 = blf[nt >> 1][(nt & 1) * 2 + 1];
                    mma_bf16(d[mt][nt], ah[mt], bh0, bh1);
                    mma_bf16(d[mt][nt], ah[mt], bl0, bl1);
                    mma_bf16(d[mt][nt], alf[mt], bh0, bh1);
                }
        }
        __syncthreads();
    }

    float* C = (yb < 4) ? g_feat : g_res;
    int wc0 = (yb & 3) * 128;
#pragma unroll
    for (int mt = 0; mt < 4; mt++) {
        int r0 = row0 + wm + 16 * mt + gr;
        int r1 = r0 + 8;
#pragma unroll
        for (int nt = 0; nt < 4; nt++) {
            int col = wc0 + wn + nt * 8 + 2 * gc;
            if (r0 < Nn)
                *reinterpret_cast<float2*>(C + (size_t)r0 * HDim + col) = make_float2(d[mt][nt][0], d[mt][nt][1]);
            if (r1 < Nn)
                *reinterpret_cast<float2*>(C + (size_t)r1 * HDim + col) = make_float2(d[mt][nt][2], d[mt][nt][3]);
        }
    }
}

// ============ GEMM2 + bias + LayerNorm: out = LN(res @ Wn + bn) ============
__global__ void __launch_bounds__(256) k_gemm2(int l, const float* __restrict__ bn,
                                               const float* __restrict__ gam,
                                               const float* __restrict__ bet,
                                               float* __restrict__ out) {
    extern __shared__ char smem[];
    uint32_t sb = s2u(smem);
    int t = threadIdx.x, lane = t & 31, wid = t >> 5;
    int gr = lane >> 2, gc = lane & 3;
    int wm = (wid & 1) * 64, wnid = wid >> 1, wn = wnid * 32;
    int row0 = blockIdx.x * 128;

    float* par = reinterpret_cast<float*>(smem + O_PARo);
    if (t < 128) { par[t] = bn[t]; par[128 + t] = gam[t]; par[256 + t] = bet[t]; }

    const __nv_bfloat16* Wh = g_w2h + (size_t)l * 128 * 512;
    const __nv_bfloat16* Wl = g_w2l + (size_t)l * 128 * 512;

    float d[4][4][4];
#pragma unroll
    for (int i = 0; i < 4; i++)
#pragma unroll
        for (int j = 0; j < 4; j++)
#pragma unroll
            for (int q = 0; q < 4; q++) d[i][j][q] = 0.f;

    int arow = (lane & 7) + ((lane >> 3) & 1) * 8;
    int akof = (lane >> 4) * 8;
    int bnr  = (lane & 7) + ((lane >> 4) << 3);
    int bkof = ((lane >> 3) & 1) * 8;

    for (int kc = 0; kc < 8; kc++) {
        int k0 = kc * 64;
#pragma unroll
        for (int u = 0; u < 8; u++) {
            int id = t + 256 * u;
            int r = id >> 4, c4 = (id & 15) * 4;
            int grow = row0 + r;
            float4 v = make_float4(0.f, 0.f, 0.f, 0.f);
            if (grow < Nn) v = *reinterpret_cast<const float4*>(g_res + (size_t)grow * HDim + k0 + c4);
            __nv_bfloat162 h0, l0, h1, l1;
            split2(v.x, v.y, h0, l0);
            split2(v.z, v.w, h1, l1);
            char* pa = smem + (size_t)(r * 72 + c4) * 2;
            reinterpret_cast<__nv_bfloat162*>(pa)[0] = h0;
            reinterpret_cast<__nv_bfloat162*>(pa)[1] = h1;
            reinterpret_cast<__nv_bfloat162*>(pa + O_ALOo)[0] = l0;
            reinterpret_cast<__nv_bfloat162*>(pa + O_ALOo)[1] = l1;
        }
#pragma unroll
        for (int u = 0; u < 4; u++) {
            int id = t + 256 * u;
            int r = id >> 3, c8 = (id & 7) * 8;
            char* pb = smem + O_BHIo + (size_t)(r * 72 + c8) * 2;
            *reinterpret_cast<uint4*>(pb) = *reinterpret_cast<const uint4*>(Wh + (size_t)r * 512 + k0 + c8);
            *reinterpret_cast<uint4*>(pb + (O_BLOo - O_BHIo)) = *reinterpret_cast<const uint4*>(Wl + (size_t)r * 512 + k0 + c8);
        }
        __syncthreads();
#pragma unroll
        for (int kt = 0; kt < 4; kt++) {
            uint32_t ah[4][4], alf[4][4], bhf[2][4], blf[2][4];
#pragma unroll
            for (int mt = 0; mt < 4; mt++) {
                uint32_t ad = sb + 2u * ((wm + 16 * mt + arow) * 72 + 16 * kt + akof);
                LDSM4(ah[mt], ad);
                LDSM4(alf[mt], ad + O_ALOo);
            }
#pragma unroll
            for (int g = 0; g < 2; g++) {
                uint32_t bd = sb + O_BHIo + 2u * ((wn + 16 * g + bnr) * 72 + 16 * kt + bkof);
                LDSM4(bhf[g], bd);
                LDSM4(blf[g], bd + (O_BLOo - O_BHIo));
            }
#pragma unroll
            for (int mt = 0; mt < 4; mt++)
#pragma unroll
                for (int nt = 0; nt < 4; nt++) {
                    uint32_t bh0 = bhf[nt >> 1][(nt & 1) * 2], bh1 = bhf[nt >> 1][(nt & 1) * 2 + 1];
                    uint32_t bl0 = blf[nt >> 1][(nt & 1) * 2], bl1 = blf[nt >> 1][(nt & 1) * 2 + 1];
                    mma_bf16(d[mt][nt], ah[mt], bh0, bh1);
                    mma_bf16(d[mt][nt], ah[mt], bl0, bl1);
                    mma_bf16(d[mt][nt], alf[mt], bh0, bh1);
                }
        }
        __syncthreads();
    }

    // ---- fused bias + LayerNorm epilogue ----
    float* red_s = reinterpret_cast<float*>(smem);          // 4 x 128
    float* red_q = reinterpret_cast<float*>(smem + 2048);   // 4 x 128
    float bnv[4][2];
#pragma unroll
    for (int nt = 0; nt < 4; nt++) {
        int col = wn + nt * 8 + 2 * gc;
        bnv[nt][0] = par[col]; bnv[nt][1] = par[col + 1];
    }
#pragma unroll
    for (int mt = 0; mt < 4; mt++) {
        float s0 = 0.f, q0 = 0.f, s1 = 0.f, q1 = 0.f;
#pragma unroll
        for (int nt = 0; nt < 4; nt++) {
            float y00 = d[mt][nt][0] + bnv[nt][0];
            float y01 = d[mt][nt][1] + bnv[nt][1];
            float y10 = d[mt][nt][2] + bnv[nt][0];
            float y11 = d[mt][nt][3] + bnv[nt][1];
            d[mt][nt][0] = y00; d[mt][nt][1] = y01;
            d[mt][nt][2] = y10; d[mt][nt][3] = y11;
            s0 += y00 + y01; q0 += y00 * y00 + y01 * y01;
            s1 += y10 + y11; q1 += y10 * y10 + y11 * y11;
        }
#pragma unroll
        for (int o = 1; o < 4; o <<= 1) {
            s0 += __shfl_xor_sync(0xffffffffu, s0, o);
            q0 += __shfl_xor_sync(0xffffffffu, q0, o);
            s1 += __shfl_xor_sync(0xffffffffu, s1, o);
            q1 += __shfl_xor_sync(0xffffffffu, q1, o);
        }
        if (gc == 0) {
            int rb = wm + 16 * mt + gr;
            red_s[wnid * 128 + rb] = s0; red_q[wnid * 128 + rb] = q0;
            red_s[wnid * 128 + rb + 8] = s1; red_q[wnid * 128 + rb + 8] = q1;
        }
    }
    __syncthreads();
#pragma unroll
    for (int mt = 0; mt < 4; mt++) {
        int rb = wm + 16 * mt + gr;
        float s0 = red_s[rb] + red_s[128 + rb] + red_s[256 + rb] + red_s[384 + rb];
        float q0 = red_q[rb] + red_q[128 + rb] + red_q[256 + rb] + red_q[384 + rb];
        float s1 = red_s[rb + 8] + red_s[128 + rb + 8] + red_s[256 + rb + 8] + red_s[384 + rb + 8];
        float q1 = red_q[rb + 8] + red_q[128 + rb + 8] + red_q[256 + rb + 8] + red_q[384 + rb + 8];
        float mu0 = s0 * (1.f / 128.f);
        float mu1 = s1 * (1.f / 128.f);
        float rstd0 = rsqrtf(q0 * (1.f / 128.f) - mu0 * mu0 + 1e-5f);
        float rstd1 = rsqrtf(q1 * (1.f / 128.f) - mu1 * mu1 + 1e-5f);
        int r0 = row0 + rb, r1 = r0 + 8;
#pragma unroll
        for (int nt = 0; nt < 4; nt++) {
            int col = wn + nt * 8 + 2 * gc;
            float g0 = par[128 + col], g1 = par[128 + col + 1];
            float b0 = par[256 + col], b1 = par[256 + col + 1];
            if (r0 < Nn)
                *reinterpret_cast<float2*>(out + (size_t)r0 * Dd + col) =
                    make_float2((d[mt][nt][0] - mu0) * rstd0 * g0 + b0,
                                (d[mt][nt][1] - mu0) * rstd0 * g1 + b1);
            if (r1 < Nn)
                *reinterpret_cast<float2*>(out + (size_t)r1 * Dd + col) =
                    make_float2((d[mt][nt][2] - mu1) * rstd1 * g0 + b0,
                                (d[mt][nt][3] - mu1) * rstd1 * g1 + b1);
        }
    }
}

// ---------------- el/er: per-node dot(feat, attn) ----------------
__global__ void k_elr(const float* __restrict__ al, const float* __restrict__ ar) {
    int gt = blockIdx.x * blockDim.x + threadIdx.x;
    int node = gt >> 5;
    int lane = gt & 31;
    if (node >= Nn) return;
    const float* f = g_feat + (size_t)node * HDim;
#pragma unroll
    for (int h = 0; h < Hh; h++) {
        float sl = 0.f, sr = 0.f;
#pragma unroll
        for (int i = 0; i < 4; i++) {
            int idx = h * 128 + lane + 32 * i;
            float v = f[idx];
            sl += v * al[idx];
            sr += v * ar[idx];
        }
#pragma unroll
        for (int o = 16; o; o >>= 1) {
            sl += __shfl_xor_sync(0xffffffffu, sl, o);
            sr += __shfl_xor_sync(0xffffffffu, sr, o);
        }
        if (lane == 0) {
            g_el[node * Hh + h] = sl;
            g_er[node * Hh + h] = sr;
        }
    }
}

// ---------------- single-pass edge kernel: ex = exp(leaky(el[s]+er[d])) into CSR slot ----------------
__global__ void k_edge(const int* __restrict__ src, const int* __restrict__ dst) {
    int e = blockIdx.x * blockDim.x + threadIdx.x;
    if (e >= Ee) return;
    int s = src[e], d = dst[e];
    float4 a = *reinterpret_cast<const float4*>(g_el + (size_t)s * 4);
    float4 b = *reinterpret_cast<const float4*>(g_er + (size_t)d * 4);
    float4 ev;
    ev.x = a.x + b.x; ev.x = ev.x > 0.f ? ev.x : NEG_ATTN * ev.x; ev.x = __expf(ev.x);
    ev.y = a.y + b.y; ev.y = ev.y > 0.f ? ev.y : NEG_ATTN * ev.y; ev.y = __expf(ev.y);
    ev.z = a.z + b.z; ev.z = ev.z > 0.f ? ev.z : NEG_ATTN * ev.z; ev.z = __expf(ev.z);
    ev.w = a.w + b.w; ev.w = ev.w > 0.f ? ev.w : NEG_ATTN * ev.w; ev.w = __expf(ev.w);
    int slot = g_slot[e];
    *reinterpret_cast<float4*>(g_ex + (size_t)slot * 4) = ev;
}

// ---------------- aggregation: one block (128 thr) per dst node; z folded in ----------------
__global__ void k_aggregate(const float* __restrict__ bgat) {
    int dn = blockIdx.x;
    int t = threadIdx.x;
    int s = g_off[dn], en = g_off[dn + 1];
    float acc0 = 0.f, acc1 = 0.f, acc2 = 0.f, acc3 = 0.f;
    float z0 = 0.f, z1 = 0.f, z2 = 0.f, z3 = 0.f;
    int p = s;
    for (; p + 2 <= en; p += 2) {
        int sn0 = g_csr_src[p], sn1 = g_csr_src[p + 1];
        float4 e0 = *reinterpret_cast<const float4*>(g_ex + (size_t)p * 4);
        float4 e1 = *reinterpret_cast<const float4*>(g_ex + (size_t)(p + 1) * 4);
        const float* f0 = g_feat + (size_t)sn0 * HDim + t;
        const float* f1 = g_feat + (size_t)sn1 * HDim + t;
        float v00 = f0[0], v01 = f0[128], v02 = f0[256], v03 = f0[384];
        float v10 = f1[0], v11 = f1[128], v12 = f1[256], v13 = f1[384];
        acc0 = fmaf(e0.x, v00, acc0); acc1 = fmaf(e0.y, v01, acc1);
        acc2 = fmaf(e0.z, v02, acc2); acc3 = fmaf(e0.w, v03, acc3);
        acc0 = fmaf(e1.x, v10, acc0); acc1 = fmaf(e1.y, v11, acc1);
        acc2 = fmaf(e1.z, v12, acc2); acc3 = fmaf(e1.w, v13, acc3);
        z0 += e0.x + e1.x; z1 += e0.y + e1.y;
        z2 += e0.z + e1.z; z3 += e0.w + e1.w;
    }
    if (p < en) {
        int sn0 = g_csr_src[p];
        float4 e0 = *reinterpret_cast<const float4*>(g_ex + (size_t)p * 4);
        const float* f0 = g_feat + (size_t)sn0 * HDim + t;
        acc0 = fmaf(e0.x, f0[0], acc0);   acc1 = fmaf(e0.y, f0[128], acc1);
        acc2 = fmaf(e0.z, f0[256], acc2); acc3 = fmaf(e0.w, f0[384], acc3);
        z0 += e0.x; z1 += e0.y; z2 += e0.z; z3 += e0.w;
    }
    float iz0 = 1.f / fmaxf(z0, 1e-20f);
    float iz1 = 1.f / fmaxf(z1, 1e-20f);
    float iz2 = 1.f / fmaxf(z2, 1e-20f);
    float iz3 = 1.f / fmaxf(z3, 1e-20f);
    size_t o = (size_t)dn * HDim + t;
    float r;
    r = acc0 * iz0 + g_res[o + 0]   + bgat[t + 0];   r = r > 0.f ? r : NEG_ACT * r; g_res[o + 0]   = r;
    r = acc1 * iz1 + g_res[o + 128] + bgat[t + 128]; r = r > 0.f ? r : NEG_ACT * r; g_res[o + 128] = r;
    r = acc2 * iz2 + g_res[o + 256] + bgat[t + 256]; r = r > 0.f ? r : NEG_ACT * r; g_res[o + 256] = r;
    r = acc3 * iz3 + g_res[o + 384] + bgat[t + 384]; r = r > 0.f ? r : NEG_ACT * r; g_res[o + 384] = r;
}

// ---------------- launch ----------------
extern "C" void kernel_launch(void* const* d_in, const int* in_sizes, int n_in,
                              void* d_out, int out_size) {
    const float* features = (const float*)d_in[0];
    const int*   src      = (const int*)  d_in[1];
    const int*   dst      = (const int*)  d_in[2];
    const float* W_fc     = (const float*)d_in[3];
    const float* attn_l   = (const float*)d_in[4];
    const float* attn_r   = (const float*)d_in[5];
    const float* W_res    = (const float*)d_in[6];
    const float* b_gat    = (const float*)d_in[7];
    const float* W_nrm    = (const float*)d_in[8];
    const float* b_nrm    = (const float*)d_in[9];
    const float* ln_g     = (const float*)d_in[10];
    const float* ln_b     = (const float*)d_in[11];
    float* out = (float*)d_out;

    cudaFuncSetAttribute(k_gemm1, cudaFuncAttributeMaxDynamicSharedMemorySize, SMEM_G1);
    cudaFuncSetAttribute(k_gemm2, cudaFuncAttributeMaxDynamicSharedMemorySize, SMEM_G2);

    float *xa = nullptr, *xb = nullptr;
    cudaGetSymbolAddress((void**)&xa, g_xa);
    cudaGetSymbolAddress((void**)&xb, g_xb);

    // CSR build + weight prep (gemm1 lands at launch slot 6 for ncu -s 5 -c 1)
    k_zero_deg<<<(Nn + 255) / 256, 256>>>();
    k_hist<<<(Ee + 255) / 256, 256>>>(dst);
    k_scan<<<1, 1024>>>();
    k_scatter<<<(Ee + 255) / 256, 256>>>(src, dst);
    k_prep_w1<<<(4 * 1024 * 128 + 255) / 256, 256>>>(W_fc, W_res);

    const float* x = features;
    for (int l = 0; l < 4; l++) {
        const float* al  = attn_l + (size_t)l * Hh * Dd;
        const float* ar  = attn_r + (size_t)l * Hh * Dd;
        const float* bg  = b_gat + (size_t)l * HDim;
        const float* bnp = b_nrm + (size_t)l * Dd;
        const float* gp  = ln_g  + (size_t)l * Dd;
        const float* bp  = ln_b  + (size_t)l * Dd;

        k_gemm1<<<dim3((Nn + 127) / 128, 8), 256, SMEM_G1>>>(x, l);
        if (l == 0) k_prep_w2<<<(4 * 128 * 512 + 255) / 256, 256>>>(W_nrm);
        k_elr<<<(Nn * 32 + 255) / 256, 256>>>(al, ar);
        k_edge<<<(Ee + 255) / 256, 256>>>(src, dst);
        k_aggregate<<<Nn, 128>>>(bg);

        float* xo = (l == 3) ? out : ((l & 1) ? xb : xa);
        k_gemm2<<<(Nn + 127) / 128, 256, SMEM_G2>>>(l, bnp, gp, bp, xo);
        x = xo;
    }
}

// round 7
// speedup vs baseline: 2.0043x; 1.1185x over previous
#include <cuda_runtime.h>
#include <cuda_bf16.h>
#include <cuda_fp16.h>
#include <math.h>
#include <float.h>
#include <stdint.h>

#define Nn 50000
#define Ee 800000
#define Hh 4
#define Dd 128
#define HDim 512
#define NEG_ATTN 0.2f
#define NEG_ACT 0.01f

// ---------------- scratch (static device allocations) ----------------
__device__ __half g_feath[(size_t)Nn * HDim];   // fp16 feat (gather source)
__device__ float g_res [Nn * HDim];
__device__ float g_xa  [Nn * Dd];
__device__ float g_xb  [Nn * Dd];
__device__ float g_el  [Nn * Hh];
__device__ float g_er  [Nn * Hh];
__device__ float g_ex  [(size_t)Ee * Hh];
__device__ int   g_deg [Nn];
__device__ int   g_off [Nn + 1];
__device__ int   g_cur [Nn];
__device__ int   g_csr_src[Ee];
__device__ int   g_slot[Ee];

// pre-split transposed weights (bf16 hi/lo), [n][k] layout
__device__ __nv_bfloat16 g_w1h[4u * 1024 * 128];
__device__ __nv_bfloat16 g_w1l[4u * 1024 * 128];
__device__ __nv_bfloat16 g_w2h[4u * 128 * 512];
__device__ __nv_bfloat16 g_w2l[4u * 128 * 512];

// smem offsets (bytes): 4 tiles of [128][72] bf16 = 18432 each
#define O_ALOo 18432
#define O_BHIo 36864
#define O_BLOo 55296
#define O_PARo 73728
#define SMEM_G1 73728
#define SMEM_G2 (73728 + 1536)

// ---------------- helpers ----------------
__device__ __forceinline__ uint32_t s2u(const void* p) {
    uint32_t a;
    asm("{ .reg .u64 t; cvta.to.shared.u64 t, %1; cvt.u32.u64 %0, t; }" : "=r"(a) : "l"(p));
    return a;
}

#define LDSM4(R, A) \
    asm volatile("ldmatrix.sync.aligned.m8n8.x4.shared.b16 {%0,%1,%2,%3}, [%4];" \
        : "=r"((R)[0]), "=r"((R)[1]), "=r"((R)[2]), "=r"((R)[3]) : "r"(A))

__device__ __forceinline__ void mma_bf16(float d[4], const uint32_t a[4],
                                         uint32_t b0, uint32_t b1) {
    asm volatile(
        "mma.sync.aligned.m16n8k16.row.col.f32.bf16.bf16.f32 "
        "{%0,%1,%2,%3},{%4,%5,%6,%7},{%8,%9},{%0,%1,%2,%3};"
        : "+f"(d[0]), "+f"(d[1]), "+f"(d[2]), "+f"(d[3])
        : "r"(a[0]), "r"(a[1]), "r"(a[2]), "r"(a[3]), "r"(b0), "r"(b1));
}

__device__ __forceinline__ void split2(float x, float y, __nv_bfloat162& h, __nv_bfloat162& lo) {
    h.x = __float2bfloat16_rn(x); h.y = __float2bfloat16_rn(y);
    lo.x = __float2bfloat16_rn(x - __bfloat162float(h.x));
    lo.y = __float2bfloat16_rn(y - __bfloat162float(h.y));
}

// ---------------- weight prep ----------------
__global__ void k_prep_w1(const float* __restrict__ Wfc, const float* __restrict__ Wres) {
    int id = blockIdx.x * 256 + threadIdx.x;
    if (id >= 4 * 1024 * 128) return;
    int k = id & 127, n = (id >> 7) & 1023, l = id >> 17;
    float v = (n < 512) ? Wfc[((size_t)l * 128 + k) * 512 + n]
                        : Wres[((size_t)l * 128 + k) * 512 + (n - 512)];
    __nv_bfloat16 h = __float2bfloat16_rn(v);
    g_w1h[id] = h;
    g_w1l[id] = __float2bfloat16_rn(v - __bfloat162float(h));
}

__global__ void k_prep_w2(const float* __restrict__ Wn) {
    int id = blockIdx.x * 256 + threadIdx.x;
    if (id >= 4 * 128 * 512) return;
    int k = id & 511, n = (id >> 9) & 127, l = id >> 16;
    float v = Wn[((size_t)l * 512 + k) * 128 + n];
    __nv_bfloat16 h = __float2bfloat16_rn(v);
    g_w2h[id] = h;
    g_w2l[id] = __float2bfloat16_rn(v - __bfloat162float(h));
}

// ---------------- CSR build ----------------
__global__ void k_zero_deg() {
    int i = blockIdx.x * blockDim.x + threadIdx.x;
    if (i < Nn) g_deg[i] = 0;
}
__global__ void k_hist(const int* __restrict__ dst) {
    int i = blockIdx.x * blockDim.x + threadIdx.x;
    if (i < Ee) atomicAdd(&g_deg[dst[i]], 1);
}
__global__ void k_scan() {
    __shared__ int sbuf[1024];
    __shared__ int carry;
    int t = threadIdx.x;
    if (t == 0) carry = 0;
    __syncthreads();
    for (int base = 0; base < Nn; base += 1024) {
        int i = base + t;
        int v = (i < Nn) ? g_deg[i] : 0;
        sbuf[t] = v;
        __syncthreads();
        for (int off = 1; off < 1024; off <<= 1) {
            int add = (t >= off) ? sbuf[t - off] : 0;
            __syncthreads();
            sbuf[t] += add;
            __syncthreads();
        }
        int incl = sbuf[t];
        int excl = carry + incl - v;
        if (i < Nn) { g_off[i] = excl; g_cur[i] = excl; }
        int total = sbuf[1023];
        __syncthreads();
        if (t == 0) carry += total;
        __syncthreads();
    }
    if (t == 0) g_off[Nn] = carry;
}
__global__ void k_scatter(const int* __restrict__ src, const int* __restrict__ dst) {
    int i = blockIdx.x * blockDim.x + threadIdx.x;
    if (i < Ee) {
        int d = dst[i];
        int p = atomicAdd(&g_cur[d], 1);
        g_csr_src[p] = src[i];
        g_slot[i] = p;
    }
}

// ============ GEMM1: [feat(fp16)|res(fp32)] = x @ W1  (bf16 split, ldmatrix+mma) ============
__global__ void __launch_bounds__(256) k_gemm1(const float* __restrict__ X, int l) {
    extern __shared__ char smem[];
    uint32_t sb = s2u(smem);
    int t = threadIdx.x, lane = t & 31, wid = t >> 5;
    int gr = lane >> 2, gc = lane & 3;
    int wm = (wid & 1) * 64, wn = (wid >> 1) * 32;
    int row0 = blockIdx.x * 128;
    int yb = blockIdx.y;

    const __nv_bfloat16* Wh = g_w1h + ((size_t)l * 1024 + (size_t)yb * 128) * 128;
    const __nv_bfloat16* Wl = g_w1l + ((size_t)l * 1024 + (size_t)yb * 128) * 128;

    float d[4][4][4];
#pragma unroll
    for (int i = 0; i < 4; i++)
#pragma unroll
        for (int j = 0; j < 4; j++)
#pragma unroll
            for (int q = 0; q < 4; q++) d[i][j][q] = 0.f;

    int arow = (lane & 7) + ((lane >> 3) & 1) * 8;
    int akof = (lane >> 4) * 8;
    int bnr  = (lane & 7) + ((lane >> 4) << 3);
    int bkof = ((lane >> 3) & 1) * 8;

#pragma unroll
    for (int kc = 0; kc < 2; kc++) {
        int k0 = kc * 64;
#pragma unroll
        for (int u = 0; u < 8; u++) {
            int id = t + 256 * u;
            int r = id >> 4, c4 = (id & 15) * 4;
            int grow = row0 + r;
            float4 v = make_float4(0.f, 0.f, 0.f, 0.f);
            if (grow < Nn) v = *reinterpret_cast<const float4*>(X + (size_t)grow * Dd + k0 + c4);
            __nv_bfloat162 h0, l0, h1, l1;
            split2(v.x, v.y, h0, l0);
            split2(v.z, v.w, h1, l1);
            char* pa = smem + (size_t)(r * 72 + c4) * 2;
            reinterpret_cast<__nv_bfloat162*>(pa)[0] = h0;
            reinterpret_cast<__nv_bfloat162*>(pa)[1] = h1;
            reinterpret_cast<__nv_bfloat162*>(pa + O_ALOo)[0] = l0;
            reinterpret_cast<__nv_bfloat162*>(pa + O_ALOo)[1] = l1;
        }
#pragma unroll
        for (int u = 0; u < 4; u++) {
            int id = t + 256 * u;
            int r = id >> 3, c8 = (id & 7) * 8;
            char* pb = smem + O_BHIo + (size_t)(r * 72 + c8) * 2;
            *reinterpret_cast<uint4*>(pb) = *reinterpret_cast<const uint4*>(Wh + (size_t)r * 128 + k0 + c8);
            *reinterpret_cast<uint4*>(pb + (O_BLOo - O_BHIo)) = *reinterpret_cast<const uint4*>(Wl + (size_t)r * 128 + k0 + c8);
        }
        __syncthreads();
#pragma unroll
        for (int kt = 0; kt < 4; kt++) {
            uint32_t ah[4][4], alf[4][4], bhf[2][4], blf[2][4];
#pragma unroll
            for (int mt = 0; mt < 4; mt++) {
                uint32_t ad = sb + 2u * ((wm + 16 * mt + arow) * 72 + 16 * kt + akof);
                LDSM4(ah[mt], ad);
                LDSM4(alf[mt], ad + O_ALOo);
            }
#pragma unroll
            for (int g = 0; g < 2; g++) {
                uint32_t bd = sb + O_BHIo + 2u * ((wn + 16 * g + bnr) * 72 + 16 * kt + bkof);
                LDSM4(bhf[g], bd);
                LDSM4(blf[g], bd + (O_BLOo - O_BHIo));
            }
#pragma unroll
            for (int mt = 0; mt < 4; mt++)
#pragma unroll
                for (int nt = 0; nt < 4; nt++) {
                    uint32_t bh0 = bhf[nt >> 1][(nt & 1) * 2], bh1 = bhf[nt >> 1][(nt & 1) * 2 + 1];
                    uint32_t bl0 = blf[nt >> 1][(nt & 1) * 2], bl1 = blf[nt >> 1][(nt & 1) * 2 + 1];
                    mma_bf16(d[mt][nt], ah[mt], bh0, bh1);
                    mma_bf16(d[mt][nt], ah[mt], bl0, bl1);
                    mma_bf16(d[mt][nt], alf[mt], bh0, bh1);
                }
        }
        __syncthreads();
    }

    int wc0 = (yb & 3) * 128;
    if (yb < 4) {
        // feat -> fp16
#pragma unroll
        for (int mt = 0; mt < 4; mt++) {
            int r0 = row0 + wm + 16 * mt + gr;
            int r1 = r0 + 8;
#pragma unroll
            for (int nt = 0; nt < 4; nt++) {
                int col = wc0 + wn + nt * 8 + 2 * gc;
                if (r0 < Nn)
                    *reinterpret_cast<__half2*>(g_feath + (size_t)r0 * HDim + col) =
                        __floats2half2_rn(d[mt][nt][0], d[mt][nt][1]);
                if (r1 < Nn)
                    *reinterpret_cast<__half2*>(g_feath + (size_t)r1 * HDim + col) =
                        __floats2half2_rn(d[mt][nt][2], d[mt][nt][3]);
            }
        }
    } else {
        // res -> fp32
#pragma unroll
        for (int mt = 0; mt < 4; mt++) {
            int r0 = row0 + wm + 16 * mt + gr;
            int r1 = r0 + 8;
#pragma unroll
            for (int nt = 0; nt < 4; nt++) {
                int col = wc0 + wn + nt * 8 + 2 * gc;
                if (r0 < Nn)
                    *reinterpret_cast<float2*>(g_res + (size_t)r0 * HDim + col) = make_float2(d[mt][nt][0], d[mt][nt][1]);
                if (r1 < Nn)
                    *reinterpret_cast<float2*>(g_res + (size_t)r1 * HDim + col) = make_float2(d[mt][nt][2], d[mt][nt][3]);
            }
        }
    }
}

// ============ GEMM2 + bias + LayerNorm: out = LN(res @ Wn + bn) ============
__global__ void __launch_bounds__(256) k_gemm2(int l, const float* __restrict__ bn,
                                               const float* __restrict__ gam,
                                               const float* __restrict__ bet,
                                               float* __restrict__ out) {
    extern __shared__ char smem[];
    uint32_t sb = s2u(smem);
    int t = threadIdx.x, lane = t & 31, wid = t >> 5;
    int gr = lane >> 2, gc = lane & 3;
    int wm = (wid & 1) * 64, wnid = wid >> 1, wn = wnid * 32;
    int row0 = blockIdx.x * 128;

    float* par = reinterpret_cast<float*>(smem + O_PARo);
    if (t < 128) { par[t] = bn[t]; par[128 + t] = gam[t]; par[256 + t] = bet[t]; }

    const __nv_bfloat16* Wh = g_w2h + (size_t)l * 128 * 512;
    const __nv_bfloat16* Wl = g_w2l + (size_t)l * 128 * 512;

    float d[4][4][4];
#pragma unroll
    for (int i = 0; i < 4; i++)
#pragma unroll
        for (int j = 0; j < 4; j++)
#pragma unroll
            for (int q = 0; q < 4; q++) d[i][j][q] = 0.f;

    int arow = (lane & 7) + ((lane >> 3) & 1) * 8;
    int akof = (lane >> 4) * 8;
    int bnr  = (lane & 7) + ((lane >> 4) << 3);
    int bkof = ((lane >> 3) & 1) * 8;

    for (int kc = 0; kc < 8; kc++) {
        int k0 = kc * 64;
#pragma unroll
        for (int u = 0; u < 8; u++) {
            int id = t + 256 * u;
            int r = id >> 4, c4 = (id & 15) * 4;
            int grow = row0 + r;
            float4 v = make_float4(0.f, 0.f, 0.f, 0.f);
            if (grow < Nn) v = *reinterpret_cast<const float4*>(g_res + (size_t)grow * HDim + k0 + c4);
            __nv_bfloat162 h0, l0, h1, l1;
            split2(v.x, v.y, h0, l0);
            split2(v.z, v.w, h1, l1);
            char* pa = smem + (size_t)(r * 72 + c4) * 2;
            reinterpret_cast<__nv_bfloat162*>(pa)[0] = h0;
            reinterpret_cast<__nv_bfloat162*>(pa)[1] = h1;
            reinterpret_cast<__nv_bfloat162*>(pa + O_ALOo)[0] = l0;
            reinterpret_cast<__nv_bfloat162*>(pa + O_ALOo)[1] = l1;
        }
#pragma unroll
        for (int u = 0; u < 4; u++) {
            int id = t + 256 * u;
            int r = id >> 3, c8 = (id & 7) * 8;
            char* pb = smem + O_BHIo + (size_t)(r * 72 + c8) * 2;
            *reinterpret_cast<uint4*>(pb) = *reinterpret_cast<const uint4*>(Wh + (size_t)r * 512 + k0 + c8);
            *reinterpret_cast<uint4*>(pb + (O_BLOo - O_BHIo)) = *reinterpret_cast<const uint4*>(Wl + (size_t)r * 512 + k0 + c8);
        }
        __syncthreads();
#pragma unroll
        for (int kt = 0; kt < 4; kt++) {
            uint32_t ah[4][4], alf[4][4], bhf[2][4], blf[2][4];
#pragma unroll
            for (int mt = 0; mt < 4; mt++) {
                uint32_t ad = sb + 2u * ((wm + 16 * mt + arow) * 72 + 16 * kt + akof);
                LDSM4(ah[mt], ad);
                LDSM4(alf[mt], ad + O_ALOo);
            }
#pragma unroll
            for (int g = 0; g < 2; g++) {
                uint32_t bd = sb + O_BHIo + 2u * ((wn + 16 * g + bnr) * 72 + 16 * kt + bkof);
                LDSM4(bhf[g], bd);
                LDSM4(blf[g], bd + (O_BLOo - O_BHIo));
            }
#pragma unroll
            for (int mt = 0; mt < 4; mt++)
#pragma unroll
                for (int nt = 0; nt < 4; nt++) {
                    uint32_t bh0 = bhf[nt >> 1][(nt & 1) * 2], bh1 = bhf[nt >> 1][(nt & 1) * 2 + 1];
                    uint32_t bl0 = blf[nt >> 1][(nt & 1) * 2], bl1 = blf[nt >> 1][(nt & 1) * 2 + 1];
                    mma_bf16(d[mt][nt], ah[mt], bh0, bh1);
                    mma_bf16(d[mt][nt], ah[mt], bl0, bl1);
                    mma_bf16(d[mt][nt], alf[mt], bh0, bh1);
                }
        }
        __syncthreads();
    }

    // ---- fused bias + LayerNorm epilogue ----
    float* red_s = reinterpret_cast<float*>(smem);          // 4 x 128
    float* red_q = reinterpret_cast<float*>(smem + 2048);   // 4 x 128
    float bnv[4][2];
#pragma unroll
    for (int nt = 0; nt < 4; nt++) {
        int col = wn + nt * 8 + 2 * gc;
        bnv[nt][0] = par[col]; bnv[nt][1] = par[col + 1];
    }
#pragma unroll
    for (int mt = 0; mt < 4; mt++) {
        float s0 = 0.f, q0 = 0.f, s1 = 0.f, q1 = 0.f;
#pragma unroll
        for (int nt = 0; nt < 4; nt++) {
            float y00 = d[mt][nt][0] + bnv[nt][0];
            float y01 = d[mt][nt][1] + bnv[nt][1];
            float y10 = d[mt][nt][2] + bnv[nt][0];
            float y11 = d[mt][nt][3] + bnv[nt][1];
            d[mt][nt][0] = y00; d[mt][nt][1] = y01;
            d[mt][nt][2] = y10; d[mt][nt][3] = y11;
            s0 += y00 + y01; q0 += y00 * y00 + y01 * y01;
            s1 += y10 + y11; q1 += y10 * y10 + y11 * y11;
        }
#pragma unroll
        for (int o = 1; o < 4; o <<= 1) {
            s0 += __shfl_xor_sync(0xffffffffu, s0, o);
            q0 += __shfl_xor_sync(0xffffffffu, q0, o);
            s1 += __shfl_xor_sync(0xffffffffu, s1, o);
            q1 += __shfl_xor_sync(0xffffffffu, q1, o);
        }
        if (gc == 0) {
            int rb = wm + 16 * mt + gr;
            red_s[wnid * 128 + rb] = s0; red_q[wnid * 128 + rb] = q0;
            red_s[wnid * 128 + rb + 8] = s1; red_q[wnid * 128 + rb + 8] = q1;
        }
    }
    __syncthreads();
#pragma unroll
    for (int mt = 0; mt < 4; mt++) {
        int rb = wm + 16 * mt + gr;
        float s0 = red_s[rb] + red_s[128 + rb] + red_s[256 + rb] + red_s[384 + rb];
        float q0 = red_q[rb] + red_q[128 + rb] + red_q[256 + rb] + red_q[384 + rb];
        float s1 = red_s[rb + 8] + red_s[128 + rb + 8] + red_s[256 + rb + 8] + red_s[384 + rb + 8];
        float q1 = red_q[rb + 8] + red_q[128 + rb + 8] + red_q[256 + rb + 8] + red_q[384 + rb + 8];
        float mu0 = s0 * (1.f / 128.f);
        float mu1 = s1 * (1.f / 128.f);
        float rstd0 = rsqrtf(q0 * (1.f / 128.f) - mu0 * mu0 + 1e-5f);
        float rstd1 = rsqrtf(q1 * (1.f / 128.f) - mu1 * mu1 + 1e-5f);
        int r0 = row0 + rb, r1 = r0 + 8;
#pragma unroll
        for (int nt = 0; nt < 4; nt++) {
            int col = wn + nt * 8 + 2 * gc;
            float g0 = par[128 + col], g1 = par[128 + col + 1];
            float b0 = par[256 + col], b1 = par[256 + col + 1];
            if (r0 < Nn)
                *reinterpret_cast<float2*>(out + (size_t)r0 * Dd + col) =
                    make_float2((d[mt][nt][0] - mu0) * rstd0 * g0 + b0,
                                (d[mt][nt][1] - mu0) * rstd0 * g1 + b1);
            if (r1 < Nn)
                *reinterpret_cast<float2*>(out + (size_t)r1 * Dd + col) =
                    make_float2((d[mt][nt][2] - mu1) * rstd1 * g0 + b0,
                                (d[mt][nt][3] - mu1) * rstd1 * g1 + b1);
        }
    }
}

// ---------------- el/er: per-node dot(feat_fp16, attn) ----------------
__global__ void k_elr(const float* __restrict__ al, const float* __restrict__ ar) {
    int gt = blockIdx.x * blockDim.x + threadIdx.x;
    int node = gt >> 5;
    int lane = gt & 31;
    if (node >= Nn) return;
    const __half2* f = reinterpret_cast<const __half2*>(g_feath + (size_t)node * HDim);
#pragma unroll
    for (int h = 0; h < Hh; h++) {
        float sl = 0.f, sr = 0.f;
#pragma unroll
        for (int i = 0; i < 2; i++) {
            int j = h * 64 + lane + 32 * i;       // half2 index
            float2 v = __half22float2(f[j]);
            float2 a2 = *reinterpret_cast<const float2*>(al + 2 * j);
            float2 b2 = *reinterpret_cast<const float2*>(ar + 2 * j);
            sl += v.x * a2.x + v.y * a2.y;
            sr += v.x * b2.x + v.y * b2.y;
        }
#pragma unroll
        for (int o = 16; o; o >>= 1) {
            sl += __shfl_xor_sync(0xffffffffu, sl, o);
            sr += __shfl_xor_sync(0xffffffffu, sr, o);
        }
        if (lane == 0) {
            g_el[node * Hh + h] = sl;
            g_er[node * Hh + h] = sr;
        }
    }
}

// ---------------- single-pass edge kernel: ex = exp(leaky(el[s]+er[d])) into CSR slot ----------------
__global__ void k_edge(const int* __restrict__ src, const int* __restrict__ dst) {
    int e = blockIdx.x * blockDim.x + threadIdx.x;
    if (e >= Ee) return;
    int s = src[e], d = dst[e];
    float4 a = *reinterpret_cast<const float4*>(g_el + (size_t)s * 4);
    float4 b = *reinterpret_cast<const float4*>(g_er + (size_t)d * 4);
    float4 ev;
    ev.x = a.x + b.x; ev.x = ev.x > 0.f ? ev.x : NEG_ATTN * ev.x; ev.x = __expf(ev.x);
    ev.y = a.y + b.y; ev.y = ev.y > 0.f ? ev.y : NEG_ATTN * ev.y; ev.y = __expf(ev.y);
    ev.z = a.z + b.z; ev.z = ev.z > 0.f ? ev.z : NEG_ATTN * ev.z; ev.z = __expf(ev.z);
    ev.w = a.w + b.w; ev.w = ev.w > 0.f ? ev.w : NEG_ATTN * ev.w; ev.w = __expf(ev.w);
    int slot = g_slot[e];
    *reinterpret_cast<float4*>(g_ex + (size_t)slot * 4) = ev;
}

// ---------------- aggregation: one block (128 thr) per dst node; fp16 gather ----------------
// thread t handles half2 cols {2t,2t+1} (head t>>6) and {256+2t,257+2t} (head 2+(t>>6))
__global__ void k_aggregate(const float* __restrict__ bgat) {
    int dn = blockIdx.x;
    int t = threadIdx.x;
    int h0 = t >> 6, h1 = 2 + (t >> 6);
    int s = g_off[dn], en = g_off[dn + 1];
    const __half2* feat2 = reinterpret_cast<const __half2*>(g_feath);
    float a00 = 0.f, a01 = 0.f, a10 = 0.f, a11 = 0.f;
    float z0 = 0.f, z1 = 0.f;
    int p = s;
    for (; p + 2 <= en; p += 2) {
        int sn0 = g_csr_src[p], sn1 = g_csr_src[p + 1];
        float4 e0 = *reinterpret_cast<const float4*>(g_ex + (size_t)p * 4);
        float4 e1 = *reinterpret_cast<const float4*>(g_ex + (size_t)(p + 1) * 4);
        const float* e0p = reinterpret_cast<const float*>(&e0);
        const float* e1p = reinterpret_cast<const float*>(&e1);
        float w00 = e0p[h0], w01 = e0p[h1];
        float w10 = e1p[h0], w11 = e1p[h1];
        float2 f00 = __half22float2(feat2[(size_t)sn0 * 256 + t]);
        float2 f01 = __half22float2(feat2[(size_t)sn0 * 256 + 128 + t]);
        float2 f10 = __half22float2(feat2[(size_t)sn1 * 256 + t]);
        float2 f11 = __half22float2(feat2[(size_t)sn1 * 256 + 128 + t]);
        a00 = fmaf(w00, f00.x, a00); a01 = fmaf(w00, f00.y, a01);
        a10 = fmaf(w01, f01.x, a10); a11 = fmaf(w01, f01.y, a11);
        a00 = fmaf(w10, f10.x, a00); a01 = fmaf(w10, f10.y, a01);
        a10 = fmaf(w11, f11.x, a10); a11 = fmaf(w11, f11.y, a11);
        z0 += w00 + w10; z1 += w01 + w11;
    }
    if (p < en) {
        int sn0 = g_csr_src[p];
        float4 e0 = *reinterpret_cast<const float4*>(g_ex + (size_t)p * 4);
        const float* e0p = reinterpret_cast<const float*>(&e0);
        float w00 = e0p[h0], w01 = e0p[h1];
        float2 f00 = __half22float2(feat2[(size_t)sn0 * 256 + t]);
        float2 f01 = __half22float2(feat2[(size_t)sn0 * 256 + 128 + t]);
        a00 = fmaf(w00, f00.x, a00); a01 = fmaf(w00, f00.y, a01);
        a10 = fmaf(w01, f01.x, a10); a11 = fmaf(w01, f01.y, a11);
        z0 += w00; z1 += w01;
    }
    float iz0 = 1.f / fmaxf(z0, 1e-20f);
    float iz1 = 1.f / fmaxf(z1, 1e-20f);
    size_t o = (size_t)dn * HDim;
    int c0 = 2 * t, c1 = 256 + 2 * t;
    float r;
    float2 rs0 = *reinterpret_cast<const float2*>(g_res + o + c0);
    float2 rs1 = *reinterpret_cast<const float2*>(g_res + o + c1);
    float2 bg0 = *reinterpret_cast<const float2*>(bgat + c0);
    float2 bg1 = *reinterpret_cast<const float2*>(bgat + c1);
    float2 o0, o1;
    r = a00 * iz0 + rs0.x + bg0.x; o0.x = r > 0.f ? r : NEG_ACT * r;
    r = a01 * iz0 + rs0.y + bg0.y; o0.y = r > 0.f ? r : NEG_ACT * r;
    r = a10 * iz1 + rs1.x + bg1.x; o1.x = r > 0.f ? r : NEG_ACT * r;
    r = a11 * iz1 + rs1.y + bg1.y; o1.y = r > 0.f ? r : NEG_ACT * r;
    *reinterpret_cast<float2*>(g_res + o + c0) = o0;
    *reinterpret_cast<float2*>(g_res + o + c1) = o1;
}

// ---------------- launch ----------------
extern "C" void kernel_launch(void* const* d_in, const int* in_sizes, int n_in,
                              void* d_out, int out_size) {
    const float* features = (const float*)d_in[0];
    const int*   src      = (const int*)  d_in[1];
    const int*   dst      = (const int*)  d_in[2];
    const float* W_fc     = (const float*)d_in[3];
    const float* attn_l   = (const float*)d_in[4];
    const float* attn_r   = (const float*)d_in[5];
    const float* W_res    = (const float*)d_in[6];
    const float* b_gat    = (const float*)d_in[7];
    const float* W_nrm    = (const float*)d_in[8];
    const float* b_nrm    = (const float*)d_in[9];
    const float* ln_g     = (const float*)d_in[10];
    const float* ln_b     = (const float*)d_in[11];
    float* out = (float*)d_out;

    cudaFuncSetAttribute(k_gemm1, cudaFuncAttributeMaxDynamicSharedMemorySize, SMEM_G1);
    cudaFuncSetAttribute(k_gemm2, cudaFuncAttributeMaxDynamicSharedMemorySize, SMEM_G2);

    float *xa = nullptr, *xb = nullptr;
    cudaGetSymbolAddress((void**)&xa, g_xa);
    cudaGetSymbolAddress((void**)&xb, g_xb);

    k_zero_deg<<<(Nn + 255) / 256, 256>>>();
    k_hist<<<(Ee + 255) / 256, 256>>>(dst);
    k_scan<<<1, 1024>>>();
    k_scatter<<<(Ee + 255) / 256, 256>>>(src, dst);
    k_prep_w1<<<(4 * 1024 * 128 + 255) / 256, 256>>>(W_fc, W_res);

    const float* x = features;
    for (int l = 0; l < 4; l++) {
        const float* al  = attn_l + (size_t)l * Hh * Dd;
        const float* ar  = attn_r + (size_t)l * Hh * Dd;
        const float* bg  = b_gat + (size_t)l * HDim;
        const float* bnp = b_nrm + (size_t)l * Dd;
        const float* gp  = ln_g  + (size_t)l * Dd;
        const float* bp  = ln_b  + (size_t)l * Dd;

        k_gemm1<<<dim3((Nn + 127) / 128, 8), 256, SMEM_G1>>>(x, l);
        if (l == 0) k_prep_w2<<<(4 * 128 * 512 + 255) / 256, 256>>>(W_nrm);
        k_elr<<<(Nn * 32 + 255) / 256, 256>>>(al, ar);
        k_edge<<<(Ee + 255) / 256, 256>>>(src, dst);
        k_aggregate<<<Nn, 128>>>(bg);

        float* xo = (l == 3) ? out : ((l & 1) ? xb : xa);
        k_gemm2<<<(Nn + 127) / 128, 256, SMEM_G2>>>(l, bnp, gp, bp, xo);
        x = xo;
    }
}

// round 9
// speedup vs baseline: 2.1192x; 1.0574x over previous
#include <cuda_runtime.h>
#include <cuda_bf16.h>
#include <cuda_fp16.h>
#include <math.h>
#include <float.h>
#include <stdint.h>

#define Nn 50000
#define Ee 800000
#define Hh 4
#define Dd 128
#define HDim 512
#define NEG_ATTN 0.2f
#define NEG_ACT 0.01f

// ---------------- scratch (static device allocations) ----------------
__device__ __half g_feath[(size_t)Nn * HDim];   // fp16 feat (gather source)
__device__ __half g_resh [(size_t)Nn * HDim];   // fp16 res / h (GEMM2 A operand)
__device__ float g_xa  [Nn * Dd];
__device__ float g_xb  [Nn * Dd];
__device__ float g_el  [Nn * Hh];
__device__ float g_er  [Nn * Hh];
__device__ float g_ex  [(size_t)Ee * Hh];
__device__ int   g_deg [Nn];
__device__ int   g_off [Nn + 1];
__device__ int   g_cur [Nn];
__device__ int   g_csr_src[Ee];
__device__ int   g_slot[Ee];

// pre-split transposed weights, [n][k] layout
__device__ __nv_bfloat16 g_w1h[4u * 1024 * 128];   // bf16 hi/lo for GEMM1
__device__ __nv_bfloat16 g_w1l[4u * 1024 * 128];
__device__ __half g_w2h[4u * 128 * 512];           // fp16 hi/lo for GEMM2
__device__ __half g_w2l[4u * 128 * 512];

// smem offsets (bytes): tiles of [128][72] 16-bit = 18432 each
#define O_ALOo 18432
#define O_BHIo 36864
#define O_BLOo 55296
#define SMEM_G1 73728
// GEMM2: A(fp16) at 0, BHI at 18432, BLO at 36864, par at 55296
#define O2_PAR 55296
#define SMEM_G2 (55296 + 1536)

// ---------------- helpers ----------------
__device__ __forceinline__ uint32_t s2u(const void* p) {
    uint32_t a;
    asm("{ .reg .u64 t; cvta.to.shared.u64 t, %1; cvt.u32.u64 %0, t; }" : "=r"(a) : "l"(p));
    return a;
}

#define LDSM4(R, A) \
    asm volatile("ldmatrix.sync.aligned.m8n8.x4.shared.b16 {%0,%1,%2,%3}, [%4];" \
        : "=r"((R)[0]), "=r"((R)[1]), "=r"((R)[2]), "=r"((R)[3]) : "r"(A))

__device__ __forceinline__ void mma_bf16(float d[4], const uint32_t a[4],
                                         uint32_t b0, uint32_t b1) {
    asm volatile(
        "mma.sync.aligned.m16n8k16.row.col.f32.bf16.bf16.f32 "
        "{%0,%1,%2,%3},{%4,%5,%6,%7},{%8,%9},{%0,%1,%2,%3};"
        : "+f"(d[0]), "+f"(d[1]), "+f"(d[2]), "+f"(d[3])
        : "r"(a[0]), "r"(a[1]), "r"(a[2]), "r"(a[3]), "r"(b0), "r"(b1));
}

__device__ __forceinline__ void mma_f16(float d[4], const uint32_t a[4],
                                        uint32_t b0, uint32_t b1) {
    asm volatile(
        "mma.sync.aligned.m16n8k16.row.col.f32.f16.f16.f32 "
        "{%0,%1,%2,%3},{%4,%5,%6,%7},{%8,%9},{%0,%1,%2,%3};"
        : "+f"(d[0]), "+f"(d[1]), "+f"(d[2]), "+f"(d[3])
        : "r"(a[0]), "r"(a[1]), "r"(a[2]), "r"(a[3]), "r"(b0), "r"(b1));
}

__device__ __forceinline__ void split2(float x, float y, __nv_bfloat162& h, __nv_bfloat162& lo) {
    h.x = __float2bfloat16_rn(x); h.y = __float2bfloat16_rn(y);
    lo.x = __float2bfloat16_rn(x - __bfloat162float(h.x));
    lo.y = __float2bfloat16_rn(y - __bfloat162float(h.y));
}

// ---------------- weight prep ----------------
__global__ void k_prep_w1(const float* __restrict__ Wfc, const float* __restrict__ Wres) {
    int id = blockIdx.x * 256 + threadIdx.x;
    if (id >= 4 * 1024 * 128) return;
    int k = id & 127, n = (id >> 7) & 1023, l = id >> 17;
    float v = (n < 512) ? Wfc[((size_t)l * 128 + k) * 512 + n]
                        : Wres[((size_t)l * 128 + k) * 512 + (n - 512)];
    __nv_bfloat16 h = __float2bfloat16_rn(v);
    g_w1h[id] = h;
    g_w1l[id] = __float2bfloat16_rn(v - __bfloat162float(h));
}

__global__ void k_prep_w2(const float* __restrict__ Wn) {
    int id = blockIdx.x * 256 + threadIdx.x;
    if (id >= 4 * 128 * 512) return;
    int k = id & 511, n = (id >> 9) & 127, l = id >> 16;
    float v = Wn[((size_t)l * 512 + k) * 128 + n];
    __half h = __float2half_rn(v);
    g_w2h[id] = h;
    g_w2l[id] = __float2half_rn(v - __half2float(h));
}

// ---------------- CSR build ----------------
__global__ void k_zero_deg() {
    int i = blockIdx.x * blockDim.x + threadIdx.x;
    if (i < Nn) g_deg[i] = 0;
}
__global__ void k_hist(const int* __restrict__ dst) {
    int i = blockIdx.x * blockDim.x + threadIdx.x;
    if (i < Ee) atomicAdd(&g_deg[dst[i]], 1);
}
__global__ void k_scan() {
    __shared__ int sbuf[1024];
    __shared__ int carry;
    int t = threadIdx.x;
    if (t == 0) carry = 0;
    __syncthreads();
    for (int base = 0; base < Nn; base += 1024) {
        int i = base + t;
        int v = (i < Nn) ? g_deg[i] : 0;
        sbuf[t] = v;
        __syncthreads();
        for (int off = 1; off < 1024; off <<= 1) {
            int add = (t >= off) ? sbuf[t - off] : 0;
            __syncthreads();
            sbuf[t] += add;
            __syncthreads();
        }
        int incl = sbuf[t];
        int excl = carry + incl - v;
        if (i < Nn) { g_off[i] = excl; g_cur[i] = excl; }
        int total = sbuf[1023];
        __syncthreads();
        if (t == 0) carry += total;
        __syncthreads();
    }
    if (t == 0) g_off[Nn] = carry;
}
__global__ void k_scatter(const int* __restrict__ src, const int* __restrict__ dst) {
    int i = blockIdx.x * blockDim.x + threadIdx.x;
    if (i < Ee) {
        int d = dst[i];
        int p = atomicAdd(&g_cur[d], 1);
        g_csr_src[p] = src[i];
        g_slot[i] = p;
    }
}

// ============ GEMM1: [feat|res] (both fp16) = x @ W1  (bf16 split, ldmatrix+mma) ============
__global__ void __launch_bounds__(256) k_gemm1(const float* __restrict__ X, int l) {
    extern __shared__ char smem[];
    uint32_t sb = s2u(smem);
    int t = threadIdx.x, lane = t & 31, wid = t >> 5;
    int gr = lane >> 2, gc = lane & 3;
    int wm = (wid & 1) * 64, wn = (wid >> 1) * 32;
    int row0 = blockIdx.x * 128;
    int yb = blockIdx.y;

    const __nv_bfloat16* Wh = g_w1h + ((size_t)l * 1024 + (size_t)yb * 128) * 128;
    const __nv_bfloat16* Wl = g_w1l + ((size_t)l * 1024 + (size_t)yb * 128) * 128;

    float d[4][4][4];
#pragma unroll
    for (int i = 0; i < 4; i++)
#pragma unroll
        for (int j = 0; j < 4; j++)
#pragma unroll
            for (int q = 0; q < 4; q++) d[i][j][q] = 0.f;

    int arow = (lane & 7) + ((lane >> 3) & 1) * 8;
    int akof = (lane >> 4) * 8;
    int bnr  = (lane & 7) + ((lane >> 4) << 3);
    int bkof = ((lane >> 3) & 1) * 8;

#pragma unroll
    for (int kc = 0; kc < 2; kc++) {
        int k0 = kc * 64;
#pragma unroll
        for (int u = 0; u < 8; u++) {
            int id = t + 256 * u;
            int r = id >> 4, c4 = (id & 15) * 4;
            int grow = row0 + r;
            float4 v = make_float4(0.f, 0.f, 0.f, 0.f);
            if (grow < Nn) v = *reinterpret_cast<const float4*>(X + (size_t)grow * Dd + k0 + c4);
            __nv_bfloat162 h0, l0, h1, l1;
            split2(v.x, v.y, h0, l0);
            split2(v.z, v.w, h1, l1);
            char* pa = smem + (size_t)(r * 72 + c4) * 2;
            reinterpret_cast<__nv_bfloat162*>(pa)[0] = h0;
            reinterpret_cast<__nv_bfloat162*>(pa)[1] = h1;
            reinterpret_cast<__nv_bfloat162*>(pa + O_ALOo)[0] = l0;
            reinterpret_cast<__nv_bfloat162*>(pa + O_ALOo)[1] = l1;
        }
#pragma unroll
        for (int u = 0; u < 4; u++) {
            int id = t + 256 * u;
            int r = id >> 3, c8 = (id & 7) * 8;
            char* pb = smem + O_BHIo + (size_t)(r * 72 + c8) * 2;
            *reinterpret_cast<uint4*>(pb) = *reinterpret_cast<const uint4*>(Wh + (size_t)r * 128 + k0 + c8);
            *reinterpret_cast<uint4*>(pb + (O_BLOo - O_BHIo)) = *reinterpret_cast<const uint4*>(Wl + (size_t)r * 128 + k0 + c8);
        }
        __syncthreads();
#pragma unroll
        for (int kt = 0; kt < 4; kt++) {
            uint32_t ah[4][4], alf[4][4], bhf[2][4], blf[2][4];
#pragma unroll
            for (int mt = 0; mt < 4; mt++) {
                uint32_t ad = sb + 2u * ((wm + 16 * mt + arow) * 72 + 16 * kt + akof);
                LDSM4(ah[mt], ad);
                LDSM4(alf[mt], ad + O_ALOo);
            }
#pragma unroll
            for (int g = 0; g < 2; g++) {
                uint32_t bd = sb + O_BHIo + 2u * ((wn + 16 * g + bnr) * 72 + 16 * kt + bkof);
                LDSM4(bhf[g], bd);
                LDSM4(blf[g], bd + (O_BLOo - O_BHIo));
            }
#pragma unroll
            for (int mt = 0; mt < 4; mt++)
#pragma unroll
                for (int nt = 0; nt < 4; nt++) {
                    uint32_t bh0 = bhf[nt >> 1][(nt & 1) * 2], bh1 = bhf[nt >> 1][(nt & 1) * 2 + 1];
                    uint32_t bl0 = blf[nt >> 1][(nt & 1) * 2], bl1 = blf[nt >> 1][(nt & 1) * 2 + 1];
                    mma_bf16(d[mt][nt], ah[mt], bh0, bh1);
                    mma_bf16(d[mt][nt], ah[mt], bl0, bl1);
                    mma_bf16(d[mt][nt], alf[mt], bh0, bh1);
                }
        }
        __syncthreads();
    }

    // unified fp16 epilogue (feat for yb<4, res for yb>=4)
    __half* C = (yb < 4) ? g_feath : g_resh;
    int wc0 = (yb & 3) * 128;
#pragma unroll
    for (int mt = 0; mt < 4; mt++) {
        int r0 = row0 + wm + 16 * mt + gr;
        int r1 = r0 + 8;
#pragma unroll
        for (int nt = 0; nt < 4; nt++) {
            int col = wc0 + wn + nt * 8 + 2 * gc;
            if (r0 < Nn)
                *reinterpret_cast<__half2*>(C + (size_t)r0 * HDim + col) =
                    __floats2half2_rn(d[mt][nt][0], d[mt][nt][1]);
            if (r1 < Nn)
                *reinterpret_cast<__half2*>(C + (size_t)r1 * HDim + col) =
                    __floats2half2_rn(d[mt][nt][2], d[mt][nt][3]);
        }
    }
}

// ============ GEMM2 + bias + LayerNorm: out = LN(h(fp16) @ Wn + bn) ============
// A fp16 single, B fp16 hi/lo -> 2 MMAs per tile
__global__ void __launch_bounds__(256) k_gemm2(int l, const float* __restrict__ bn,
                                               const float* __restrict__ gam,
                                               const float* __restrict__ bet,
                                               float* __restrict__ out) {
    extern __shared__ char smem[];
    uint32_t sb = s2u(smem);
    int t = threadIdx.x, lane = t & 31, wid = t >> 5;
    int gr = lane >> 2, gc = lane & 3;
    int wm = (wid & 1) * 64, wnid = wid >> 1, wn = wnid * 32;
    int row0 = blockIdx.x * 128;

    float* par = reinterpret_cast<float*>(smem + O2_PAR);
    if (t < 128) { par[t] = bn[t]; par[128 + t] = gam[t]; par[256 + t] = bet[t]; }

    const __half* Wh = g_w2h + (size_t)l * 128 * 512;
    const __half* Wl = g_w2l + (size_t)l * 128 * 512;

    float d[4][4][4];
#pragma unroll
    for (int i = 0; i < 4; i++)
#pragma unroll
        for (int j = 0; j < 4; j++)
#pragma unroll
            for (int q = 0; q < 4; q++) d[i][j][q] = 0.f;

    int arow = (lane & 7) + ((lane >> 3) & 1) * 8;
    int akof = (lane >> 4) * 8;
    int bnr  = (lane & 7) + ((lane >> 4) << 3);
    int bkof = ((lane >> 3) & 1) * 8;

    for (int kc = 0; kc < 8; kc++) {
        int k0 = kc * 64;
        // A: 128 rows x 64 fp16 — straight vector copy (8 halfs per iter)
#pragma unroll
        for (int u = 0; u < 4; u++) {
            int id = t + 256 * u;            // 0..1023
            int r = id >> 3, c8 = (id & 7) * 8;   // r 0..127, c8 0..56
            int grow = row0 + r;
            uint4 v = make_uint4(0u, 0u, 0u, 0u);
            if (grow < Nn) v = *reinterpret_cast<const uint4*>(g_resh + (size_t)grow * HDim + k0 + c8);
            *reinterpret_cast<uint4*>(smem + (size_t)(r * 72 + c8) * 2) = v;
        }
        // B: 128 n-rows x 64 fp16 hi/lo
#pragma unroll
        for (int u = 0; u < 4; u++) {
            int id = t + 256 * u;
            int r = id >> 3, c8 = (id & 7) * 8;
            char* pb = smem + O_ALOo + (size_t)(r * 72 + c8) * 2;
            *reinterpret_cast<uint4*>(pb) = *reinterpret_cast<const uint4*>(Wh + (size_t)r * 512 + k0 + c8);
            *reinterpret_cast<uint4*>(pb + 18432) = *reinterpret_cast<const uint4*>(Wl + (size_t)r * 512 + k0 + c8);
        }
        __syncthreads();
#pragma unroll
        for (int kt = 0; kt < 4; kt++) {
            uint32_t ah[4][4], bhf[2][4], blf[2][4];
#pragma unroll
            for (int mt = 0; mt < 4; mt++) {
                uint32_t ad = sb + 2u * ((wm + 16 * mt + arow) * 72 + 16 * kt + akof);
                LDSM4(ah[mt], ad);
            }
#pragma unroll
            for (int g = 0; g < 2; g++) {
                uint32_t bd = sb + O_ALOo + 2u * ((wn + 16 * g + bnr) * 72 + 16 * kt + bkof);
                LDSM4(bhf[g], bd);
                LDSM4(blf[g], bd + 18432);
            }
#pragma unroll
            for (int mt = 0; mt < 4; mt++)
#pragma unroll
                for (int nt = 0; nt < 4; nt++) {
                    uint32_t bh0 = bhf[nt >> 1][(nt & 1) * 2], bh1 = bhf[nt >> 1][(nt & 1) * 2 + 1];
                    uint32_t bl0 = blf[nt >> 1][(nt & 1) * 2], bl1 = blf[nt >> 1][(nt & 1) * 2 + 1];
                    mma_f16(d[mt][nt], ah[mt], bh0, bh1);
                    mma_f16(d[mt][nt], ah[mt], bl0, bl1);
                }
        }
        __syncthreads();
    }

    // ---- fused bias + LayerNorm epilogue ----
    float* red_s = reinterpret_cast<float*>(smem);          // 4 x 128
    float* red_q = reinterpret_cast<float*>(smem + 2048);   // 4 x 128
    float bnv[4][2];
#pragma unroll
    for (int nt = 0; nt < 4; nt++) {
        int col = wn + nt * 8 + 2 * gc;
        bnv[nt][0] = par[col]; bnv[nt][1] = par[col + 1];
    }
#pragma unroll
    for (int mt = 0; mt < 4; mt++) {
        float s0 = 0.f, q0 = 0.f, s1 = 0.f, q1 = 0.f;
#pragma unroll
        for (int nt = 0; nt < 4; nt++) {
            float y00 = d[mt][nt][0] + bnv[nt][0];
            float y01 = d[mt][nt][1] + bnv[nt][1];
            float y10 = d[mt][nt][2] + bnv[nt][0];
            float y11 = d[mt][nt][3] + bnv[nt][1];
            d[mt][nt][0] = y00; d[mt][nt][1] = y01;
            d[mt][nt][2] = y10; d[mt][nt][3] = y11;
            s0 += y00 + y01; q0 += y00 * y00 + y01 * y01;
            s1 += y10 + y11; q1 += y10 * y10 + y11 * y11;
        }
#pragma unroll
        for (int o = 1; o < 4; o <<= 1) {
            s0 += __shfl_xor_sync(0xffffffffu, s0, o);
            q0 += __shfl_xor_sync(0xffffffffu, q0, o);
            s1 += __shfl_xor_sync(0xffffffffu, s1, o);
            q1 += __shfl_xor_sync(0xffffffffu, q1, o);
        }
        if (gc == 0) {
            int rb = wm + 16 * mt + gr;
            red_s[wnid * 128 + rb] = s0; red_q[wnid * 128 + rb] = q0;
            red_s[wnid * 128 + rb + 8] = s1; red_q[wnid * 128 + rb + 8] = q1;
        }
    }
    __syncthreads();
#pragma unroll
    for (int mt = 0; mt < 4; mt++) {
        int rb = wm + 16 * mt + gr;
        float s0 = red_s[rb] + red_s[128 + rb] + red_s[256 + rb] + red_s[384 + rb];
        float q0 = red_q[rb] + red_q[128 + rb] + red_q[256 + rb] + red_q[384 + rb];
        float s1 = red_s[rb + 8] + red_s[128 + rb + 8] + red_s[256 + rb + 8] + red_s[384 + rb + 8];
        float q1 = red_q[rb + 8] + red_q[128 + rb + 8] + red_q[256 + rb + 8] + red_q[384 + rb + 8];
        float mu0 = s0 * (1.f / 128.f);
        float mu1 = s1 * (1.f / 128.f);
        float rstd0 = rsqrtf(q0 * (1.f / 128.f) - mu0 * mu0 + 1e-5f);
        float rstd1 = rsqrtf(q1 * (1.f / 128.f) - mu1 * mu1 + 1e-5f);
        int r0 = row0 + rb, r1 = r0 + 8;
#pragma unroll
        for (int nt = 0; nt < 4; nt++) {
            int col = wn + nt * 8 + 2 * gc;
            float g0 = par[128 + col], g1 = par[128 + col + 1];
            float b0 = par[256 + col], b1 = par[256 + col + 1];
            if (r0 < Nn)
                *reinterpret_cast<float2*>(out + (size_t)r0 * Dd + col) =
                    make_float2((d[mt][nt][0] - mu0) * rstd0 * g0 + b0,
                                (d[mt][nt][1] - mu0) * rstd0 * g1 + b1);
            if (r1 < Nn)
                *reinterpret_cast<float2*>(out + (size_t)r1 * Dd + col) =
                    make_float2((d[mt][nt][2] - mu1) * rstd1 * g0 + b0,
                                (d[mt][nt][3] - mu1) * rstd1 * g1 + b1);
        }
    }
}

// ---------------- el/er: per-node dot(feat_fp16, attn) ----------------
__global__ void k_elr(const float* __restrict__ al, const float* __restrict__ ar) {
    int gt = blockIdx.x * blockDim.x + threadIdx.x;
    int node = gt >> 5;
    int lane = gt & 31;
    if (node >= Nn) return;
    const __half2* f = reinterpret_cast<const __half2*>(g_feath + (size_t)node * HDim);
#pragma unroll
    for (int h = 0; h < Hh; h++) {
        float sl = 0.f, sr = 0.f;
#pragma unroll
        for (int i = 0; i < 2; i++) {
            int j = h * 64 + lane + 32 * i;
            float2 v = __half22float2(f[j]);
            float2 a2 = *reinterpret_cast<const float2*>(al + 2 * j);
            float2 b2 = *reinterpret_cast<const float2*>(ar + 2 * j);
            sl += v.x * a2.x + v.y * a2.y;
            sr += v.x * b2.x + v.y * b2.y;
        }
#pragma unroll
        for (int o = 16; o; o >>= 1) {
            sl += __shfl_xor_sync(0xffffffffu, sl, o);
            sr += __shfl_xor_sync(0xffffffffu, sr, o);
        }
        if (lane == 0) {
            g_el[node * Hh + h] = sl;
            g_er[node * Hh + h] = sr;
        }
    }
}

// ---------------- single-pass edge kernel ----------------
__global__ void k_edge(const int* __restrict__ src, const int* __restrict__ dst) {
    int e = blockIdx.x * blockDim.x + threadIdx.x;
    if (e >= Ee) return;
    int s = src[e], d = dst[e];
    float4 a = *reinterpret_cast<const float4*>(g_el + (size_t)s * 4);
    float4 b = *reinterpret_cast<const float4*>(g_er + (size_t)d * 4);
    float4 ev;
    ev.x = a.x + b.x; ev.x = ev.x > 0.f ? ev.x : NEG_ATTN * ev.x; ev.x = __expf(ev.x);
    ev.y = a.y + b.y; ev.y = ev.y > 0.f ? ev.y : NEG_ATTN * ev.y; ev.y = __expf(ev.y);
    ev.z = a.z + b.z; ev.z = ev.z > 0.f ? ev.z : NEG_ATTN * ev.z; ev.z = __expf(ev.z);
    ev.w = a.w + b.w; ev.w = ev.w > 0.f ? ev.w : NEG_ATTN * ev.w; ev.w = __expf(ev.w);
    int slot = g_slot[e];
    *reinterpret_cast<float4*>(g_ex + (size_t)slot * 4) = ev;
}

// ---------------- aggregation: one block (128 thr) per dst node; fp16 gather, fp16 res ----------------
__global__ void k_aggregate(const float* __restrict__ bgat) {
    int dn = blockIdx.x;
    int t = threadIdx.x;
    int h0 = t >> 6, h1 = 2 + (t >> 6);
    int s = g_off[dn], en = g_off[dn + 1];
    const __half2* feat2 = reinterpret_cast<const __half2*>(g_feath);
    float a00 = 0.f, a01 = 0.f, a10 = 0.f, a11 = 0.f;
    float z0 = 0.f, z1 = 0.f;
    int p = s;
    for (; p + 2 <= en; p += 2) {
        int sn0 = g_csr_src[p], sn1 = g_csr_src[p + 1];
        float4 e0 = *reinterpret_cast<const float4*>(g_ex + (size_t)p * 4);
        float4 e1 = *reinterpret_cast<const float4*>(g_ex + (size_t)(p + 1) * 4);
        const float* e0p = reinterpret_cast<const float*>(&e0);
        const float* e1p = reinterpret_cast<const float*>(&e1);
        float w00 = e0p[h0], w01 = e0p[h1];
        float w10 = e1p[h0], w11 = e1p[h1];
        float2 f00 = __half22float2(feat2[(size_t)sn0 * 256 + t]);
        float2 f01 = __half22float2(feat2[(size_t)sn0 * 256 + 128 + t]);
        float2 f10 = __half22float2(feat2[(size_t)sn1 * 256 + t]);
        float2 f11 = __half22float2(feat2[(size_t)sn1 * 256 + 128 + t]);
        a00 = fmaf(w00, f00.x, a00); a01 = fmaf(w00, f00.y, a01);
        a10 = fmaf(w01, f01.x, a10); a11 = fmaf(w01, f01.y, a11);
        a00 = fmaf(w10, f10.x, a00); a01 = fmaf(w10, f10.y, a01);
        a10 = fmaf(w11, f11.x, a10); a11 = fmaf(w11, f11.y, a11);
        z0 += w00 + w10; z1 += w01 + w11;
    }
    if (p < en) {
        int sn0 = g_csr_src[p];
        float4 e0 = *reinterpret_cast<const float4*>(g_ex + (size_t)p * 4);
        const float* e0p = reinterpret_cast<const float*>(&e0);
        float w00 = e0p[h0], w01 = e0p[h1];
        float2 f00 = __half22float2(feat2[(size_t)sn0 * 256 + t]);
        float2 f01 = __half22float2(feat2[(size_t)sn0 * 256 + 128 + t]);
        a00 = fmaf(w00, f00.x, a00); a01 = fmaf(w00, f00.y, a01);
        a10 = fmaf(w01, f01.x, a10); a11 = fmaf(w01, f01.y, a11);
        z0 += w00; z1 += w01;
    }
    float iz0 = 1.f / fmaxf(z0, 1e-20f);
    float iz1 = 1.f / fmaxf(z1, 1e-20f);
    __half2* res2 = reinterpret_cast<__half2*>(g_resh);
    size_t o2 = (size_t)dn * 256;
    int c0 = 2 * t, c1 = 256 + 2 * t;
    float2 rs0 = __half22float2(res2[o2 + t]);
    float2 rs1 = __half22float2(res2[o2 + 128 + t]);
    float2 bg0 = *reinterpret_cast<const float2*>(bgat + c0);
    float2 bg1 = *reinterpret_cast<const float2*>(bgat + c1);
    float r;
    float2 o0, o1;
    r = a00 * iz0 + rs0.x + bg0.x; o0.x = r > 0.f ? r : NEG_ACT * r;
    r = a01 * iz0 + rs0.y + bg0.y; o0.y = r > 0.f ? r : NEG_ACT * r;
    r = a10 * iz1 + rs1.x + bg1.x; o1.x = r > 0.f ? r : NEG_ACT * r;
    r = a11 * iz1 + rs1.y + bg1.y; o1.y = r > 0.f ? r : NEG_ACT * r;
    res2[o2 + t]       = __floats2half2_rn(o0.x, o0.y);
    res2[o2 + 128 + t] = __floats2half2_rn(o1.x, o1.y);
}

// ---------------- launch ----------------
extern "C" void kernel_launch(void* const* d_in, const int* in_sizes, int n_in,
                              void* d_out, int out_size) {
    const float* features = (const float*)d_in[0];
    const int*   src      = (const int*)  d_in[1];
    const int*   dst      = (const int*)  d_in[2];
    const float* W_fc     = (const float*)d_in[3];
    const float* attn_l   = (const float*)d_in[4];
    const float* attn_r   = (const float*)d_in[5];
    const float* W_res    = (const float*)d_in[6];
    const float* b_gat    = (const float*)d_in[7];
    const float* W_nrm    = (const float*)d_in[8];
    const float* b_nrm    = (const float*)d_in[9];
    const float* ln_g     = (const float*)d_in[10];
    const float* ln_b     = (const float*)d_in[11];
    float* out = (float*)d_out;

    cudaFuncSetAttribute(k_gemm1, cudaFuncAttributeMaxDynamicSharedMemorySize, SMEM_G1);
    cudaFuncSetAttribute(k_gemm2, cudaFuncAttributeMaxDynamicSharedMemorySize, SMEM_G2);

    float *xa = nullptr, *xb = nullptr;
    cudaGetSymbolAddress((void**)&xa, g_xa);
    cudaGetSymbolAddress((void**)&xb, g_xb);

    k_zero_deg<<<(Nn + 255) / 256, 256>>>();
    k_hist<<<(Ee + 255) / 256, 256>>>(dst);
    k_scan<<<1, 1024>>>();
    k_scatter<<<(Ee + 255) / 256, 256>>>(src, dst);
    k_prep_w1<<<(4 * 1024 * 128 + 255) / 256, 256>>>(W_fc, W_res);

    const float* x = features;
    for (int l = 0; l < 4; l++) {
        const float* al  = attn_l + (size_t)l * Hh * Dd;
        const float* ar  = attn_r + (size_t)l * Hh * Dd;
        const float* bg  = b_gat + (size_t)l * HDim;
        const float* bnp = b_nrm + (size_t)l * Dd;
        const float* gp  = ln_g  + (size_t)l * Dd;
        const float* bp  = ln_b  + (size_t)l * Dd;

        k_gemm1<<<dim3((Nn + 127) / 128, 8), 256, SMEM_G1>>>(x, l);
        if (l == 0) k_prep_w2<<<(4 * 128 * 512 + 255) / 256, 256>>>(W_nrm);
        k_elr<<<(Nn * 32 + 255) / 256, 256>>>(al, ar);
        k_edge<<<(Ee + 255) / 256, 256>>>(src, dst);
        k_aggregate<<<Nn, 128>>>(bg);

        float* xo = (l == 3) ? out : ((l & 1) ? xb : xa);
        k_gemm2<<<(Nn + 127) / 128, 256, SMEM_G2>>>(l, bnp, gp, bp, xo);
        x = xo;
    }
}

// round 11
// speedup vs baseline: 2.2730x; 1.0725x over previous
#include <cuda_runtime.h>
#include <cuda_bf16.h>
#include <cuda_fp16.h>
#include <math.h>
#include <float.h>
#include <stdint.h>

#define Nn 50000
#define Ee 800000
#define Hh 4
#define Dd 128
#define HDim 512
#define NEG_ATTN 0.2f
#define NEG_ACT 0.01f

// ---------------- scratch (static device allocations) ----------------
__device__ __half g_feath[(size_t)Nn * HDim];   // fp16 feat (gather source)
__device__ __half g_resh [(size_t)Nn * HDim];   // fp16 res / h (GEMM2 A operand)
__device__ __nv_bfloat16 g_xah[(size_t)Nn * Dd];  // layer input x, bf16 hi
__device__ __nv_bfloat16 g_xal[(size_t)Nn * Dd];  // layer input x, bf16 lo
__device__ float g_el  [Nn * Hh];
__device__ float g_er  [Nn * Hh];
__device__ float g_ex  [(size_t)Ee * Hh];
__device__ int   g_deg [Nn];
__device__ int   g_off [Nn + 1];
__device__ int   g_cur [Nn];
__device__ int   g_csr_src[Ee];
__device__ int   g_slot[Ee];

// pre-split transposed weights, [n][k] layout
__device__ __nv_bfloat16 g_w1h[4u * 1024 * 128];   // bf16 hi/lo for GEMM1
__device__ __nv_bfloat16 g_w1l[4u * 1024 * 128];
__device__ __half g_w2h[4u * 128 * 512];           // fp16 hi/lo for GEMM2
__device__ __half g_w2l[4u * 128 * 512];

// smem offsets (bytes): tiles of [128][72] 16-bit = 18432 each
#define O_ALOo 18432
#define O_BHIo 36864
#define O_BLOo 55296
#define SMEM_G1 73728
// GEMM2: A(fp16) at 0, BHI at 18432, BLO at 36864, par at 55296
#define O2_PAR 55296
#define SMEM_G2 (55296 + 1536)

// ---------------- helpers ----------------
__device__ __forceinline__ uint32_t s2u(const void* p) {
    uint32_t a;
    asm("{ .reg .u64 t; cvta.to.shared.u64 t, %1; cvt.u32.u64 %0, t; }" : "=r"(a) : "l"(p));
    return a;
}

#define LDSM4(R, A) \
    asm volatile("ldmatrix.sync.aligned.m8n8.x4.shared.b16 {%0,%1,%2,%3}, [%4];" \
        : "=r"((R)[0]), "=r"((R)[1]), "=r"((R)[2]), "=r"((R)[3]) : "r"(A))

__device__ __forceinline__ void mma_bf16(float d[4], const uint32_t a[4],
                                         uint32_t b0, uint32_t b1) {
    asm volatile(
        "mma.sync.aligned.m16n8k16.row.col.f32.bf16.bf16.f32 "
        "{%0,%1,%2,%3},{%4,%5,%6,%7},{%8,%9},{%0,%1,%2,%3};"
        : "+f"(d[0]), "+f"(d[1]), "+f"(d[2]), "+f"(d[3])
        : "r"(a[0]), "r"(a[1]), "r"(a[2]), "r"(a[3]), "r"(b0), "r"(b1));
}

__device__ __forceinline__ void mma_f16(float d[4], const uint32_t a[4],
                                        uint32_t b0, uint32_t b1) {
    asm volatile(
        "mma.sync.aligned.m16n8k16.row.col.f32.f16.f16.f32 "
        "{%0,%1,%2,%3},{%4,%5,%6,%7},{%8,%9},{%0,%1,%2,%3};"
        : "+f"(d[0]), "+f"(d[1]), "+f"(d[2]), "+f"(d[3])
        : "r"(a[0]), "r"(a[1]), "r"(a[2]), "r"(a[3]), "r"(b0), "r"(b1));
}

// ---------------- weight / input prep ----------------
__global__ void k_prep_w1(const float* __restrict__ Wfc, const float* __restrict__ Wres) {
    int id = blockIdx.x * 256 + threadIdx.x;
    if (id >= 4 * 1024 * 128) return;
    int k = id & 127, n = (id >> 7) & 1023, l = id >> 17;
    float v = (n < 512) ? Wfc[((size_t)l * 128 + k) * 512 + n]
                        : Wres[((size_t)l * 128 + k) * 512 + (n - 512)];
    __nv_bfloat16 h = __float2bfloat16_rn(v);
    g_w1h[id] = h;
    g_w1l[id] = __float2bfloat16_rn(v - __bfloat162float(h));
}

__global__ void k_prep_w2(const float* __restrict__ Wn) {
    int id = blockIdx.x * 256 + threadIdx.x;
    if (id >= 4 * 128 * 512) return;
    int k = id & 511, n = (id >> 9) & 127, l = id >> 16;
    float v = Wn[((size_t)l * 512 + k) * 128 + n];
    __half h = __float2half_rn(v);
    g_w2h[id] = h;
    g_w2l[id] = __float2half_rn(v - __half2float(h));
}

__global__ void k_prep_x(const float* __restrict__ X) {
    int id = blockIdx.x * 256 + threadIdx.x;
    if (id >= Nn * Dd) return;
    float v = X[id];
    __nv_bfloat16 h = __float2bfloat16_rn(v);
    g_xah[id] = h;
    g_xal[id] = __float2bfloat16_rn(v - __bfloat162float(h));
}

// ---------------- CSR build ----------------
__global__ void k_zero_deg() {
    int i = blockIdx.x * blockDim.x + threadIdx.x;
    if (i < Nn) g_deg[i] = 0;
}
__global__ void k_hist(const int* __restrict__ dst) {
    int i = blockIdx.x * blockDim.x + threadIdx.x;
    if (i < Ee) atomicAdd(&g_deg[dst[i]], 1);
}
__global__ void k_scan() {
    __shared__ int sbuf[1024];
    __shared__ int carry;
    int t = threadIdx.x;
    if (t == 0) carry = 0;
    __syncthreads();
    for (int base = 0; base < Nn; base += 1024) {
        int i = base + t;
        int v = (i < Nn) ? g_deg[i] : 0;
        sbuf[t] = v;
        __syncthreads();
        for (int off = 1; off < 1024; off <<= 1) {
            int add = (t >= off) ? sbuf[t - off] : 0;
            __syncthreads();
            sbuf[t] += add;
            __syncthreads();
        }
        int incl = sbuf[t];
        int excl = carry + incl - v;
        if (i < Nn) { g_off[i] = excl; g_cur[i] = excl; }
        int total = sbuf[1023];
        __syncthreads();
        if (t == 0) carry += total;
        __syncthreads();
    }
    if (t == 0) g_off[Nn] = carry;
}
__global__ void k_scatter(const int* __restrict__ src, const int* __restrict__ dst) {
    int i = blockIdx.x * blockDim.x + threadIdx.x;
    if (i < Ee) {
        int d = dst[i];
        int p = atomicAdd(&g_cur[d], 1);
        g_csr_src[p] = src[i];
        g_slot[i] = p;
    }
}

// ============ GEMM1: [feat|res] = x @ W1 ; fused el/er for yb<4 ============
// A pre-split bf16 hi/lo (straight copy); B bf16 hi/lo; 3 MMAs per tile.
__global__ void __launch_bounds__(256) k_gemm1(int l, const float* __restrict__ al,
                                               const float* __restrict__ ar) {
    extern __shared__ char smem[];
    uint32_t sb = s2u(smem);
    int t = threadIdx.x, lane = t & 31, wid = t >> 5;
    int gr = lane >> 2, gc = lane & 3;
    int wm = (wid & 1) * 64, wnid = wid >> 1, wn = wnid * 32;
    int row0 = blockIdx.x * 128;
    int yb = blockIdx.y;

    const __nv_bfloat16* Wh = g_w1h + ((size_t)l * 1024 + (size_t)yb * 128) * 128;
    const __nv_bfloat16* Wl = g_w1l + ((size_t)l * 1024 + (size_t)yb * 128) * 128;

    float d[4][4][4];
#pragma unroll
    for (int i = 0; i < 4; i++)
#pragma unroll
        for (int j = 0; j < 4; j++)
#pragma unroll
            for (int q = 0; q < 4; q++) d[i][j][q] = 0.f;

    int arow = (lane & 7) + ((lane >> 3) & 1) * 8;
    int akof = (lane >> 4) * 8;
    int bnr  = (lane & 7) + ((lane >> 4) << 3);
    int bkof = ((lane >> 3) & 1) * 8;

#pragma unroll
    for (int kc = 0; kc < 2; kc++) {
        int k0 = kc * 64;
        // A: 128 rows x 64 bf16 hi/lo — straight vector copy
#pragma unroll
        for (int u = 0; u < 4; u++) {
            int id = t + 256 * u;
            int r = id >> 3, c8 = (id & 7) * 8;
            int grow = row0 + r;
            uint4 vh = make_uint4(0u, 0u, 0u, 0u), vl = make_uint4(0u, 0u, 0u, 0u);
            if (grow < Nn) {
                vh = *reinterpret_cast<const uint4*>(g_xah + (size_t)grow * Dd + k0 + c8);
                vl = *reinterpret_cast<const uint4*>(g_xal + (size_t)grow * Dd + k0 + c8);
            }
            char* pa = smem + (size_t)(r * 72 + c8) * 2;
            *reinterpret_cast<uint4*>(pa) = vh;
            *reinterpret_cast<uint4*>(pa + O_ALOo) = vl;
        }
        // B: 128 n-rows x 64 bf16 hi/lo
#pragma unroll
        for (int u = 0; u < 4; u++) {
            int id = t + 256 * u;
            int r = id >> 3, c8 = (id & 7) * 8;
            char* pb = smem + O_BHIo + (size_t)(r * 72 + c8) * 2;
            *reinterpret_cast<uint4*>(pb) = *reinterpret_cast<const uint4*>(Wh + (size_t)r * 128 + k0 + c8);
            *reinterpret_cast<uint4*>(pb + (O_BLOo - O_BHIo)) = *reinterpret_cast<const uint4*>(Wl + (size_t)r * 128 + k0 + c8);
        }
        __syncthreads();
#pragma unroll
        for (int kt = 0; kt < 4; kt++) {
            uint32_t ah[4][4], alf[4][4], bhf[2][4], blf[2][4];
#pragma unroll
            for (int mt = 0; mt < 4; mt++) {
                uint32_t ad = sb + 2u * ((wm + 16 * mt + arow) * 72 + 16 * kt + akof);
                LDSM4(ah[mt], ad);
                LDSM4(alf[mt], ad + O_ALOo);
            }
#pragma unroll
            for (int g = 0; g < 2; g++) {
                uint32_t bd = sb + O_BHIo + 2u * ((wn + 16 * g + bnr) * 72 + 16 * kt + bkof);
                LDSM4(bhf[g], bd);
                LDSM4(blf[g], bd + (O_BLOo - O_BHIo));
            }
#pragma unroll
            for (int mt = 0; mt < 4; mt++)
#pragma unroll
                for (int nt = 0; nt < 4; nt++) {
                    uint32_t bh0 = bhf[nt >> 1][(nt & 1) * 2], bh1 = bhf[nt >> 1][(nt & 1) * 2 + 1];
                    uint32_t bl0 = blf[nt >> 1][(nt & 1) * 2], bl1 = blf[nt >> 1][(nt & 1) * 2 + 1];
                    mma_bf16(d[mt][nt], ah[mt], bh0, bh1);
                    mma_bf16(d[mt][nt], ah[mt], bl0, bl1);
                    mma_bf16(d[mt][nt], alf[mt], bh0, bh1);
                }
        }
        __syncthreads();
    }

    // fp16 store (feat for yb<4, res for yb>=4)
    __half* C = (yb < 4) ? g_feath : g_resh;
    int wc0 = (yb & 3) * 128;
#pragma unroll
    for (int mt = 0; mt < 4; mt++) {
        int r0 = row0 + wm + 16 * mt + gr;
        int r1 = r0 + 8;
#pragma unroll
        for (int nt = 0; nt < 4; nt++) {
            int col = wc0 + wn + nt * 8 + 2 * gc;
            if (r0 < Nn)
                *reinterpret_cast<__half2*>(C + (size_t)r0 * HDim + col) =
                    __floats2half2_rn(d[mt][nt][0], d[mt][nt][1]);
            if (r1 < Nn)
                *reinterpret_cast<__half2*>(C + (size_t)r1 * HDim + col) =
                    __floats2half2_rn(d[mt][nt][2], d[mt][nt][3]);
        }
    }

    // fused el/er for this block's head (yb<4): fp32 dot from accumulators
    if (yb < 4) {
        float* red_el = reinterpret_cast<float*>(smem);          // [4][128]
        float* red_er = reinterpret_cast<float*>(smem + 2048);   // [4][128]
        float alv[4][2], arv[4][2];
#pragma unroll
        for (int nt = 0; nt < 4; nt++) {
            int dim = wn + nt * 8 + 2 * gc;          // 0..127 within head
            alv[nt][0] = al[yb * 128 + dim];     alv[nt][1] = al[yb * 128 + dim + 1];
            arv[nt][0] = ar[yb * 128 + dim];     arv[nt][1] = ar[yb * 128 + dim + 1];
        }
#pragma unroll
        for (int mt = 0; mt < 4; mt++) {
            float sl0 = 0.f, sr0 = 0.f, sl1 = 0.f, sr1 = 0.f;
#pragma unroll
            for (int nt = 0; nt < 4; nt++) {
                sl0 += d[mt][nt][0] * alv[nt][0] + d[mt][nt][1] * alv[nt][1];
                sr0 += d[mt][nt][0] * arv[nt][0] + d[mt][nt][1] * arv[nt][1];
                sl1 += d[mt][nt][2] * alv[nt][0] + d[mt][nt][3] * alv[nt][1];
                sr1 += d[mt][nt][2] * arv[nt][0] + d[mt][nt][3] * arv[nt][1];
            }
#pragma unroll
            for (int o = 1; o < 4; o <<= 1) {
                sl0 += __shfl_xor_sync(0xffffffffu, sl0, o);
                sr0 += __shfl_xor_sync(0xffffffffu, sr0, o);
                sl1 += __shfl_xor_sync(0xffffffffu, sl1, o);
                sr1 += __shfl_xor_sync(0xffffffffu, sr1, o);
            }
            if (gc == 0) {
                int rb = wm + 16 * mt + gr;
                red_el[wnid * 128 + rb] = sl0;      red_el[wnid * 128 + rb + 8] = sl1;
                red_er[wnid * 128 + rb] = sr0;      red_er[wnid * 128 + rb + 8] = sr1;
            }
        }
        __syncthreads();
        if (gc == 0 && wnid == 0) {   // wid 0,1 cover all 128 rows
#pragma unroll
            for (int mt = 0; mt < 4; mt++) {
                int rb = wm + 16 * mt + gr;
#pragma unroll
                for (int q = 0; q < 2; q++) {
                    int rr = rb + 8 * q;
                    int node = row0 + rr;
                    if (node < Nn) {
                        float e = red_el[rr] + red_el[128 + rr] + red_el[256 + rr] + red_el[384 + rr];
                        float f = red_er[rr] + red_er[128 + rr] + red_er[256 + rr] + red_er[384 + rr];
                        g_el[node * 4 + yb] = e;
                        g_er[node * 4 + yb] = f;
                    }
                }
            }
        }
    }
}

// ============ GEMM2 + bias + LayerNorm: out = LN(h(fp16) @ Wn + bn) ============
// A fp16 single, B fp16 hi/lo -> 2 MMAs per tile. Non-last layers emit bf16 hi/lo x.
__global__ void __launch_bounds__(256) k_gemm2(int l, const float* __restrict__ bn,
                                               const float* __restrict__ gam,
                                               const float* __restrict__ bet,
                                               float* __restrict__ out, int last) {
    extern __shared__ char smem[];
    uint32_t sb = s2u(smem);
    int t = threadIdx.x, lane = t & 31, wid = t >> 5;
    int gr = lane >> 2, gc = lane & 3;
    int wm = (wid & 1) * 64, wnid = wid >> 1, wn = wnid * 32;
    int row0 = blockIdx.x * 128;

    float* par = reinterpret_cast<float*>(smem + O2_PAR);
    if (t < 128) { par[t] = bn[t]; par[128 + t] = gam[t]; par[256 + t] = bet[t]; }

    const __half* Wh = g_w2h + (size_t)l * 128 * 512;
    const __half* Wl = g_w2l + (size_t)l * 128 * 512;

    float d[4][4][4];
#pragma unroll
    for (int i = 0; i < 4; i++)
#pragma unroll
        for (int j = 0; j < 4; j++)
#pragma unroll
            for (int q = 0; q < 4; q++) d[i][j][q] = 0.f;

    int arow = (lane & 7) + ((lane >> 3) & 1) * 8;
    int akof = (lane >> 4) * 8;
    int bnr  = (lane & 7) + ((lane >> 4) << 3);
    int bkof = ((lane >> 3) & 1) * 8;

    for (int kc = 0; kc < 8; kc++) {
        int k0 = kc * 64;
#pragma unroll
        for (int u = 0; u < 4; u++) {
            int id = t + 256 * u;
            int r = id >> 3, c8 = (id & 7) * 8;
            int grow = row0 + r;
            uint4 v = make_uint4(0u, 0u, 0u, 0u);
            if (grow < Nn) v = *reinterpret_cast<const uint4*>(g_resh + (size_t)grow * HDim + k0 + c8);
            *reinterpret_cast<uint4*>(smem + (size_t)(r * 72 + c8) * 2) = v;
        }
#pragma unroll
        for (int u = 0; u < 4; u++) {
            int id = t + 256 * u;
            int r = id >> 3, c8 = (id & 7) * 8;
            char* pb = smem + O_ALOo + (size_t)(r * 72 + c8) * 2;
            *reinterpret_cast<uint4*>(pb) = *reinterpret_cast<const uint4*>(Wh + (size_t)r * 512 + k0 + c8);
            *reinterpret_cast<uint4*>(pb + 18432) = *reinterpret_cast<const uint4*>(Wl + (size_t)r * 512 + k0 + c8);
        }
        __syncthreads();
#pragma unroll
        for (int kt = 0; kt < 4; kt++) {
            uint32_t ah[4][4], bhf[2][4], blf[2][4];
#pragma unroll
            for (int mt = 0; mt < 4; mt++) {
                uint32_t ad = sb + 2u * ((wm + 16 * mt + arow) * 72 + 16 * kt + akof);
                LDSM4(ah[mt], ad);
            }
#pragma unroll
            for (int g = 0; g < 2; g++) {
                uint32_t bd = sb + O_ALOo + 2u * ((wn + 16 * g + bnr) * 72 + 16 * kt + bkof);
                LDSM4(bhf[g], bd);
                LDSM4(blf[g], bd + 18432);
            }
#pragma unroll
            for (int mt = 0; mt < 4; mt++)
#pragma unroll
                for (int nt = 0; nt < 4; nt++) {
                    uint32_t bh0 = bhf[nt >> 1][(nt & 1) * 2], bh1 = bhf[nt >> 1][(nt & 1) * 2 + 1];
                    uint32_t bl0 = blf[nt >> 1][(nt & 1) * 2], bl1 = blf[nt >> 1][(nt & 1) * 2 + 1];
                    mma_f16(d[mt][nt], ah[mt], bh0, bh1);
                    mma_f16(d[mt][nt], ah[mt], bl0, bl1);
                }
        }
        __syncthreads();
    }

    // ---- fused bias + LayerNorm epilogue ----
    float* red_s = reinterpret_cast<float*>(smem);          // 4 x 128
    float* red_q = reinterpret_cast<float*>(smem + 2048);   // 4 x 128
    float bnv[4][2];
#pragma unroll
    for (int nt = 0; nt < 4; nt++) {
        int col = wn + nt * 8 + 2 * gc;
        bnv[nt][0] = par[col]; bnv[nt][1] = par[col + 1];
    }
#pragma unroll
    for (int mt = 0; mt < 4; mt++) {
        float s0 = 0.f, q0 = 0.f, s1 = 0.f, q1 = 0.f;
#pragma unroll
        for (int nt = 0; nt < 4; nt++) {
            float y00 = d[mt][nt][0] + bnv[nt][0];
            float y01 = d[mt][nt][1] + bnv[nt][1];
            float y10 = d[mt][nt][2] + bnv[nt][0];
            float y11 = d[mt][nt][3] + bnv[nt][1];
            d[mt][nt][0] = y00; d[mt][nt][1] = y01;
            d[mt][nt][2] = y10; d[mt][nt][3] = y11;
            s0 += y00 + y01; q0 += y00 * y00 + y01 * y01;
            s1 += y10 + y11; q1 += y10 * y10 + y11 * y11;
        }
#pragma unroll
        for (int o = 1; o < 4; o <<= 1) {
            s0 += __shfl_xor_sync(0xffffffffu, s0, o);
            q0 += __shfl_xor_sync(0xffffffffu, q0, o);
            s1 += __shfl_xor_sync(0xffffffffu, s1, o);
            q1 += __shfl_xor_sync(0xffffffffu, q1, o);
        }
        if (gc == 0) {
            int rb = wm + 16 * mt + gr;
            red_s[wnid * 128 + rb] = s0; red_q[wnid * 128 + rb] = q0;
            red_s[wnid * 128 + rb + 8] = s1; red_q[wnid * 128 + rb + 8] = q1;
        }
    }
    __syncthreads();
#pragma unroll
    for (int mt = 0; mt < 4; mt++) {
        int rb = wm + 16 * mt + gr;
        float s0 = red_s[rb] + red_s[128 + rb] + red_s[256 + rb] + red_s[384 + rb];
        float q0 = red_q[rb] + red_q[128 + rb] + red_q[256 + rb] + red_q[384 + rb];
        float s1 = red_s[rb + 8] + red_s[128 + rb + 8] + red_s[256 + rb + 8] + red_s[384 + rb + 8];
        float q1 = red_q[rb + 8] + red_q[128 + rb + 8] + red_q[256 + rb + 8] + red_q[384 + rb + 8];
        float mu0 = s0 * (1.f / 128.f);
        float mu1 = s1 * (1.f / 128.f);
        float rstd0 = rsqrtf(q0 * (1.f / 128.f) - mu0 * mu0 + 1e-5f);
        float rstd1 = rsqrtf(q1 * (1.f / 128.f) - mu1 * mu1 + 1e-5f);
        int r0 = row0 + rb, r1 = r0 + 8;
#pragma unroll
        for (int nt = 0; nt < 4; nt++) {
            int col = wn + nt * 8 + 2 * gc;
            float g0 = par[128 + col], g1 = par[128 + col + 1];
            float b0 = par[256 + col], b1 = par[256 + col + 1];
            float v00 = (d[mt][nt][0] - mu0) * rstd0 * g0 + b0;
            float v01 = (d[mt][nt][1] - mu0) * rstd0 * g1 + b1;
            float v10 = (d[mt][nt][2] - mu1) * rstd1 * g0 + b0;
            float v11 = (d[mt][nt][3] - mu1) * rstd1 * g1 + b1;
            if (last) {
                if (r0 < Nn)
                    *reinterpret_cast<float2*>(out + (size_t)r0 * Dd + col) = make_float2(v00, v01);
                if (r1 < Nn)
                    *reinterpret_cast<float2*>(out + (size_t)r1 * Dd + col) = make_float2(v10, v11);
            } else {
                if (r0 < Nn) {
                    __nv_bfloat162 h, lo;
                    h.x = __float2bfloat16_rn(v00); h.y = __float2bfloat16_rn(v01);
                    lo.x = __float2bfloat16_rn(v00 - __bfloat162float(h.x));
                    lo.y = __float2bfloat16_rn(v01 - __bfloat162float(h.y));
                    *reinterpret_cast<__nv_bfloat162*>(g_xah + (size_t)r0 * Dd + col) = h;
                    *reinterpret_cast<__nv_bfloat162*>(g_xal + (size_t)r0 * Dd + col) = lo;
                }
                if (r1 < Nn) {
                    __nv_bfloat162 h, lo;
                    h.x = __float2bfloat16_rn(v10); h.y = __float2bfloat16_rn(v11);
                    lo.x = __float2bfloat16_rn(v10 - __bfloat162float(h.x));
                    lo.y = __float2bfloat16_rn(v11 - __bfloat162float(h.y));
                    *reinterpret_cast<__nv_bfloat162*>(g_xah + (size_t)r1 * Dd + col) = h;
                    *reinterpret_cast<__nv_bfloat162*>(g_xal + (size_t)r1 * Dd + col) = lo;
                }
            }
        }
    }
}

// ---------------- single-pass edge kernel ----------------
__global__ void k_edge(const int* __restrict__ src, const int* __restrict__ dst) {
    int e = blockIdx.x * blockDim.x + threadIdx.x;
    if (e >= Ee) return;
    int s = src[e], d = dst[e];
    float4 a = *reinterpret_cast<const float4*>(g_el + (size_t)s * 4);
    float4 b = *reinterpret_cast<const float4*>(g_er + (size_t)d * 4);
    float4 ev;
    ev.x = a.x + b.x; ev.x = ev.x > 0.f ? ev.x : NEG_ATTN * ev.x; ev.x = __expf(ev.x);
    ev.y = a.y + b.y; ev.y = ev.y > 0.f ? ev.y : NEG_ATTN * ev.y; ev.y = __expf(ev.y);
    ev.z = a.z + b.z; ev.z = ev.z > 0.f ? ev.z : NEG_ATTN * ev.z; ev.z = __expf(ev.z);
    ev.w = a.w + b.w; ev.w = ev.w > 0.f ? ev.w : NEG_ATTN * ev.w; ev.w = __expf(ev.w);
    int slot = g_slot[e];
    *reinterpret_cast<float4*>(g_ex + (size_t)slot * 4) = ev;
}

// ---------------- aggregation: one block (128 thr) per dst node; fp16 gather, fp16 res ----------------
__global__ void k_aggregate(const float* __restrict__ bgat) {
    int dn = blockIdx.x;
    int t = threadIdx.x;
    int h0 = t >> 6, h1 = 2 + (t >> 6);
    int s = g_off[dn], en = g_off[dn + 1];
    const __half2* feat2 = reinterpret_cast<const __half2*>(g_feath);
    float a00 = 0.f, a01 = 0.f, a10 = 0.f, a11 = 0.f;
    float z0 = 0.f, z1 = 0.f;
    int p = s;
    for (; p + 2 <= en; p += 2) {
        int sn0 = g_csr_src[p], sn1 = g_csr_src[p + 1];
        float4 e0 = *reinterpret_cast<const float4*>(g_ex + (size_t)p * 4);
        float4 e1 = *reinterpret_cast<const float4*>(g_ex + (size_t)(p + 1) * 4);
        const float* e0p = reinterpret_cast<const float*>(&e0);
        const float* e1p = reinterpret_cast<const float*>(&e1);
        float w00 = e0p[h0], w01 = e0p[h1];
        float w10 = e1p[h0], w11 = e1p[h1];
        float2 f00 = __half22float2(feat2[(size_t)sn0 * 256 + t]);
        float2 f01 = __half22float2(feat2[(size_t)sn0 * 256 + 128 + t]);
        float2 f10 = __half22float2(feat2[(size_t)sn1 * 256 + t]);
        float2 f11 = __half22float2(feat2[(size_t)sn1 * 256 + 128 + t]);
        a00 = fmaf(w00, f00.x, a00); a01 = fmaf(w00, f00.y, a01);
        a10 = fmaf(w01, f01.x, a10); a11 = fmaf(w01, f01.y, a11);
        a00 = fmaf(w10, f10.x, a00); a01 = fmaf(w10, f10.y, a01);
        a10 = fmaf(w11, f11.x, a10); a11 = fmaf(w11, f11.y, a11);
        z0 += w00 + w10; z1 += w01 + w11;
    }
    if (p < en) {
        int sn0 = g_csr_src[p];
        float4 e0 = *reinterpret_cast<const float4*>(g_ex + (size_t)p * 4);
        const float* e0p = reinterpret_cast<const float*>(&e0);
        float w00 = e0p[h0], w01 = e0p[h1];
        float2 f00 = __half22float2(feat2[(size_t)sn0 * 256 + t]);
        float2 f01 = __half22float2(feat2[(size_t)sn0 * 256 + 128 + t]);
        a00 = fmaf(w00, f00.x, a00); a01 = fmaf(w00, f00.y, a01);
        a10 = fmaf(w01, f01.x, a10); a11 = fmaf(w01, f01.y, a11);
        z0 += w00; z1 += w01;
    }
    float iz0 = 1.f / fmaxf(z0, 1e-20f);
    float iz1 = 1.f / fmaxf(z1, 1e-20f);
    __half2* res2 = reinterpret_cast<__half2*>(g_resh);
    size_t o2 = (size_t)dn * 256;
    int c0 = 2 * t, c1 = 256 + 2 * t;
    float2 rs0 = __half22float2(res2[o2 + t]);
    float2 rs1 = __half22float2(res2[o2 + 128 + t]);
    float2 bg0 = *reinterpret_cast<const float2*>(bgat + c0);
    float2 bg1 = *reinterpret_cast<const float2*>(bgat + c1);
    float r;
    float2 o0, o1;
    r = a00 * iz0 + rs0.x + bg0.x; o0.x = r > 0.f ? r : NEG_ACT * r;
    r = a01 * iz0 + rs0.y + bg0.y; o0.y = r > 0.f ? r : NEG_ACT * r;
    r = a10 * iz1 + rs1.x + bg1.x; o1.x = r > 0.f ? r : NEG_ACT * r;
    r = a11 * iz1 + rs1.y + bg1.y; o1.y = r > 0.f ? r : NEG_ACT * r;
    res2[o2 + t]       = __floats2half2_rn(o0.x, o0.y);
    res2[o2 + 128 + t] = __floats2half2_rn(o1.x, o1.y);
}

// ---------------- launch ----------------
extern "C" void kernel_launch(void* const* d_in, const int* in_sizes, int n_in,
                              void* d_out, int out_size) {
    const float* features = (const float*)d_in[0];
    const int*   src      = (const int*)  d_in[1];
    const int*   dst      = (const int*)  d_in[2];
    const float* W_fc     = (const float*)d_in[3];
    const float* attn_l   = (const float*)d_in[4];
    const float* attn_r   = (const float*)d_in[5];
    const float* W_res    = (const float*)d_in[6];
    const float* b_gat    = (const float*)d_in[7];
    const float* W_nrm    = (const float*)d_in[8];
    const float* b_nrm    = (const float*)d_in[9];
    const float* ln_g     = (const float*)d_in[10];
    const float* ln_b     = (const float*)d_in[11];
    float* out = (float*)d_out;

    cudaFuncSetAttribute(k_gemm1, cudaFuncAttributeMaxDynamicSharedMemorySize, SMEM_G1);
    cudaFuncSetAttribute(k_gemm2, cudaFuncAttributeMaxDynamicSharedMemorySize, SMEM_G2);

    k_zero_deg<<<(Nn + 255) / 256, 256>>>();
    k_hist<<<(Ee + 255) / 256, 256>>>(dst);
    k_scan<<<1, 1024>>>();
    k_scatter<<<(Ee + 255) / 256, 256>>>(src, dst);
    k_prep_w1<<<(4 * 1024 * 128 + 255) / 256, 256>>>(W_fc, W_res);
    k_prep_x<<<(Nn * Dd + 255) / 256, 256>>>(features);

    for (int l = 0; l < 4; l++) {
        const float* al  = attn_l + (size_t)l * Hh * Dd;
        const float* ar  = attn_r + (size_t)l * Hh * Dd;
        const float* bg  = b_gat + (size_t)l * HDim;
        const float* bnp = b_nrm + (size_t)l * Dd;
        const float* gp  = ln_g  + (size_t)l * Dd;
        const float* bp  = ln_b  + (size_t)l * Dd;

        k_gemm1<<<dim3((Nn + 127) / 128, 8), 256, SMEM_G1>>>(l, al, ar);
        if (l == 0) k_prep_w2<<<(4 * 128 * 512 + 255) / 256, 256>>>(W_nrm);
        k_edge<<<(Ee + 255) / 256, 256>>>(src, dst);
        k_aggregate<<<Nn, 128>>>(bg);

        k_gemm2<<<(Nn + 127) / 128, 256, SMEM_G2>>>(l, bnp, gp, bp, out, l == 3 ? 1 : 0);
    }
}

// round 13
// speedup vs baseline: 2.3195x; 1.0205x over previous
#include <cuda_runtime.h>
#include <cuda_bf16.h>
#include <cuda_fp16.h>
#include <math.h>
#include <float.h>
#include <stdint.h>

#define Nn 50000
#define Ee 800000
#define Hh 4
#define Dd 128
#define HDim 512
#define NEG_ATTN 0.2f
#define NEG_ACT 0.01f

// ---------------- scratch (static device allocations) ----------------
__device__ __half g_feath[(size_t)Nn * HDim];   // fp16 feat (gather source)
__device__ __half g_resh [(size_t)Nn * HDim];   // fp16 res / h (GEMM2 A operand)
__device__ __half g_xh   [(size_t)Nn * Dd];     // layer input x, fp16
__device__ float g_el  [Nn * Hh];
__device__ float g_er  [Nn * Hh];
__device__ float g_ex  [(size_t)Ee * Hh];
__device__ int   g_deg [Nn];
__device__ int   g_off [Nn + 1];
__device__ int   g_cur [Nn];
__device__ int   g_csr_src[Ee];
__device__ int   g_slot[Ee];

// pre-split transposed weights, [n][k] layout, fp16 hi/lo
__device__ __half g_w1h[4u * 1024 * 128];
__device__ __half g_w1l[4u * 1024 * 128];
__device__ __half g_w2h[4u * 128 * 512];
__device__ __half g_w2l[4u * 128 * 512];

// smem offsets (bytes): tiles of [128][72] 16-bit = 18432 each
// GEMM1: A(fp16) at 0, BHI at 18432, BLO at 36864
#define O_BHIo 18432
#define O_BLOo 36864
#define SMEM_G1 55296
// GEMM2: A(fp16) at 0, BHI at 18432, BLO at 36864, par at 55296
#define O2_PAR 55296
#define SMEM_G2 (55296 + 1536)

// ---------------- helpers ----------------
__device__ __forceinline__ uint32_t s2u(const void* p) {
    uint32_t a;
    asm("{ .reg .u64 t; cvta.to.shared.u64 t, %1; cvt.u32.u64 %0, t; }" : "=r"(a) : "l"(p));
    return a;
}

#define LDSM4(R, A) \
    asm volatile("ldmatrix.sync.aligned.m8n8.x4.shared.b16 {%0,%1,%2,%3}, [%4];" \
        : "=r"((R)[0]), "=r"((R)[1]), "=r"((R)[2]), "=r"((R)[3]) : "r"(A))

__device__ __forceinline__ void mma_f16(float d[4], const uint32_t a[4],
                                        uint32_t b0, uint32_t b1) {
    asm volatile(
        "mma.sync.aligned.m16n8k16.row.col.f32.f16.f16.f32 "
        "{%0,%1,%2,%3},{%4,%5,%6,%7},{%8,%9},{%0,%1,%2,%3};"
        : "+f"(d[0]), "+f"(d[1]), "+f"(d[2]), "+f"(d[3])
        : "r"(a[0]), "r"(a[1]), "r"(a[2]), "r"(a[3]), "r"(b0), "r"(b1));
}

// ---------------- weight / input prep ----------------
__global__ void k_prep_w1(const float* __restrict__ Wfc, const float* __restrict__ Wres) {
    int id = blockIdx.x * 256 + threadIdx.x;
    if (id >= 4 * 1024 * 128) return;
    int k = id & 127, n = (id >> 7) & 1023, l = id >> 17;
    float v = (n < 512) ? Wfc[((size_t)l * 128 + k) * 512 + n]
                        : Wres[((size_t)l * 128 + k) * 512 + (n - 512)];
    __half h = __float2half_rn(v);
    g_w1h[id] = h;
    g_w1l[id] = __float2half_rn(v - __half2float(h));
}

__global__ void k_prep_w2(const float* __restrict__ Wn) {
    int id = blockIdx.x * 256 + threadIdx.x;
    if (id >= 4 * 128 * 512) return;
    int k = id & 511, n = (id >> 9) & 127, l = id >> 16;
    float v = Wn[((size_t)l * 512 + k) * 128 + n];
    __half h = __float2half_rn(v);
    g_w2h[id] = h;
    g_w2l[id] = __float2half_rn(v - __half2float(h));
}

__global__ void k_prep_x(const float* __restrict__ X) {
    int id = blockIdx.x * 256 + threadIdx.x;
    if (id >= Nn * Dd) return;
    g_xh[id] = __float2half_rn(X[id]);
}

// ---------------- CSR build ----------------
__global__ void k_zero_deg() {
    int i = blockIdx.x * blockDim.x + threadIdx.x;
    if (i < Nn) g_deg[i] = 0;
}
__global__ void k_hist(const int* __restrict__ dst) {
    int i = blockIdx.x * blockDim.x + threadIdx.x;
    if (i < Ee) atomicAdd(&g_deg[dst[i]], 1);
}
__global__ void k_scan() {
    __shared__ int sbuf[1024];
    __shared__ int carry;
    int t = threadIdx.x;
    if (t == 0) carry = 0;
    __syncthreads();
    for (int base = 0; base < Nn; base += 1024) {
        int i = base + t;
        int v = (i < Nn) ? g_deg[i] : 0;
        sbuf[t] = v;
        __syncthreads();
        for (int off = 1; off < 1024; off <<= 1) {
            int add = (t >= off) ? sbuf[t - off] : 0;
            __syncthreads();
            sbuf[t] += add;
            __syncthreads();
        }
        int incl = sbuf[t];
        int excl = carry + incl - v;
        if (i < Nn) { g_off[i] = excl; g_cur[i] = excl; }
        int total = sbuf[1023];
        __syncthreads();
        if (t == 0) carry += total;
        __syncthreads();
    }
    if (t == 0) g_off[Nn] = carry;
}
__global__ void k_scatter(const int* __restrict__ src, const int* __restrict__ dst) {
    int i = blockIdx.x * blockDim.x + threadIdx.x;
    if (i < Ee) {
        int d = dst[i];
        int p = atomicAdd(&g_cur[d], 1);
        g_csr_src[p] = src[i];
        g_slot[i] = p;
    }
}

// ============ GEMM1: [feat|res] = x(fp16) @ W1(fp16 hi/lo) ; fused el/er for yb<4 ============
// 2 MMAs per tile.
__global__ void __launch_bounds__(256) k_gemm1(int l, const float* __restrict__ al,
                                               const float* __restrict__ ar) {
    extern __shared__ char smem[];
    uint32_t sb = s2u(smem);
    int t = threadIdx.x, lane = t & 31, wid = t >> 5;
    int gr = lane >> 2, gc = lane & 3;
    int wm = (wid & 1) * 64, wnid = wid >> 1, wn = wnid * 32;
    int row0 = blockIdx.x * 128;
    int yb = blockIdx.y;

    const __half* Wh = g_w1h + ((size_t)l * 1024 + (size_t)yb * 128) * 128;
    const __half* Wl = g_w1l + ((size_t)l * 1024 + (size_t)yb * 128) * 128;

    float d[4][4][4];
#pragma unroll
    for (int i = 0; i < 4; i++)
#pragma unroll
        for (int j = 0; j < 4; j++)
#pragma unroll
            for (int q = 0; q < 4; q++) d[i][j][q] = 0.f;

    int arow = (lane & 7) + ((lane >> 3) & 1) * 8;
    int akof = (lane >> 4) * 8;
    int bnr  = (lane & 7) + ((lane >> 4) << 3);
    int bkof = ((lane >> 3) & 1) * 8;

#pragma unroll
    for (int kc = 0; kc < 2; kc++) {
        int k0 = kc * 64;
        // A: 128 rows x 64 fp16 — straight vector copy
#pragma unroll
        for (int u = 0; u < 4; u++) {
            int id = t + 256 * u;
            int r = id >> 3, c8 = (id & 7) * 8;
            int grow = row0 + r;
            uint4 v = make_uint4(0u, 0u, 0u, 0u);
            if (grow < Nn) v = *reinterpret_cast<const uint4*>(g_xh + (size_t)grow * Dd + k0 + c8);
            *reinterpret_cast<uint4*>(smem + (size_t)(r * 72 + c8) * 2) = v;
        }
        // B: 128 n-rows x 64 fp16 hi/lo
#pragma unroll
        for (int u = 0; u < 4; u++) {
            int id = t + 256 * u;
            int r = id >> 3, c8 = (id & 7) * 8;
            char* pb = smem + O_BHIo + (size_t)(r * 72 + c8) * 2;
            *reinterpret_cast<uint4*>(pb) = *reinterpret_cast<const uint4*>(Wh + (size_t)r * 128 + k0 + c8);
            *reinterpret_cast<uint4*>(pb + (O_BLOo - O_BHIo)) = *reinterpret_cast<const uint4*>(Wl + (size_t)r * 128 + k0 + c8);
        }
        __syncthreads();
#pragma unroll
        for (int kt = 0; kt < 4; kt++) {
            uint32_t ah[4][4], bhf[2][4], blf[2][4];
#pragma unroll
            for (int mt = 0; mt < 4; mt++) {
                uint32_t ad = sb + 2u * ((wm + 16 * mt + arow) * 72 + 16 * kt + akof);
                LDSM4(ah[mt], ad);
            }
#pragma unroll
            for (int g = 0; g < 2; g++) {
                uint32_t bd = sb + O_BHIo + 2u * ((wn + 16 * g + bnr) * 72 + 16 * kt + bkof);
                LDSM4(bhf[g], bd);
                LDSM4(blf[g], bd + (O_BLOo - O_BHIo));
            }
#pragma unroll
            for (int mt = 0; mt < 4; mt++)
#pragma unroll
                for (int nt = 0; nt < 4; nt++) {
                    uint32_t bh0 = bhf[nt >> 1][(nt & 1) * 2], bh1 = bhf[nt >> 1][(nt & 1) * 2 + 1];
                    uint32_t bl0 = blf[nt >> 1][(nt & 1) * 2], bl1 = blf[nt >> 1][(nt & 1) * 2 + 1];
                    mma_f16(d[mt][nt], ah[mt], bh0, bh1);
                    mma_f16(d[mt][nt], ah[mt], bl0, bl1);
                }
        }
        __syncthreads();
    }

    // fp16 store (feat for yb<4, res for yb>=4)
    __half* C = (yb < 4) ? g_feath : g_resh;
    int wc0 = (yb & 3) * 128;
#pragma unroll
    for (int mt = 0; mt < 4; mt++) {
        int r0 = row0 + wm + 16 * mt + gr;
        int r1 = r0 + 8;
#pragma unroll
        for (int nt = 0; nt < 4; nt++) {
            int col = wc0 + wn + nt * 8 + 2 * gc;
            if (r0 < Nn)
                *reinterpret_cast<__half2*>(C + (size_t)r0 * HDim + col) =
                    __floats2half2_rn(d[mt][nt][0], d[mt][nt][1]);
            if (r1 < Nn)
                *reinterpret_cast<__half2*>(C + (size_t)r1 * HDim + col) =
                    __floats2half2_rn(d[mt][nt][2], d[mt][nt][3]);
        }
    }

    // fused el/er for this block's head (yb<4): fp32 dot from accumulators
    if (yb < 4) {
        float* red_el = reinterpret_cast<float*>(smem);          // [4][128]
        float* red_er = reinterpret_cast<float*>(smem + 2048);   // [4][128]
        float alv[4][2], arv[4][2];
#pragma unroll
        for (int nt = 0; nt < 4; nt++) {
            int dim = wn + nt * 8 + 2 * gc;
            alv[nt][0] = al[yb * 128 + dim];     alv[nt][1] = al[yb * 128 + dim + 1];
            arv[nt][0] = ar[yb * 128 + dim];     arv[nt][1] = ar[yb * 128 + dim + 1];
        }
#pragma unroll
        for (int mt = 0; mt < 4; mt++) {
            float sl0 = 0.f, sr0 = 0.f, sl1 = 0.f, sr1 = 0.f;
#pragma unroll
            for (int nt = 0; nt < 4; nt++) {
                sl0 += d[mt][nt][0] * alv[nt][0] + d[mt][nt][1] * alv[nt][1];
                sr0 += d[mt][nt][0] * arv[nt][0] + d[mt][nt][1] * arv[nt][1];
                sl1 += d[mt][nt][2] * alv[nt][0] + d[mt][nt][3] * alv[nt][1];
                sr1 += d[mt][nt][2] * arv[nt][0] + d[mt][nt][3] * arv[nt][1];
            }
#pragma unroll
            for (int o = 1; o < 4; o <<= 1) {
                sl0 += __shfl_xor_sync(0xffffffffu, sl0, o);
                sr0 += __shfl_xor_sync(0xffffffffu, sr0, o);
                sl1 += __shfl_xor_sync(0xffffffffu, sl1, o);
                sr1 += __shfl_xor_sync(0xffffffffu, sr1, o);
            }
            if (gc == 0) {
                int rb = wm + 16 * mt + gr;
                red_el[wnid * 128 + rb] = sl0;      red_el[wnid * 128 + rb + 8] = sl1;
                red_er[wnid * 128 + rb] = sr0;      red_er[wnid * 128 + rb + 8] = sr1;
            }
        }
        __syncthreads();
        if (gc == 0 && wnid == 0) {
#pragma unroll
            for (int mt = 0; mt < 4; mt++) {
                int rb = wm + 16 * mt + gr;
#pragma unroll
                for (int q = 0; q < 2; q++) {
                    int rr = rb + 8 * q;
                    int node = row0 + rr;
                    if (node < Nn) {
                        float e = red_el[rr] + red_el[128 + rr] + red_el[256 + rr] + red_el[384 + rr];
                        float f = red_er[rr] + red_er[128 + rr] + red_er[256 + rr] + red_er[384 + rr];
                        g_el[node * 4 + yb] = e;
                        g_er[node * 4 + yb] = f;
                    }
                }
            }
        }
    }
}

// ============ GEMM2 + bias + LayerNorm: out = LN(h(fp16) @ Wn + bn) ============
__global__ void __launch_bounds__(256) k_gemm2(int l, const float* __restrict__ bn,
                                               const float* __restrict__ gam,
                                               const float* __restrict__ bet,
                                               float* __restrict__ out, int last) {
    extern __shared__ char smem[];
    uint32_t sb = s2u(smem);
    int t = threadIdx.x, lane = t & 31, wid = t >> 5;
    int gr = lane >> 2, gc = lane & 3;
    int wm = (wid & 1) * 64, wnid = wid >> 1, wn = wnid * 32;
    int row0 = blockIdx.x * 128;

    float* par = reinterpret_cast<float*>(smem + O2_PAR);
    if (t < 128) { par[t] = bn[t]; par[128 + t] = gam[t]; par[256 + t] = bet[t]; }

    const __half* Wh = g_w2h + (size_t)l * 128 * 512;
    const __half* Wl = g_w2l + (size_t)l * 128 * 512;

    float d[4][4][4];
#pragma unroll
    for (int i = 0; i < 4; i++)
#pragma unroll
        for (int j = 0; j < 4; j++)
#pragma unroll
            for (int q = 0; q < 4; q++) d[i][j][q] = 0.f;

    int arow = (lane & 7) + ((lane >> 3) & 1) * 8;
    int akof = (lane >> 4) * 8;
    int bnr  = (lane & 7) + ((lane >> 4) << 3);
    int bkof = ((lane >> 3) & 1) * 8;

    for (int kc = 0; kc < 8; kc++) {
        int k0 = kc * 64;
#pragma unroll
        for (int u = 0; u < 4; u++) {
            int id = t + 256 * u;
            int r = id >> 3, c8 = (id & 7) * 8;
            int grow = row0 + r;
            uint4 v = make_uint4(0u, 0u, 0u, 0u);
            if (grow < Nn) v = *reinterpret_cast<const uint4*>(g_resh + (size_t)grow * HDim + k0 + c8);
            *reinterpret_cast<uint4*>(smem + (size_t)(r * 72 + c8) * 2) = v;
        }
#pragma unroll
        for (int u = 0; u < 4; u++) {
            int id = t + 256 * u;
            int r = id >> 3, c8 = (id & 7) * 8;
            char* pb = smem + O_BHIo + (size_t)(r * 72 + c8) * 2;
            *reinterpret_cast<uint4*>(pb) = *reinterpret_cast<const uint4*>(Wh + (size_t)r * 512 + k0 + c8);
            *reinterpret_cast<uint4*>(pb + (O_BLOo - O_BHIo)) = *reinterpret_cast<const uint4*>(Wl + (size_t)r * 512 + k0 + c8);
        }
        __syncthreads();
#pragma unroll
        for (int kt = 0; kt < 4; kt++) {
            uint32_t ah[4][4], bhf[2][4], blf[2][4];
#pragma unroll
            for (int mt = 0; mt < 4; mt++) {
                uint32_t ad = sb + 2u * ((wm + 16 * mt + arow) * 72 + 16 * kt + akof);
                LDSM4(ah[mt], ad);
            }
#pragma unroll
            for (int g = 0; g < 2; g++) {
                uint32_t bd = sb + O_BHIo + 2u * ((wn + 16 * g + bnr) * 72 + 16 * kt + bkof);
                LDSM4(bhf[g], bd);
                LDSM4(blf[g], bd + (O_BLOo - O_BHIo));
            }
#pragma unroll
            for (int mt = 0; mt < 4; mt++)
#pragma unroll
                for (int nt = 0; nt < 4; nt++) {
                    uint32_t bh0 = bhf[nt >> 1][(nt & 1) * 2], bh1 = bhf[nt >> 1][(nt & 1) * 2 + 1];
                    uint32_t bl0 = blf[nt >> 1][(nt & 1) * 2], bl1 = blf[nt >> 1][(nt & 1) * 2 + 1];
                    mma_f16(d[mt][nt], ah[mt], bh0, bh1);
                    mma_f16(d[mt][nt], ah[mt], bl0, bl1);
                }
        }
        __syncthreads();
    }

    // ---- fused bias + LayerNorm epilogue ----
    float* red_s = reinterpret_cast<float*>(smem);          // 4 x 128
    float* red_q = reinterpret_cast<float*>(smem + 2048);   // 4 x 128
    float bnv[4][2];
#pragma unroll
    for (int nt = 0; nt < 4; nt++) {
        int col = wn + nt * 8 + 2 * gc;
        bnv[nt][0] = par[col]; bnv[nt][1] = par[col + 1];
    }
#pragma unroll
    for (int mt = 0; mt < 4; mt++) {
        float s0 = 0.f, q0 = 0.f, s1 = 0.f, q1 = 0.f;
#pragma unroll
        for (int nt = 0; nt < 4; nt++) {
            float y00 = d[mt][nt][0] + bnv[nt][0];
            float y01 = d[mt][nt][1] + bnv[nt][1];
            float y10 = d[mt][nt][2] + bnv[nt][0];
            float y11 = d[mt][nt][3] + bnv[nt][1];
            d[mt][nt][0] = y00; d[mt][nt][1] = y01;
            d[mt][nt][2] = y10; d[mt][nt][3] = y11;
            s0 += y00 + y01; q0 += y00 * y00 + y01 * y01;
            s1 += y10 + y11; q1 += y10 * y10 + y11 * y11;
        }
#pragma unroll
        for (int o = 1; o < 4; o <<= 1) {
            s0 += __shfl_xor_sync(0xffffffffu, s0, o);
            q0 += __shfl_xor_sync(0xffffffffu, q0, o);
            s1 += __shfl_xor_sync(0xffffffffu, s1, o);
            q1 += __shfl_xor_sync(0xffffffffu, q1, o);
        }
        if (gc == 0) {
            int rb = wm + 16 * mt + gr;
            red_s[wnid * 128 + rb] = s0; red_q[wnid * 128 + rb] = q0;
            red_s[wnid * 128 + rb + 8] = s1; red_q[wnid * 128 + rb + 8] = q1;
        }
    }
    __syncthreads();
#pragma unroll
    for (int mt = 0; mt < 4; mt++) {
        int rb = wm + 16 * mt + gr;
        float s0 = red_s[rb] + red_s[128 + rb] + red_s[256 + rb] + red_s[384 + rb];
        float q0 = red_q[rb] + red_q[128 + rb] + red_q[256 + rb] + red_q[384 + rb];
        float s1 = red_s[rb + 8] + red_s[128 + rb + 8] + red_s[256 + rb + 8] + red_s[384 + rb + 8];
        float q1 = red_q[rb + 8] + red_q[128 + rb + 8] + red_q[256 + rb + 8] + red_q[384 + rb + 8];
        float mu0 = s0 * (1.f / 128.f);
        float mu1 = s1 * (1.f / 128.f);
        float rstd0 = rsqrtf(q0 * (1.f / 128.f) - mu0 * mu0 + 1e-5f);
        float rstd1 = rsqrtf(q1 * (1.f / 128.f) - mu1 * mu1 + 1e-5f);
        int r0 = row0 + rb, r1 = r0 + 8;
#pragma unroll
        for (int nt = 0; nt < 4; nt++) {
            int col = wn + nt * 8 + 2 * gc;
            float g0 = par[128 + col], g1 = par[128 + col + 1];
            float b0 = par[256 + col], b1 = par[256 + col + 1];
            float v00 = (d[mt][nt][0] - mu0) * rstd0 * g0 + b0;
            float v01 = (d[mt][nt][1] - mu0) * rstd0 * g1 + b1;
            float v10 = (d[mt][nt][2] - mu1) * rstd1 * g0 + b0;
            float v11 = (d[mt][nt][3] - mu1) * rstd1 * g1 + b1;
            if (last) {
                if (r0 < Nn)
                    *reinterpret_cast<float2*>(out + (size_t)r0 * Dd + col) = make_float2(v00, v01);
                if (r1 < Nn)
                    *reinterpret_cast<float2*>(out + (size_t)r1 * Dd + col) = make_float2(v10, v11);
            } else {
                if (r0 < Nn)
                    *reinterpret_cast<__half2*>(g_xh + (size_t)r0 * Dd + col) = __floats2half2_rn(v00, v01);
                if (r1 < Nn)
                    *reinterpret_cast<__half2*>(g_xh + (size_t)r1 * Dd + col) = __floats2half2_rn(v10, v11);
            }
        }
    }
}

// ---------------- single-pass edge kernel ----------------
__global__ void k_edge(const int* __restrict__ src, const int* __restrict__ dst) {
    int e = blockIdx.x * blockDim.x + threadIdx.x;
    if (e >= Ee) return;
    int s = src[e], d = dst[e];
    float4 a = *reinterpret_cast<const float4*>(g_el + (size_t)s * 4);
    float4 b = *reinterpret_cast<const float4*>(g_er + (size_t)d * 4);
    float4 ev;
    ev.x = a.x + b.x; ev.x = ev.x > 0.f ? ev.x : NEG_ATTN * ev.x; ev.x = __expf(ev.x);
    ev.y = a.y + b.y; ev.y = ev.y > 0.f ? ev.y : NEG_ATTN * ev.y; ev.y = __expf(ev.y);
    ev.z = a.z + b.z; ev.z = ev.z > 0.f ? ev.z : NEG_ATTN * ev.z; ev.z = __expf(ev.z);
    ev.w = a.w + b.w; ev.w = ev.w > 0.f ? ev.w : NEG_ATTN * ev.w; ev.w = __expf(ev.w);
    int slot = g_slot[e];
    *reinterpret_cast<float4*>(g_ex + (size_t)slot * 4) = ev;
}

// ---------------- aggregation: one block (128 thr) per dst node; fp16 gather, fp16 res ----------------
__global__ void k_aggregate(const float* __restrict__ bgat) {
    int dn = blockIdx.x;
    int t = threadIdx.x;
    int h0 = t >> 6, h1 = 2 + (t >> 6);
    int s = g_off[dn], en = g_off[dn + 1];
    const __half2* feat2 = reinterpret_cast<const __half2*>(g_feath);
    float a00 = 0.f, a01 = 0.f, a10 = 0.f, a11 = 0.f;
    float z0 = 0.f, z1 = 0.f;
    int p = s;
    for (; p + 2 <= en; p += 2) {
        int sn0 = g_csr_src[p], sn1 = g_csr_src[p + 1];
        float4 e0 = *reinterpret_cast<const float4*>(g_ex + (size_t)p * 4);
        float4 e1 = *reinterpret_cast<const float4*>(g_ex + (size_t)(p + 1) * 4);
        const float* e0p = reinterpret_cast<const float*>(&e0);
        const float* e1p = reinterpret_cast<const float*>(&e1);
        float w00 = e0p[h0], w01 = e0p[h1];
        float w10 = e1p[h0], w11 = e1p[h1];
        float2 f00 = __half22float2(feat2[(size_t)sn0 * 256 + t]);
        float2 f01 = __half22float2(feat2[(size_t)sn0 * 256 + 128 + t]);
        float2 f10 = __half22float2(feat2[(size_t)sn1 * 256 + t]);
        float2 f11 = __half22float2(feat2[(size_t)sn1 * 256 + 128 + t]);
        a00 = fmaf(w00, f00.x, a00); a01 = fmaf(w00, f00.y, a01);
        a10 = fmaf(w01, f01.x, a10); a11 = fmaf(w01, f01.y, a11);
        a00 = fmaf(w10, f10.x, a00); a01 = fmaf(w10, f10.y, a01);
        a10 = fmaf(w11, f11.x, a10); a11 = fmaf(w11, f11.y, a11);
        z0 += w00 + w10; z1 += w01 + w11;
    }
    if (p < en) {
        int sn0 = g_csr_src[p];
        float4 e0 = *reinterpret_cast<const float4*>(g_ex + (size_t)p * 4);
        const float* e0p = reinterpret_cast<const float*>(&e0);
        float w00 = e0p[h0], w01 = e0p[h1];
        float2 f00 = __half22float2(feat2[(size_t)sn0 * 256 + t]);
        float2 f01 = __half22float2(feat2[(size_t)sn0 * 256 + 128 + t]);
        a00 = fmaf(w00, f00.x, a00); a01 = fmaf(w00, f00.y, a01);
        a10 = fmaf(w01, f01.x, a10); a11 = fmaf(w01, f01.y, a11);
        z0 += w00; z1 += w01;
    }
    float iz0 = 1.f / fmaxf(z0, 1e-20f);
    float iz1 = 1.f / fmaxf(z1, 1e-20f);
    __half2* res2 = reinterpret_cast<__half2*>(g_resh);
    size_t o2 = (size_t)dn * 256;
    int c0 = 2 * t, c1 = 256 + 2 * t;
    float2 rs0 = __half22float2(res2[o2 + t]);
    float2 rs1 = __half22float2(res2[o2 + 128 + t]);
    float2 bg0 = *reinterpret_cast<const float2*>(bgat + c0);
    float2 bg1 = *reinterpret_cast<const float2*>(bgat + c1);
    float r;
    float2 o0, o1;
    r = a00 * iz0 + rs0.x + bg0.x; o0.x = r > 0.f ? r : NEG_ACT * r;
    r = a01 * iz0 + rs0.y + bg0.y; o0.y = r > 0.f ? r : NEG_ACT * r;
    r = a10 * iz1 + rs1.x + bg1.x; o1.x = r > 0.f ? r : NEG_ACT * r;
    r = a11 * iz1 + rs1.y + bg1.y; o1.y = r > 0.f ? r : NEG_ACT * r;
    res2[o2 + t]       = __floats2half2_rn(o0.x, o0.y);
    res2[o2 + 128 + t] = __floats2half2_rn(o1.x, o1.y);
}

// ---------------- launch ----------------
extern "C" void kernel_launch(void* const* d_in, const int* in_sizes, int n_in,
                              void* d_out, int out_size) {
    const float* features = (const float*)d_in[0];
    const int*   src      = (const int*)  d_in[1];
    const int*   dst      = (const int*)  d_in[2];
    const float* W_fc     = (const float*)d_in[3];
    const float* attn_l   = (const float*)d_in[4];
    const float* attn_r   = (const float*)d_in[5];
    const float* W_res    = (const float*)d_in[6];
    const float* b_gat    = (const float*)d_in[7];
    const float* W_nrm    = (const float*)d_in[8];
    const float* b_nrm    = (const float*)d_in[9];
    const float* ln_g     = (const float*)d_in[10];
    const float* ln_b     = (const float*)d_in[11];
    float* out = (float*)d_out;

    cudaFuncSetAttribute(k_gemm1, cudaFuncAttributeMaxDynamicSharedMemorySize, SMEM_G1);
    cudaFuncSetAttribute(k_gemm2, cudaFuncAttributeMaxDynamicSharedMemorySize, SMEM_G2);

    k_zero_deg<<<(Nn + 255) / 256, 256>>>();
    k_hist<<<(Ee + 255) / 256, 256>>>(dst);
    k_scan<<<1, 1024>>>();
    k_scatter<<<(Ee + 255) / 256, 256>>>(src, dst);
    k_prep_w1<<<(4 * 1024 * 128 + 255) / 256, 256>>>(W_fc, W_res);
    k_prep_x<<<(Nn * Dd + 255) / 256, 256>>>(features);

    for (int l = 0; l < 4; l++) {
        const float* al  = attn_l + (size_t)l * Hh * Dd;
        const float* ar  = attn_r + (size_t)l * Hh * Dd;
        const float* bg  = b_gat + (size_t)l * HDim;
        const float* bnp = b_nrm + (size_t)l * Dd;
        const float* gp  = ln_g  + (size_t)l * Dd;
        const float* bp  = ln_b  + (size_t)l * Dd;

        k_gemm1<<<dim3((Nn + 127) / 128, 8), 256, SMEM_G1>>>(l, al, ar);
        if (l == 0) k_prep_w2<<<(4 * 128 * 512 + 255) / 256, 256>>>(W_nrm);
        k_edge<<<(Ee + 255) / 256, 256>>>(src, dst);
        k_aggregate<<<Nn, 128>>>(bg);

        k_gemm2<<<(Nn + 127) / 128, 256, SMEM_G2>>>(l, bnp, gp, bp, out, l == 3 ? 1 : 0);
    }
}

// round 14
// speedup vs baseline: 3.0277x; 1.3053x over previous
#include <cuda_runtime.h>
#include <cuda_bf16.h>
#include <cuda_fp16.h>
#include <math.h>
#include <float.h>
#include <stdint.h>

#define Nn 50000
#define Ee 800000
#define Hh 4
#define Dd 128
#define HDim 512
#define NEG_ATTN 0.2f
#define NEG_ACT 0.01f

// ---------------- scratch (static device allocations) ----------------
__device__ __half g_feath[(size_t)Nn * HDim];   // fp16 feat (gather source)
__device__ __half g_resh [(size_t)Nn * HDim];   // fp16 res / h (GEMM2 A operand)
__device__ __half g_xh   [(size_t)Nn * Dd];     // layer input x, fp16
__device__ float g_el  [Nn * Hh];
__device__ float g_er  [Nn * Hh];
__device__ int   g_deg [Nn];
__device__ int   g_off [Nn + 1];
__device__ int   g_cur [Nn];
__device__ int   g_csr_src[Ee];

// pre-split transposed weights, [n][k] layout, fp16 hi/lo
__device__ __half g_w1h[4u * 1024 * 128];
__device__ __half g_w1l[4u * 1024 * 128];
__device__ __half g_w2h[4u * 128 * 512];
__device__ __half g_w2l[4u * 128 * 512];

// smem offsets (bytes): tiles of [128][72] 16-bit = 18432 each
#define O_BHIo 18432
#define O_BLOo 36864
#define SMEM_G1 55296
#define O2_PAR 55296
#define SMEM_G2 (55296 + 1536)

// ---------------- helpers ----------------
__device__ __forceinline__ uint32_t s2u(const void* p) {
    uint32_t a;
    asm("{ .reg .u64 t; cvta.to.shared.u64 t, %1; cvt.u32.u64 %0, t; }" : "=r"(a) : "l"(p));
    return a;
}

#define LDSM4(R, A) \
    asm volatile("ldmatrix.sync.aligned.m8n8.x4.shared.b16 {%0,%1,%2,%3}, [%4];" \
        : "=r"((R)[0]), "=r"((R)[1]), "=r"((R)[2]), "=r"((R)[3]) : "r"(A))

__device__ __forceinline__ void mma_f16(float d[4], const uint32_t a[4],
                                        uint32_t b0, uint32_t b1) {
    asm volatile(
        "mma.sync.aligned.m16n8k16.row.col.f32.f16.f16.f32 "
        "{%0,%1,%2,%3},{%4,%5,%6,%7},{%8,%9},{%0,%1,%2,%3};"
        : "+f"(d[0]), "+f"(d[1]), "+f"(d[2]), "+f"(d[3])
        : "r"(a[0]), "r"(a[1]), "r"(a[2]), "r"(a[3]), "r"(b0), "r"(b1));
}

// ---------------- weight / input prep ----------------
__global__ void k_prep_w1(const float* __restrict__ Wfc, const float* __restrict__ Wres) {
    int id = blockIdx.x * 256 + threadIdx.x;
    if (id >= 4 * 1024 * 128) return;
    int k = id & 127, n = (id >> 7) & 1023, l = id >> 17;
    float v = (n < 512) ? Wfc[((size_t)l * 128 + k) * 512 + n]
                        : Wres[((size_t)l * 128 + k) * 512 + (n - 512)];
    __half h = __float2half_rn(v);
    g_w1h[id] = h;
    g_w1l[id] = __float2half_rn(v - __half2float(h));
}

__global__ void k_prep_w2(const float* __restrict__ Wn) {
    int id = blockIdx.x * 256 + threadIdx.x;
    if (id >= 4 * 128 * 512) return;
    int k = id & 511, n = (id >> 9) & 127, l = id >> 16;
    float v = Wn[((size_t)l * 512 + k) * 128 + n];
    __half h = __float2half_rn(v);
    g_w2h[id] = h;
    g_w2l[id] = __float2half_rn(v - __half2float(h));
}

__global__ void k_prep_x(const float* __restrict__ X) {
    int id = blockIdx.x * 256 + threadIdx.x;
    if (id >= Nn * Dd) return;
    g_xh[id] = __float2half_rn(X[id]);
}

// ---------------- CSR build ----------------
__global__ void k_zero_deg() {
    int i = blockIdx.x * blockDim.x + threadIdx.x;
    if (i < Nn) g_deg[i] = 0;
}
__global__ void k_hist(const int* __restrict__ dst) {
    int i = blockIdx.x * blockDim.x + threadIdx.x;
    if (i < Ee) atomicAdd(&g_deg[dst[i]], 1);
}
__global__ void k_scan() {
    __shared__ int sbuf[1024];
    __shared__ int carry;
    int t = threadIdx.x;
    if (t == 0) carry = 0;
    __syncthreads();
    for (int base = 0; base < Nn; base += 1024) {
        int i = base + t;
        int v = (i < Nn) ? g_deg[i] : 0;
        sbuf[t] = v;
        __syncthreads();
        for (int off = 1; off < 1024; off <<= 1) {
            int add = (t >= off) ? sbuf[t - off] : 0;
            __syncthreads();
            sbuf[t] += add;
            __syncthreads();
        }
        int incl = sbuf[t];
        int excl = carry + incl - v;
        if (i < Nn) { g_off[i] = excl; g_cur[i] = excl; }
        int total = sbuf[1023];
        __syncthreads();
        if (t == 0) carry += total;
        __syncthreads();
    }
    if (t == 0) g_off[Nn] = carry;
}
__global__ void k_scatter(const int* __restrict__ src, const int* __restrict__ dst) {
    int i = blockIdx.x * blockDim.x + threadIdx.x;
    if (i < Ee) {
        int d = dst[i];
        int p = atomicAdd(&g_cur[d], 1);
        g_csr_src[p] = src[i];
    }
}

// ============ GEMM1: [feat|res] = x(fp16) @ W1(fp16 hi/lo) ; fused el/er for yb<4 ============
__global__ void __launch_bounds__(256) k_gemm1(int l, const float* __restrict__ al,
                                               const float* __restrict__ ar) {
    extern __shared__ char smem[];
    uint32_t sb = s2u(smem);
    int t = threadIdx.x, lane = t & 31, wid = t >> 5;
    int gr = lane >> 2, gc = lane & 3;
    int wm = (wid & 1) * 64, wnid = wid >> 1, wn = wnid * 32;
    int row0 = blockIdx.x * 128;
    int yb = blockIdx.y;

    const __half* Wh = g_w1h + ((size_t)l * 1024 + (size_t)yb * 128) * 128;
    const __half* Wl = g_w1l + ((size_t)l * 1024 + (size_t)yb * 128) * 128;

    float d[4][4][4];
#pragma unroll
    for (int i = 0; i < 4; i++)
#pragma unroll
        for (int j = 0; j < 4; j++)
#pragma unroll
            for (int q = 0; q < 4; q++) d[i][j][q] = 0.f;

    int arow = (lane & 7) + ((lane >> 3) & 1) * 8;
    int akof = (lane >> 4) * 8;
    int bnr  = (lane & 7) + ((lane >> 4) << 3);
    int bkof = ((lane >> 3) & 1) * 8;

#pragma unroll
    for (int kc = 0; kc < 2; kc++) {
        int k0 = kc * 64;
#pragma unroll
        for (int u = 0; u < 4; u++) {
            int id = t + 256 * u;
            int r = id >> 3, c8 = (id & 7) * 8;
            int grow = row0 + r;
            uint4 v = make_uint4(0u, 0u, 0u, 0u);
            if (grow < Nn) v = *reinterpret_cast<const uint4*>(g_xh + (size_t)grow * Dd + k0 + c8);
            *reinterpret_cast<uint4*>(smem + (size_t)(r * 72 + c8) * 2) = v;
        }
#pragma unroll
        for (int u = 0; u < 4; u++) {
            int id = t + 256 * u;
            int r = id >> 3, c8 = (id & 7) * 8;
            char* pb = smem + O_BHIo + (size_t)(r * 72 + c8) * 2;
            *reinterpret_cast<uint4*>(pb) = *reinterpret_cast<const uint4*>(Wh + (size_t)r * 128 + k0 + c8);
            *reinterpret_cast<uint4*>(pb + (O_BLOo - O_BHIo)) = *reinterpret_cast<const uint4*>(Wl + (size_t)r * 128 + k0 + c8);
        }
        __syncthreads();
#pragma unroll
        for (int kt = 0; kt < 4; kt++) {
            uint32_t ah[4][4], bhf[2][4], blf[2][4];
#pragma unroll
            for (int mt = 0; mt < 4; mt++) {
                uint32_t ad = sb + 2u * ((wm + 16 * mt + arow) * 72 + 16 * kt + akof);
                LDSM4(ah[mt], ad);
            }
#pragma unroll
            for (int g = 0; g < 2; g++) {
                uint32_t bd = sb + O_BHIo + 2u * ((wn + 16 * g + bnr) * 72 + 16 * kt + bkof);
                LDSM4(bhf[g], bd);
                LDSM4(blf[g], bd + (O_BLOo - O_BHIo));
            }
#pragma unroll
            for (int mt = 0; mt < 4; mt++)
#pragma unroll
                for (int nt = 0; nt < 4; nt++) {
                    uint32_t bh0 = bhf[nt >> 1][(nt & 1) * 2], bh1 = bhf[nt >> 1][(nt & 1) * 2 + 1];
                    uint32_t bl0 = blf[nt >> 1][(nt & 1) * 2], bl1 = blf[nt >> 1][(nt & 1) * 2 + 1];
                    mma_f16(d[mt][nt], ah[mt], bh0, bh1);
                    mma_f16(d[mt][nt], ah[mt], bl0, bl1);
                }
        }
        __syncthreads();
    }

    // fp16 store (feat for yb<4, res for yb>=4)
    __half* C = (yb < 4) ? g_feath : g_resh;
    int wc0 = (yb & 3) * 128;
#pragma unroll
    for (int mt = 0; mt < 4; mt++) {
        int r0 = row0 + wm + 16 * mt + gr;
        int r1 = r0 + 8;
#pragma unroll
        for (int nt = 0; nt < 4; nt++) {
            int col = wc0 + wn + nt * 8 + 2 * gc;
            if (r0 < Nn)
                *reinterpret_cast<__half2*>(C + (size_t)r0 * HDim + col) =
                    __floats2half2_rn(d[mt][nt][0], d[mt][nt][1]);
            if (r1 < Nn)
                *reinterpret_cast<__half2*>(C + (size_t)r1 * HDim + col) =
                    __floats2half2_rn(d[mt][nt][2], d[mt][nt][3]);
        }
    }

    // fused el/er for this block's head (yb<4): fp32 dot from accumulators
    if (yb < 4) {
        float* red_el = reinterpret_cast<float*>(smem);
        float* red_er = reinterpret_cast<float*>(smem + 2048);
        float alv[4][2], arv[4][2];
#pragma unroll
        for (int nt = 0; nt < 4; nt++) {
            int dim = wn + nt * 8 + 2 * gc;
            alv[nt][0] = al[yb * 128 + dim];     alv[nt][1] = al[yb * 128 + dim + 1];
            arv[nt][0] = ar[yb * 128 + dim];     arv[nt][1] = ar[yb * 128 + dim + 1];
        }
#pragma unroll
        for (int mt = 0; mt < 4; mt++) {
            float sl0 = 0.f, sr0 = 0.f, sl1 = 0.f, sr1 = 0.f;
#pragma unroll
            for (int nt = 0; nt < 4; nt++) {
                sl0 += d[mt][nt][0] * alv[nt][0] + d[mt][nt][1] * alv[nt][1];
                sr0 += d[mt][nt][0] * arv[nt][0] + d[mt][nt][1] * arv[nt][1];
                sl1 += d[mt][nt][2] * alv[nt][0] + d[mt][nt][3] * alv[nt][1];
                sr1 += d[mt][nt][2] * arv[nt][0] + d[mt][nt][3] * arv[nt][1];
            }
#pragma unroll
            for (int o = 1; o < 4; o <<= 1) {
                sl0 += __shfl_xor_sync(0xffffffffu, sl0, o);
                sr0 += __shfl_xor_sync(0xffffffffu, sr0, o);
                sl1 += __shfl_xor_sync(0xffffffffu, sl1, o);
                sr1 += __shfl_xor_sync(0xffffffffu, sr1, o);
            }
            if (gc == 0) {
                int rb = wm + 16 * mt + gr;
                red_el[wnid * 128 + rb] = sl0;      red_el[wnid * 128 + rb + 8] = sl1;
                red_er[wnid * 128 + rb] = sr0;      red_er[wnid * 128 + rb + 8] = sr1;
            }
        }
        __syncthreads();
        if (gc == 0 && wnid == 0) {
#pragma unroll
            for (int mt = 0; mt < 4; mt++) {
                int rb = wm + 16 * mt + gr;
#pragma unroll
                for (int q = 0; q < 2; q++) {
                    int rr = rb + 8 * q;
                    int node = row0 + rr;
                    if (node < Nn) {
                        float e = red_el[rr] + red_el[128 + rr] + red_el[256 + rr] + red_el[384 + rr];
                        float f = red_er[rr] + red_er[128 + rr] + red_er[256 + rr] + red_er[384 + rr];
                        g_el[node * 4 + yb] = e;
                        g_er[node * 4 + yb] = f;
                    }
                }
            }
        }
    }
}

// ============ GEMM2 + bias + LayerNorm: out = LN(h(fp16) @ Wn + bn) ============
__global__ void __launch_bounds__(256) k_gemm2(int l, const float* __restrict__ bn,
                                               const float* __restrict__ gam,
                                               const float* __restrict__ bet,
                                               float* __restrict__ out, int last) {
    extern __shared__ char smem[];
    uint32_t sb = s2u(smem);
    int t = threadIdx.x, lane = t & 31, wid = t >> 5;
    int gr = lane >> 2, gc = lane & 3;
    int wm = (wid & 1) * 64, wnid = wid >> 1, wn = wnid * 32;
    int row0 = blockIdx.x * 128;

    float* par = reinterpret_cast<float*>(smem + O2_PAR);
    if (t < 128) { par[t] = bn[t]; par[128 + t] = gam[t]; par[256 + t] = bet[t]; }

    const __half* Wh = g_w2h + (size_t)l * 128 * 512;
    const __half* Wl = g_w2l + (size_t)l * 128 * 512;

    float d[4][4][4];
#pragma unroll
    for (int i = 0; i < 4; i++)
#pragma unroll
        for (int j = 0; j < 4; j++)
#pragma unroll
            for (int q = 0; q < 4; q++) d[i][j][q] = 0.f;

    int arow = (lane & 7) + ((lane >> 3) & 1) * 8;
    int akof = (lane >> 4) * 8;
    int bnr  = (lane & 7) + ((lane >> 4) << 3);
    int bkof = ((lane >> 3) & 1) * 8;

    for (int kc = 0; kc < 8; kc++) {
        int k0 = kc * 64;
#pragma unroll
        for (int u = 0; u < 4; u++) {
            int id = t + 256 * u;
            int r = id >> 3, c8 = (id & 7) * 8;
            int grow = row0 + r;
            uint4 v = make_uint4(0u, 0u, 0u, 0u);
            if (grow < Nn) v = *reinterpret_cast<const uint4*>(g_resh + (size_t)grow * HDim + k0 + c8);
            *reinterpret_cast<uint4*>(smem + (size_t)(r * 72 + c8) * 2) = v;
        }
#pragma unroll
        for (int u = 0; u < 4; u++) {
            int id = t + 256 * u;
            int r = id >> 3, c8 = (id & 7) * 8;
            char* pb = smem + O_BHIo + (size_t)(r * 72 + c8) * 2;
            *reinterpret_cast<uint4*>(pb) = *reinterpret_cast<const uint4*>(Wh + (size_t)r * 512 + k0 + c8);
            *reinterpret_cast<uint4*>(pb + (O_BLOo - O_BHIo)) = *reinterpret_cast<const uint4*>(Wl + (size_t)r * 512 + k0 + c8);
        }
        __syncthreads();
#pragma unroll
        for (int kt = 0; kt < 4; kt++) {
            uint32_t ah[4][4], bhf[2][4], blf[2][4];
#pragma unroll
            for (int mt = 0; mt < 4; mt++) {
                uint32_t ad = sb + 2u * ((wm + 16 * mt + arow) * 72 + 16 * kt + akof);
                LDSM4(ah[mt], ad);
            }
#pragma unroll
            for (int g = 0; g < 2; g++) {
                uint32_t bd = sb + O_BHIo + 2u * ((wn + 16 * g + bnr) * 72 + 16 * kt + bkof);
                LDSM4(bhf[g], bd);
                LDSM4(blf[g], bd + (O_BLOo - O_BHIo));
            }
#pragma unroll
            for (int mt = 0; mt < 4; mt++)
#pragma unroll
                for (int nt = 0; nt < 4; nt++) {
                    uint32_t bh0 = bhf[nt >> 1][(nt & 1) * 2], bh1 = bhf[nt >> 1][(nt & 1) * 2 + 1];
                    uint32_t bl0 = blf[nt >> 1][(nt & 1) * 2], bl1 = blf[nt >> 1][(nt & 1) * 2 + 1];
                    mma_f16(d[mt][nt], ah[mt], bh0, bh1);
                    mma_f16(d[mt][nt], ah[mt], bl0, bl1);
                }
        }
        __syncthreads();
    }

    // ---- fused bias + LayerNorm epilogue ----
    float* red_s = reinterpret_cast<float*>(smem);
    float* red_q = reinterpret_cast<float*>(smem + 2048);
    float bnv[4][2];
#pragma unroll
    for (int nt = 0; nt < 4; nt++) {
        int col = wn + nt * 8 + 2 * gc;
        bnv[nt][0] = par[col]; bnv[nt][1] = par[col + 1];
    }
#pragma unroll
    for (int mt = 0; mt < 4; mt++) {
        float s0 = 0.f, q0 = 0.f, s1 = 0.f, q1 = 0.f;
#pragma unroll
        for (int nt = 0; nt < 4; nt++) {
            float y00 = d[mt][nt][0] + bnv[nt][0];
            float y01 = d[mt][nt][1] + bnv[nt][1];
            float y10 = d[mt][nt][2] + bnv[nt][0];
            float y11 = d[mt][nt][3] + bnv[nt][1];
            d[mt][nt][0] = y00; d[mt][nt][1] = y01;
            d[mt][nt][2] = y10; d[mt][nt][3] = y11;
            s0 += y00 + y01; q0 += y00 * y00 + y01 * y01;
            s1 += y10 + y11; q1 += y10 * y10 + y11 * y11;
        }
#pragma unroll
        for (int o = 1; o < 4; o <<= 1) {
            s0 += __shfl_xor_sync(0xffffffffu, s0, o);
            q0 += __shfl_xor_sync(0xffffffffu, q0, o);
            s1 += __shfl_xor_sync(0xffffffffu, s1, o);
            q1 += __shfl_xor_sync(0xffffffffu, q1, o);
        }
        if (gc == 0) {
            int rb = wm + 16 * mt + gr;
            red_s[wnid * 128 + rb] = s0; red_q[wnid * 128 + rb] = q0;
            red_s[wnid * 128 + rb + 8] = s1; red_q[wnid * 128 + rb + 8] = q1;
        }
    }
    __syncthreads();
#pragma unroll
    for (int mt = 0; mt < 4; mt++) {
        int rb = wm + 16 * mt + gr;
        float s0 = red_s[rb] + red_s[128 + rb] + red_s[256 + rb] + red_s[384 + rb];
        float q0 = red_q[rb] + red_q[128 + rb] + red_q[256 + rb] + red_q[384 + rb];
        float s1 = red_s[rb + 8] + red_s[128 + rb + 8] + red_s[256 + rb + 8] + red_s[384 + rb + 8];
        float q1 = red_q[rb + 8] + red_q[128 + rb + 8] + red_q[256 + rb + 8] + red_q[384 + rb + 8];
        float mu0 = s0 * (1.f / 128.f);
        float mu1 = s1 * (1.f / 128.f);
        float rstd0 = rsqrtf(q0 * (1.f / 128.f) - mu0 * mu0 + 1e-5f);
        float rstd1 = rsqrtf(q1 * (1.f / 128.f) - mu1 * mu1 + 1e-5f);
        int r0 = row0 + rb, r1 = r0 + 8;
#pragma unroll
        for (int nt = 0; nt < 4; nt++) {
            int col = wn + nt * 8 + 2 * gc;
            float g0 = par[128 + col], g1 = par[128 + col + 1];
            float b0 = par[256 + col], b1 = par[256 + col + 1];
            float v00 = (d[mt][nt][0] - mu0) * rstd0 * g0 + b0;
            float v01 = (d[mt][nt][1] - mu0) * rstd0 * g1 + b1;
            float v10 = (d[mt][nt][2] - mu1) * rstd1 * g0 + b0;
            float v11 = (d[mt][nt][3] - mu1) * rstd1 * g1 + b1;
            if (last) {
                if (r0 < Nn)
                    *reinterpret_cast<float2*>(out + (size_t)r0 * Dd + col) = make_float2(v00, v01);
                if (r1 < Nn)
                    *reinterpret_cast<float2*>(out + (size_t)r1 * Dd + col) = make_float2(v10, v11);
            } else {
                if (r0 < Nn)
                    *reinterpret_cast<__half2*>(g_xh + (size_t)r0 * Dd + col) = __floats2half2_rn(v00, v01);
                if (r1 < Nn)
                    *reinterpret_cast<__half2*>(g_xh + (size_t)r1 * Dd + col) = __floats2half2_rn(v10, v11);
            }
        }
    }
}

// ---------------- fused edge-softmax + aggregation ----------------
// One block (128 thr) per dst node. Warp w owns head w; lane ln owns cols 4ln..4ln+3.
// Weights computed lane-parallel per 32-edge batch, then broadcast via shfl.
__global__ void k_aggregate(const float* __restrict__ bgat) {
    int dn = blockIdx.x;
    int w = threadIdx.x >> 5, ln = threadIdx.x & 31;
    int s = g_off[dn], en = g_off[dn + 1];
    float erd = g_er[dn * 4 + w];
    float a0 = 0.f, a1 = 0.f, a2 = 0.f, a3 = 0.f, z = 0.f;

    for (int base = s; base < en; base += 32) {
        int cnt = en - base; if (cnt > 32) cnt = 32;
        int idx = (ln < cnt) ? g_csr_src[base + ln] : 0;
        float e = g_el[idx * 4 + w] + erd;
        e = e > 0.f ? e : NEG_ATTN * e;
        float wv = (ln < cnt) ? __expf(e) : 0.f;
        for (int j = 0; j < cnt; j++) {
            int sn   = __shfl_sync(0xffffffffu, idx, j);
            float wg = __shfl_sync(0xffffffffu, wv, j);
            uint2 u = *reinterpret_cast<const uint2*>(g_feath + (size_t)sn * 512 + w * 128 + 4 * ln);
            float2 f0 = __half22float2(*reinterpret_cast<__half2*>(&u.x));
            float2 f1 = __half22float2(*reinterpret_cast<__half2*>(&u.y));
            a0 = fmaf(wg, f0.x, a0); a1 = fmaf(wg, f0.y, a1);
            a2 = fmaf(wg, f1.x, a2); a3 = fmaf(wg, f1.y, a3);
            z += wg;
        }
    }

    float iz = 1.f / fmaxf(z, 1e-20f);
    int col = w * 128 + 4 * ln;
    size_t o = (size_t)dn * HDim + col;
    uint2 ru = *reinterpret_cast<const uint2*>(g_resh + o);
    float2 r0 = __half22float2(*reinterpret_cast<__half2*>(&ru.x));
    float2 r1 = __half22float2(*reinterpret_cast<__half2*>(&ru.y));
    float4 bg = *reinterpret_cast<const float4*>(bgat + col);
    float v0 = a0 * iz + r0.x + bg.x; v0 = v0 > 0.f ? v0 : NEG_ACT * v0;
    float v1 = a1 * iz + r0.y + bg.y; v1 = v1 > 0.f ? v1 : NEG_ACT * v1;
    float v2 = a2 * iz + r1.x + bg.z; v2 = v2 > 0.f ? v2 : NEG_ACT * v2;
    float v3 = a3 * iz + r1.y + bg.w; v3 = v3 > 0.f ? v3 : NEG_ACT * v3;
    uint2 ou;
    *reinterpret_cast<__half2*>(&ou.x) = __floats2half2_rn(v0, v1);
    *reinterpret_cast<__half2*>(&ou.y) = __floats2half2_rn(v2, v3);
    *reinterpret_cast<uint2*>(g_resh + o) = ou;
}

// ---------------- launch ----------------
extern "C" void kernel_launch(void* const* d_in, const int* in_sizes, int n_in,
                              void* d_out, int out_size) {
    const float* features = (const float*)d_in[0];
    const int*   src      = (const int*)  d_in[1];
    const int*   dst      = (const int*)  d_in[2];
    const float* W_fc     = (const float*)d_in[3];
    const float* attn_l   = (const float*)d_in[4];
    const float* attn_r   = (const float*)d_in[5];
    const float* W_res    = (const float*)d_in[6];
    const float* b_gat    = (const float*)d_in[7];
    const float* W_nrm    = (const float*)d_in[8];
    const float* b_nrm    = (const float*)d_in[9];
    const float* ln_g     = (const float*)d_in[10];
    const float* ln_b     = (const float*)d_in[11];
    float* out = (float*)d_out;

    cudaFuncSetAttribute(k_gemm1, cudaFuncAttributeMaxDynamicSharedMemorySize, SMEM_G1);
    cudaFuncSetAttribute(k_gemm2, cudaFuncAttributeMaxDynamicSharedMemorySize, SMEM_G2);

    k_zero_deg<<<(Nn + 255) / 256, 256>>>();
    k_hist<<<(Ee + 255) / 256, 256>>>(dst);
    k_scan<<<1, 1024>>>();
    k_scatter<<<(Ee + 255) / 256, 256>>>(src, dst);
    k_prep_w1<<<(4 * 1024 * 128 + 255) / 256, 256>>>(W_fc, W_res);
    k_prep_x<<<(Nn * Dd + 255) / 256, 256>>>(features);

    for (int l = 0; l < 4; l++) {
        const float* al  = attn_l + (size_t)l * Hh * Dd;
        const float* ar  = attn_r + (size_t)l * Hh * Dd;
        const float* bg  = b_gat + (size_t)l * HDim;
        const float* bnp = b_nrm + (size_t)l * Dd;
        const float* gp  = ln_g  + (size_t)l * Dd;
        const float* bp  = ln_b  + (size_t)l * Dd;

        k_gemm1<<<dim3((Nn + 127) / 128, 8), 256, SMEM_G1>>>(l, al, ar);
        if (l == 0) k_prep_w2<<<(4 * 128 * 512 + 255) / 256, 256>>>(W_nrm);
        k_aggregate<<<Nn, 128>>>(bg);
        k_gemm2<<<(Nn + 127) / 128, 256, SMEM_G2>>>(l, bnp, gp, bp, out, l == 3 ? 1 : 0);
    }
}

// round 15
// speedup vs baseline: 3.3364x; 1.1020x over previous
#include <cuda_runtime.h>
#include <cuda_bf16.h>
#include <cuda_fp16.h>
#include <math.h>
#include <float.h>
#include <stdint.h>

#define Nn 50000
#define Ee 800000
#define Hh 4
#define Dd 128
#define HDim 512
#define NEG_ATTN 0.2f
#define NEG_ACT 0.01f

// ---------------- scratch (static device allocations) ----------------
__device__ __half g_feath[(size_t)Nn * HDim];   // fp16 feat (gather source)
__device__ __half g_resh [(size_t)Nn * HDim];   // fp16 res / h (GEMM2 A operand)
__device__ __half g_xh   [(size_t)Nn * Dd];     // layer input x, fp16
__device__ float g_el  [Nn * Hh];
__device__ float g_er  [Nn * Hh];
__device__ int   g_deg [Nn];
__device__ int   g_off [Nn + 1];
__device__ int   g_cur [Nn];
__device__ int   g_csr_src[Ee];

// transposed weights, [n][k] layout
__device__ __half g_w1h[4u * 1024 * 128];          // plain fp16 for GEMM1
__device__ __half g_w2h[4u * 128 * 512];           // fp16 hi/lo for GEMM2
__device__ __half g_w2l[4u * 128 * 512];

// smem offsets (bytes): tiles of [128][72] 16-bit = 18432 each
// GEMM1: A at 0, B at 18432 -> 36864 total
#define O_BHIo 18432
#define O_BLOo 36864
#define SMEM_G1 36864
// GEMM2: A at 0, BHI at 18432, BLO at 36864, par at 55296
#define O2_PAR 55296
#define SMEM_G2 (55296 + 1536)

// ---------------- helpers ----------------
__device__ __forceinline__ uint32_t s2u(const void* p) {
    uint32_t a;
    asm("{ .reg .u64 t; cvta.to.shared.u64 t, %1; cvt.u32.u64 %0, t; }" : "=r"(a) : "l"(p));
    return a;
}

#define LDSM4(R, A) \
    asm volatile("ldmatrix.sync.aligned.m8n8.x4.shared.b16 {%0,%1,%2,%3}, [%4];" \
        : "=r"((R)[0]), "=r"((R)[1]), "=r"((R)[2]), "=r"((R)[3]) : "r"(A))

__device__ __forceinline__ void mma_f16(float d[4], const uint32_t a[4],
                                        uint32_t b0, uint32_t b1) {
    asm volatile(
        "mma.sync.aligned.m16n8k16.row.col.f32.f16.f16.f32 "
        "{%0,%1,%2,%3},{%4,%5,%6,%7},{%8,%9},{%0,%1,%2,%3};"
        : "+f"(d[0]), "+f"(d[1]), "+f"(d[2]), "+f"(d[3])
        : "r"(a[0]), "r"(a[1]), "r"(a[2]), "r"(a[3]), "r"(b0), "r"(b1));
}

// ---------------- weight / input prep ----------------
__global__ void k_prep_w1(const float* __restrict__ Wfc, const float* __restrict__ Wres) {
    int id = blockIdx.x * 256 + threadIdx.x;
    if (id >= 4 * 1024 * 128) return;
    int k = id & 127, n = (id >> 7) & 1023, l = id >> 17;
    float v = (n < 512) ? Wfc[((size_t)l * 128 + k) * 512 + n]
                        : Wres[((size_t)l * 128 + k) * 512 + (n - 512)];
    g_w1h[id] = __float2half_rn(v);
}

__global__ void k_prep_w2(const float* __restrict__ Wn) {
    int id = blockIdx.x * 256 + threadIdx.x;
    if (id >= 4 * 128 * 512) return;
    int k = id & 511, n = (id >> 9) & 127, l = id >> 16;
    float v = Wn[((size_t)l * 512 + k) * 128 + n];
    __half h = __float2half_rn(v);
    g_w2h[id] = h;
    g_w2l[id] = __float2half_rn(v - __half2float(h));
}

__global__ void k_prep_x(const float* __restrict__ X) {
    int id = blockIdx.x * 256 + threadIdx.x;
    if (id >= Nn * Dd) return;
    g_xh[id] = __float2half_rn(X[id]);
}

// ---------------- CSR build ----------------
__global__ void k_zero_deg() {
    int i = blockIdx.x * blockDim.x + threadIdx.x;
    if (i < Nn) g_deg[i] = 0;
}
__global__ void k_hist(const int* __restrict__ dst) {
    int i = blockIdx.x * blockDim.x + threadIdx.x;
    if (i < Ee) atomicAdd(&g_deg[dst[i]], 1);
}
__global__ void k_scan() {
    __shared__ int sbuf[1024];
    __shared__ int carry;
    int t = threadIdx.x;
    if (t == 0) carry = 0;
    __syncthreads();
    for (int base = 0; base < Nn; base += 1024) {
        int i = base + t;
        int v = (i < Nn) ? g_deg[i] : 0;
        sbuf[t] = v;
        __syncthreads();
        for (int off = 1; off < 1024; off <<= 1) {
            int add = (t >= off) ? sbuf[t - off] : 0;
            __syncthreads();
            sbuf[t] += add;
            __syncthreads();
        }
        int incl = sbuf[t];
        int excl = carry + incl - v;
        if (i < Nn) { g_off[i] = excl; g_cur[i] = excl; }
        int total = sbuf[1023];
        __syncthreads();
        if (t == 0) carry += total;
        __syncthreads();
    }
    if (t == 0) g_off[Nn] = carry;
}
__global__ void k_scatter(const int* __restrict__ src, const int* __restrict__ dst) {
    int i = blockIdx.x * blockDim.x + threadIdx.x;
    if (i < Ee) {
        int d = dst[i];
        int p = atomicAdd(&g_cur[d], 1);
        g_csr_src[p] = src[i];
    }
}

// ============ GEMM1: [feat|res] = x(fp16) @ W1(fp16) ; fused el/er for yb<4 ============
// 1 MMA per tile.
__global__ void __launch_bounds__(256) k_gemm1(int l, const float* __restrict__ al,
                                               const float* __restrict__ ar) {
    extern __shared__ char smem[];
    uint32_t sb = s2u(smem);
    int t = threadIdx.x, lane = t & 31, wid = t >> 5;
    int gr = lane >> 2, gc = lane & 3;
    int wm = (wid & 1) * 64, wnid = wid >> 1, wn = wnid * 32;
    int row0 = blockIdx.x * 128;
    int yb = blockIdx.y;

    const __half* Wh = g_w1h + ((size_t)l * 1024 + (size_t)yb * 128) * 128;

    float d[4][4][4];
#pragma unroll
    for (int i = 0; i < 4; i++)
#pragma unroll
        for (int j = 0; j < 4; j++)
#pragma unroll
            for (int q = 0; q < 4; q++) d[i][j][q] = 0.f;

    int arow = (lane & 7) + ((lane >> 3) & 1) * 8;
    int akof = (lane >> 4) * 8;
    int bnr  = (lane & 7) + ((lane >> 4) << 3);
    int bkof = ((lane >> 3) & 1) * 8;

#pragma unroll
    for (int kc = 0; kc < 2; kc++) {
        int k0 = kc * 64;
        // A: 128 rows x 64 fp16
#pragma unroll
        for (int u = 0; u < 4; u++) {
            int id = t + 256 * u;
            int r = id >> 3, c8 = (id & 7) * 8;
            int grow = row0 + r;
            uint4 v = make_uint4(0u, 0u, 0u, 0u);
            if (grow < Nn) v = *reinterpret_cast<const uint4*>(g_xh + (size_t)grow * Dd + k0 + c8);
            *reinterpret_cast<uint4*>(smem + (size_t)(r * 72 + c8) * 2) = v;
        }
        // B: 128 n-rows x 64 fp16
#pragma unroll
        for (int u = 0; u < 4; u++) {
            int id = t + 256 * u;
            int r = id >> 3, c8 = (id & 7) * 8;
            *reinterpret_cast<uint4*>(smem + O_BHIo + (size_t)(r * 72 + c8) * 2) =
                *reinterpret_cast<const uint4*>(Wh + (size_t)r * 128 + k0 + c8);
        }
        __syncthreads();
#pragma unroll
        for (int kt = 0; kt < 4; kt++) {
            uint32_t ah[4][4], bhf[2][4];
#pragma unroll
            for (int mt = 0; mt < 4; mt++) {
                uint32_t ad = sb + 2u * ((wm + 16 * mt + arow) * 72 + 16 * kt + akof);
                LDSM4(ah[mt], ad);
            }
#pragma unroll
            for (int g = 0; g < 2; g++) {
                uint32_t bd = sb + O_BHIo + 2u * ((wn + 16 * g + bnr) * 72 + 16 * kt + bkof);
                LDSM4(bhf[g], bd);
            }
#pragma unroll
            for (int mt = 0; mt < 4; mt++)
#pragma unroll
                for (int nt = 0; nt < 4; nt++) {
                    uint32_t bh0 = bhf[nt >> 1][(nt & 1) * 2], bh1 = bhf[nt >> 1][(nt & 1) * 2 + 1];
                    mma_f16(d[mt][nt], ah[mt], bh0, bh1);
                }
        }
        __syncthreads();
    }

    // fp16 store (feat for yb<4, res for yb>=4)
    __half* C = (yb < 4) ? g_feath : g_resh;
    int wc0 = (yb & 3) * 128;
#pragma unroll
    for (int mt = 0; mt < 4; mt++) {
        int r0 = row0 + wm + 16 * mt + gr;
        int r1 = r0 + 8;
#pragma unroll
        for (int nt = 0; nt < 4; nt++) {
            int col = wc0 + wn + nt * 8 + 2 * gc;
            if (r0 < Nn)
                *reinterpret_cast<__half2*>(C + (size_t)r0 * HDim + col) =
                    __floats2half2_rn(d[mt][nt][0], d[mt][nt][1]);
            if (r1 < Nn)
                *reinterpret_cast<__half2*>(C + (size_t)r1 * HDim + col) =
                    __floats2half2_rn(d[mt][nt][2], d[mt][nt][3]);
        }
    }

    // fused el/er for this block's head (yb<4): fp32 dot from accumulators
    if (yb < 4) {
        float* red_el = reinterpret_cast<float*>(smem);
        float* red_er = reinterpret_cast<float*>(smem + 2048);
        float alv[4][2], arv[4][2];
#pragma unroll
        for (int nt = 0; nt < 4; nt++) {
            int dim = wn + nt * 8 + 2 * gc;
            alv[nt][0] = al[yb * 128 + dim];     alv[nt][1] = al[yb * 128 + dim + 1];
            arv[nt][0] = ar[yb * 128 + dim];     arv[nt][1] = ar[yb * 128 + dim + 1];
        }
#pragma unroll
        for (int mt = 0; mt < 4; mt++) {
            float sl0 = 0.f, sr0 = 0.f, sl1 = 0.f, sr1 = 0.f;
#pragma unroll
            for (int nt = 0; nt < 4; nt++) {
                sl0 += d[mt][nt][0] * alv[nt][0] + d[mt][nt][1] * alv[nt][1];
                sr0 += d[mt][nt][0] * arv[nt][0] + d[mt][nt][1] * arv[nt][1];
                sl1 += d[mt][nt][2] * alv[nt][0] + d[mt][nt][3] * alv[nt][1];
                sr1 += d[mt][nt][2] * arv[nt][0] + d[mt][nt][3] * arv[nt][1];
            }
#pragma unroll
            for (int o = 1; o < 4; o <<= 1) {
                sl0 += __shfl_xor_sync(0xffffffffu, sl0, o);
                sr0 += __shfl_xor_sync(0xffffffffu, sr0, o);
                sl1 += __shfl_xor_sync(0xffffffffu, sl1, o);
                sr1 += __shfl_xor_sync(0xffffffffu, sr1, o);
            }
            if (gc == 0) {
                int rb = wm + 16 * mt + gr;
                red_el[wnid * 128 + rb] = sl0;      red_el[wnid * 128 + rb + 8] = sl1;
                red_er[wnid * 128 + rb] = sr0;      red_er[wnid * 128 + rb + 8] = sr1;
            }
        }
        __syncthreads();
        if (gc == 0 && wnid == 0) {
#pragma unroll
            for (int mt = 0; mt < 4; mt++) {
                int rb = wm + 16 * mt + gr;
#pragma unroll
                for (int q = 0; q < 2; q++) {
                    int rr = rb + 8 * q;
                    int node = row0 + rr;
                    if (node < Nn) {
                        float e = red_el[rr] + red_el[128 + rr] + red_el[256 + rr] + red_el[384 + rr];
                        float f = red_er[rr] + red_er[128 + rr] + red_er[256 + rr] + red_er[384 + rr];
                        g_el[node * 4 + yb] = e;
                        g_er[node * 4 + yb] = f;
                    }
                }
            }
        }
    }
}

// ============ GEMM2 + bias + LayerNorm: out = LN(h(fp16) @ Wn + bn) ============
__global__ void __launch_bounds__(256) k_gemm2(int l, const float* __restrict__ bn,
                                               const float* __restrict__ gam,
                                               const float* __restrict__ bet,
                                               float* __restrict__ out, int last) {
    extern __shared__ char smem[];
    uint32_t sb = s2u(smem);
    int t = threadIdx.x, lane = t & 31, wid = t >> 5;
    int gr = lane >> 2, gc = lane & 3;
    int wm = (wid & 1) * 64, wnid = wid >> 1, wn = wnid * 32;
    int row0 = blockIdx.x * 128;

    float* par = reinterpret_cast<float*>(smem + O2_PAR);
    if (t < 128) { par[t] = bn[t]; par[128 + t] = gam[t]; par[256 + t] = bet[t]; }

    const __half* Wh = g_w2h + (size_t)l * 128 * 512;
    const __half* Wl = g_w2l + (size_t)l * 128 * 512;

    float d[4][4][4];
#pragma unroll
    for (int i = 0; i < 4; i++)
#pragma unroll
        for (int j = 0; j < 4; j++)
#pragma unroll
            for (int q = 0; q < 4; q++) d[i][j][q] = 0.f;

    int arow = (lane & 7) + ((lane >> 3) & 1) * 8;
    int akof = (lane >> 4) * 8;
    int bnr  = (lane & 7) + ((lane >> 4) << 3);
    int bkof = ((lane >> 3) & 1) * 8;

    for (int kc = 0; kc < 8; kc++) {
        int k0 = kc * 64;
#pragma unroll
        for (int u = 0; u < 4; u++) {
            int id = t + 256 * u;
            int r = id >> 3, c8 = (id & 7) * 8;
            int grow = row0 + r;
            uint4 v = make_uint4(0u, 0u, 0u, 0u);
            if (grow < Nn) v = *reinterpret_cast<const uint4*>(g_resh + (size_t)grow * HDim + k0 + c8);
            *reinterpret_cast<uint4*>(smem + (size_t)(r * 72 + c8) * 2) = v;
        }
#pragma unroll
        for (int u = 0; u < 4; u++) {
            int id = t + 256 * u;
            int r = id >> 3, c8 = (id & 7) * 8;
            char* pb = smem + O_BHIo + (size_t)(r * 72 + c8) * 2;
            *reinterpret_cast<uint4*>(pb) = *reinterpret_cast<const uint4*>(Wh + (size_t)r * 512 + k0 + c8);
            *reinterpret_cast<uint4*>(pb + (O_BLOo - O_BHIo)) = *reinterpret_cast<const uint4*>(Wl + (size_t)r * 512 + k0 + c8);
        }
        __syncthreads();
#pragma unroll
        for (int kt = 0; kt < 4; kt++) {
            uint32_t ah[4][4], bhf[2][4], blf[2][4];
#pragma unroll
            for (int mt = 0; mt < 4; mt++) {
                uint32_t ad = sb + 2u * ((wm + 16 * mt + arow) * 72 + 16 * kt + akof);
                LDSM4(ah[mt], ad);
            }
#pragma unroll
            for (int g = 0; g < 2; g++) {
                uint32_t bd = sb + O_BHIo + 2u * ((wn + 16 * g + bnr) * 72 + 16 * kt + bkof);
                LDSM4(bhf[g], bd);
                LDSM4(blf[g], bd + (O_BLOo - O_BHIo));
            }
#pragma unroll
            for (int mt = 0; mt < 4; mt++)
#pragma unroll
                for (int nt = 0; nt < 4; nt++) {
                    uint32_t bh0 = bhf[nt >> 1][(nt & 1) * 2], bh1 = bhf[nt >> 1][(nt & 1) * 2 + 1];
                    uint32_t bl0 = blf[nt >> 1][(nt & 1) * 2], bl1 = blf[nt >> 1][(nt & 1) * 2 + 1];
                    mma_f16(d[mt][nt], ah[mt], bh0, bh1);
                    mma_f16(d[mt][nt], ah[mt], bl0, bl1);
                }
        }
        __syncthreads();
    }

    // ---- fused bias + LayerNorm epilogue ----
    float* red_s = reinterpret_cast<float*>(smem);
    float* red_q = reinterpret_cast<float*>(smem + 2048);
    float bnv[4][2];
#pragma unroll
    for (int nt = 0; nt < 4; nt++) {
        int col = wn + nt * 8 + 2 * gc;
        bnv[nt][0] = par[col]; bnv[nt][1] = par[col + 1];
    }
#pragma unroll
    for (int mt = 0; mt < 4; mt++) {
        float s0 = 0.f, q0 = 0.f, s1 = 0.f, q1 = 0.f;
#pragma unroll
        for (int nt = 0; nt < 4; nt++) {
            float y00 = d[mt][nt][0] + bnv[nt][0];
            float y01 = d[mt][nt][1] + bnv[nt][1];
            float y10 = d[mt][nt][2] + bnv[nt][0];
            float y11 = d[mt][nt][3] + bnv[nt][1];
            d[mt][nt][0] = y00; d[mt][nt][1] = y01;
            d[mt][nt][2] = y10; d[mt][nt][3] = y11;
            s0 += y00 + y01; q0 += y00 * y00 + y01 * y01;
            s1 += y10 + y11; q1 += y10 * y10 + y11 * y11;
        }
#pragma unroll
        for (int o = 1; o < 4; o <<= 1) {
            s0 += __shfl_xor_sync(0xffffffffu, s0, o);
            q0 += __shfl_xor_sync(0xffffffffu, q0, o);
            s1 += __shfl_xor_sync(0xffffffffu, s1, o);
            q1 += __shfl_xor_sync(0xffffffffu, q1, o);
        }
        if (gc == 0) {
            int rb = wm + 16 * mt + gr;
            red_s[wnid * 128 + rb] = s0; red_q[wnid * 128 + rb] = q0;
            red_s[wnid * 128 + rb + 8] = s1; red_q[wnid * 128 + rb + 8] = q1;
        }
    }
    __syncthreads();
#pragma unroll
    for (int mt = 0; mt < 4; mt++) {
        int rb = wm + 16 * mt + gr;
        float s0 = red_s[rb] + red_s[128 + rb] + red_s[256 + rb] + red_s[384 + rb];
        float q0 = red_q[rb] + red_q[128 + rb] + red_q[256 + rb] + red_q[384 + rb];
        float s1 = red_s[rb + 8] + red_s[128 + rb + 8] + red_s[256 + rb + 8] + red_s[384 + rb + 8];
        float q1 = red_q[rb + 8] + red_q[128 + rb + 8] + red_q[256 + rb + 8] + red_q[384 + rb + 8];
        float mu0 = s0 * (1.f / 128.f);
        float mu1 = s1 * (1.f / 128.f);
        float rstd0 = rsqrtf(q0 * (1.f / 128.f) - mu0 * mu0 + 1e-5f);
        float rstd1 = rsqrtf(q1 * (1.f / 128.f) - mu1 * mu1 + 1e-5f);
        int r0 = row0 + rb, r1 = r0 + 8;
#pragma unroll
        for (int nt = 0; nt < 4; nt++) {
            int col = wn + nt * 8 + 2 * gc;
            float g0 = par[128 + col], g1 = par[128 + col + 1];
            float b0 = par[256 + col], b1 = par[256 + col + 1];
            float v00 = (d[mt][nt][0] - mu0) * rstd0 * g0 + b0;
            float v01 = (d[mt][nt][1] - mu0) * rstd0 * g1 + b1;
            float v10 = (d[mt][nt][2] - mu1) * rstd1 * g0 + b0;
            float v11 = (d[mt][nt][3] - mu1) * rstd1 * g1 + b1;
            if (last) {
                if (r0 < Nn)
                    *reinterpret_cast<float2*>(out + (size_t)r0 * Dd + col) = make_float2(v00, v01);
                if (r1 < Nn)
                    *reinterpret_cast<float2*>(out + (size_t)r1 * Dd + col) = make_float2(v10, v11);
            } else {
                if (r0 < Nn)
                    *reinterpret_cast<__half2*>(g_xh + (size_t)r0 * Dd + col) = __floats2half2_rn(v00, v01);
                if (r1 < Nn)
                    *reinterpret_cast<__half2*>(g_xh + (size_t)r1 * Dd + col) = __floats2half2_rn(v10, v11);
            }
        }
    }
}

// ---------------- fused edge-softmax + aggregation ----------------
__global__ void k_aggregate(const float* __restrict__ bgat) {
    int dn = blockIdx.x;
    int w = threadIdx.x >> 5, ln = threadIdx.x & 31;
    int s = g_off[dn], en = g_off[dn + 1];
    float erd = g_er[dn * 4 + w];
    float a0 = 0.f, a1 = 0.f, a2 = 0.f, a3 = 0.f, z = 0.f;

    for (int base = s; base < en; base += 32) {
        int cnt = en - base; if (cnt > 32) cnt = 32;
        int idx = (ln < cnt) ? g_csr_src[base + ln] : 0;
        float e = g_el[idx * 4 + w] + erd;
        e = e > 0.f ? e : NEG_ATTN * e;
        float wv = (ln < cnt) ? __expf(e) : 0.f;
        for (int j = 0; j < cnt; j++) {
            int sn   = __shfl_sync(0xffffffffu, idx, j);
            float wg = __shfl_sync(0xffffffffu, wv, j);
            uint2 u = *reinterpret_cast<const uint2*>(g_feath + (size_t)sn * 512 + w * 128 + 4 * ln);
            float2 f0 = __half22float2(*reinterpret_cast<__half2*>(&u.x));
            float2 f1 = __half22float2(*reinterpret_cast<__half2*>(&u.y));
            a0 = fmaf(wg, f0.x, a0); a1 = fmaf(wg, f0.y, a1);
            a2 = fmaf(wg, f1.x, a2); a3 = fmaf(wg, f1.y, a3);
            z += wg;
        }
    }

    float iz = 1.f / fmaxf(z, 1e-20f);
    int col = w * 128 + 4 * ln;
    size_t o = (size_t)dn * HDim + col;
    uint2 ru = *reinterpret_cast<const uint2*>(g_resh + o);
    float2 r0 = __half22float2(*reinterpret_cast<__half2*>(&ru.x));
    float2 r1 = __half22float2(*reinterpret_cast<__half2*>(&ru.y));
    float4 bg = *reinterpret_cast<const float4*>(bgat + col);
    float v0 = a0 * iz + r0.x + bg.x; v0 = v0 > 0.f ? v0 : NEG_ACT * v0;
    float v1 = a1 * iz + r0.y + bg.y; v1 = v1 > 0.f ? v1 : NEG_ACT * v1;
    float v2 = a2 * iz + r1.x + bg.z; v2 = v2 > 0.f ? v2 : NEG_ACT * v2;
    float v3 = a3 * iz + r1.y + bg.w; v3 = v3 > 0.f ? v3 : NEG_ACT * v3;
    uint2 ou;
    *reinterpret_cast<__half2*>(&ou.x) = __floats2half2_rn(v0, v1);
    *reinterpret_cast<__half2*>(&ou.y) = __floats2half2_rn(v2, v3);
    *reinterpret_cast<uint2*>(g_resh + o) = ou;
}

// ---------------- launch ----------------
extern "C" void kernel_launch(void* const* d_in, const int* in_sizes, int n_in,
                              void* d_out, int out_size) {
    const float* features = (const float*)d_in[0];
    const int*   src      = (const int*)  d_in[1];
    const int*   dst      = (const int*)  d_in[2];
    const float* W_fc     = (const float*)d_in[3];
    const float* attn_l   = (const float*)d_in[4];
    const float* attn_r   = (const float*)d_in[5];
    const float* W_res    = (const float*)d_in[6];
    const float* b_gat    = (const float*)d_in[7];
    const float* W_nrm    = (const float*)d_in[8];
    const float* b_nrm    = (const float*)d_in[9];
    const float* ln_g     = (const float*)d_in[10];
    const float* ln_b     = (const float*)d_in[11];
    float* out = (float*)d_out;

    cudaFuncSetAttribute(k_gemm1, cudaFuncAttributeMaxDynamicSharedMemorySize, SMEM_G1);
    cudaFuncSetAttribute(k_gemm2, cudaFuncAttributeMaxDynamicSharedMemorySize, SMEM_G2);

    k_zero_deg<<<(Nn + 255) / 256, 256>>>();
    k_hist<<<(Ee + 255) / 256, 256>>>(dst);
    k_scan<<<1, 1024>>>();
    k_scatter<<<(Ee + 255) / 256, 256>>>(src, dst);
    k_prep_w1<<<(4 * 1024 * 128 + 255) / 256, 256>>>(W_fc, W_res);
    k_prep_x<<<(Nn * Dd + 255) / 256, 256>>>(features);

    for (int l = 0; l < 4; l++) {
        const float* al  = attn_l + (size_t)l * Hh * Dd;
        const float* ar  = attn_r + (size_t)l * Hh * Dd;
        const float* bg  = b_gat + (size_t)l * HDim;
        const float* bnp = b_nrm + (size_t)l * Dd;
        const float* gp  = ln_g  + (size_t)l * Dd;
        const float* bp  = ln_b  + (size_t)l * Dd;

        k_gemm1<<<dim3((Nn + 127) / 128, 8), 256, SMEM_G1>>>(l, al, ar);
        if (l == 0) k_prep_w2<<<(4 * 128 * 512 + 255) / 256, 256>>>(W_nrm);
        k_aggregate<<<Nn, 128>>>(bg);
        k_gemm2<<<(Nn + 127) / 128, 256, SMEM_G2>>>(l, bnp, gp, bp, out, l == 3 ? 1 : 0);
    }
}